// round 2
// baseline (speedup 1.0000x reference)
#include <cuda_runtime.h>
#include <math.h>
#include <float.h>

#define D 64
#define L 64
#define DIMF 512
#define G 256
#define M 192                 // 3*L nodes (= hyperedges) per dialogue
#define KTOP 12
#define NROWS 4096            // D*L
#define NNODE (D*M)           // 12288
#define TAUINV (1.0f/0.07f)

// ---- scratch (static device arrays; no allocation allowed) ----
__device__ float    g_sq[NNODE];
__device__ unsigned g_H[NNODE*6];       // 192-bit incidence mask per edge
__device__ float    g_dege[NNODE];
__device__ float    g_X[NNODE*G];
__device__ float    g_E[NNODE*G];
__device__ float    g_Y[NNODE*G];
__device__ float    g_invn[3*NROWS];
__device__ float    g_diag[3*NROWS];
__device__ float    g_rowsum[3*NROWS];
__device__ float    g_colsum[3*NROWS];

__device__ __forceinline__ const float* feat_row(int d, int n,
        const float* t, const float* a, const float* v) {
    int mod = n >> 6, i = n & 63;
    const float* base = (mod == 0) ? t : (mod == 1) ? a : v;
    return base + (size_t)(d * L + i) * DIMF;
}

// ---------------- K1: per-node squared norms ----------------
__global__ void k_sq(const float* t, const float* a, const float* v) {
    int warp = (blockIdx.x * blockDim.x + threadIdx.x) >> 5;
    int lane = threadIdx.x & 31;
    if (warp >= NNODE) return;
    int d = warp / M, n = warp % M;
    const float* r = feat_row(d, n, t, a, v);
    float s = 0.f;
    #pragma unroll
    for (int c = lane; c < DIMF; c += 32) { float x = r[c]; s += x * x; }
    #pragma unroll
    for (int o = 16; o; o >>= 1) s += __shfl_down_sync(0xffffffffu, s, o);
    if (lane == 0) g_sq[warp] = s;
}

// ---------------- K2: gram + d2 + top-12 + incidence masks ----------------
#define K2BK 32
__global__ void k_gram_topk(const float* t, const float* a, const float* v) {
    int d  = blockIdx.x / 6;
    int i0 = (blockIdx.x % 6) * 32;
    __shared__ float sA[32][K2BK + 1];
    __shared__ float sB[M * (K2BK + 1)];      // reused as d2 buffer [32][193]
    __shared__ const float* ptrB[M];
    int tid = threadIdx.x;
    int tx = tid & 31, ty = tid >> 5;
    if (tid < M) ptrB[tid] = feat_row(d, tid, t, a, v);
    __syncthreads();

    float acc[4][6];
    #pragma unroll
    for (int i = 0; i < 4; i++)
        #pragma unroll
        for (int c = 0; c < 6; c++) acc[i][c] = 0.f;

    for (int kc = 0; kc < DIMF; kc += K2BK) {
        #pragma unroll
        for (int it = 0; it < 4; it++) {
            int idx = tid + it * 256;
            int r = idx >> 5, c = idx & 31;
            sA[r][c] = ptrB[i0 + r][kc + c];
        }
        #pragma unroll
        for (int it = 0; it < 24; it++) {
            int idx = tid + it * 256;
            int r = idx >> 5, c = idx & 31;
            sB[r * (K2BK + 1) + c] = ptrB[r][kc + c];
        }
        __syncthreads();
        #pragma unroll
        for (int kk = 0; kk < K2BK; kk++) {
            float av[4], bv[6];
            #pragma unroll
            for (int i = 0; i < 4; i++) av[i] = sA[ty * 4 + i][kk];
            #pragma unroll
            for (int c = 0; c < 6; c++) bv[c] = sB[(tx * 6 + c) * (K2BK + 1) + kk];
            #pragma unroll
            for (int i = 0; i < 4; i++)
                #pragma unroll
                for (int c = 0; c < 6; c++) acc[i][c] += av[i] * bv[c];
        }
        __syncthreads();
    }

    // d2 into reused sB buffer, pitch 193
    float* d2s = sB;
    #pragma unroll
    for (int i = 0; i < 4; i++) {
        int row = i0 + ty * 4 + i;
        float sqi = g_sq[d * M + row];
        #pragma unroll
        for (int c = 0; c < 6; c++) {
            int col = tx * 6 + c;
            float v2 = sqi + g_sq[d * M + col] - 2.f * acc[i][c];
            d2s[(ty * 4 + i) * 193 + col] = fmaxf(v2, 0.f);
        }
    }
    __syncthreads();

    // top-12 smallest per row (tie -> lower index), one warp per 4 rows
    for (int q = 0; q < 4; q++) {
        int r = ty * 4 + q;
        float val[6];
        #pragma unroll
        for (int s = 0; s < 6; s++) val[s] = d2s[r * 193 + tx + 32 * s];
        unsigned mask[6] = {0, 0, 0, 0, 0, 0};
        for (int pick = 0; pick < KTOP; pick++) {
            float bv = val[0]; int bi = tx;
            #pragma unroll
            for (int s = 1; s < 6; s++) {
                float vv = val[s];
                if (vv < bv) { bv = vv; bi = tx + 32 * s; }
            }
            #pragma unroll
            for (int o = 16; o; o >>= 1) {
                float ov = __shfl_down_sync(0xffffffffu, bv, o);
                int   oi = __shfl_down_sync(0xffffffffu, bi, o);
                if (ov < bv || (ov == bv && oi < bi)) { bv = ov; bi = oi; }
            }
            bi = __shfl_sync(0xffffffffu, bi, 0);
            if ((bi & 31) == tx) val[bi >> 5] = FLT_MAX;
            mask[bi >> 5] |= 1u << (bi & 31);
        }
        if (tx == 0) {
            int e = i0 + r;
            int u = e / 3;
            mask[u >> 5]           |= 1u << (u & 31);
            mask[(u + 64) >> 5]    |= 1u << ((u + 64) & 31);
            mask[(u + 128) >> 5]   |= 1u << ((u + 128) & 31);
            int deg = 0;
            #pragma unroll
            for (int w = 0; w < 6; w++) {
                g_H[(size_t)(d * M + e) * 6 + w] = mask[w];
                deg += __popc(mask[w]);
            }
            g_dege[d * M + e] = (float)deg;
        }
    }
}

// ---------------- K3: X = feat @ W_fc + b_fc ----------------
__global__ void k_fc(const float* t, const float* a, const float* v,
                     const float* Wfc, const float* bfc) {
    int bn = blockIdx.x, bm = blockIdx.y;
    __shared__ float sA[16][65];
    __shared__ float sB[16][64];
    __shared__ const float* ptrA[64];
    int tid = threadIdx.x, tx = tid & 15, ty = tid >> 4;
    if (tid < 64) { int gn = bm * 64 + tid; ptrA[tid] = feat_row(gn / M, gn % M, t, a, v); }
    __syncthreads();
    float acc[4][4] = {};
    for (int kc = 0; kc < DIMF; kc += 16) {
        #pragma unroll
        for (int it = 0; it < 4; it++) {
            int idx = tid + it * 256;
            int r = idx >> 4, c = idx & 15;
            sA[c][r] = ptrA[r][kc + c];
            int r2 = idx >> 6, c2 = idx & 63;
            sB[r2][c2] = Wfc[(size_t)(kc + r2) * G + bn * 64 + c2];
        }
        __syncthreads();
        #pragma unroll
        for (int kk = 0; kk < 16; kk++) {
            float aa[4], bb[4];
            #pragma unroll
            for (int i = 0; i < 4; i++) aa[i] = sA[kk][ty * 4 + i];
            #pragma unroll
            for (int j = 0; j < 4; j++) bb[j] = sB[kk][tx * 4 + j];
            #pragma unroll
            for (int i = 0; i < 4; i++)
                #pragma unroll
                for (int j = 0; j < 4; j++) acc[i][j] += aa[i] * bb[j];
        }
        __syncthreads();
    }
    #pragma unroll
    for (int i = 0; i < 4; i++)
        #pragma unroll
        for (int j = 0; j < 4; j++) {
            int gn = bm * 64 + ty * 4 + i, gc = bn * 64 + tx * 4 + j;
            g_X[(size_t)gn * G + gc] = acc[i][j] + bfc[gc];
        }
}

// ---------------- K4: edge features E (mean over member nodes) ----------------
__global__ void k_edge() {
    int eg = blockIdx.x;
    __shared__ unsigned msk[6];
    __shared__ float sdeg;
    if (threadIdx.x < 6) msk[threadIdx.x] = g_H[(size_t)eg * 6 + threadIdx.x];
    if (threadIdx.x == 6) sdeg = g_dege[eg];
    __syncthreads();
    int g = threadIdx.x;
    int d = eg / M;
    float accv = 0.f;
    #pragma unroll
    for (int w = 0; w < 6; w++) {
        unsigned b = msk[w];
        while (b) {
            int n = w * 32 + __ffs(b) - 1;
            b &= b - 1;
            accv += g_X[(size_t)(d * M + n) * G + g];
        }
    }
    g_E[(size_t)eg * G + g] = accv / sdeg;
}

// ---------------- K5: node features Y (mean over incident edges) ----------------
__global__ void k_node() {
    int ng = blockIdx.x;
    int d = ng / M, n = ng % M;
    __shared__ unsigned cm[6];
    int tid = threadIdx.x;
    int w = tid >> 5, lane = tid & 31;
    if (w < 6) {
        int e = tid;  // 0..191
        unsigned bit = (g_H[(size_t)(d * M + e) * 6 + (n >> 5)] >> (n & 31)) & 1u;
        unsigned bal = __ballot_sync(0xffffffffu, bit != 0);
        if (lane == 0) cm[w] = bal;
    }
    __syncthreads();
    int g = tid;
    float accv = 0.f; int deg = 0;
    #pragma unroll
    for (int w2 = 0; w2 < 6; w2++) {
        unsigned b = cm[w2];
        deg += __popc(b);
        while (b) {
            int e = w2 * 32 + __ffs(b) - 1;
            b &= b - 1;
            accv += g_E[(size_t)(d * M + e) * G + g];
        }
    }
    g_Y[(size_t)ng * G + g] = accv / (float)deg;
}

// ---------------- K6: out = relu(Y @ W_h + b_h), regrouped into d_out ----------------
__global__ void k_out(const float* Wh, const float* bh, float* out) {
    int bn = blockIdx.x, bm = blockIdx.y;
    __shared__ float sA[16][65];
    __shared__ float sB[16][64];
    int tid = threadIdx.x, tx = tid & 15, ty = tid >> 4;
    float acc[4][4] = {};
    for (int kc = 0; kc < G; kc += 16) {
        #pragma unroll
        for (int it = 0; it < 4; it++) {
            int idx = tid + it * 256;
            int r = idx >> 4, c = idx & 15;
            sA[c][r] = g_Y[(size_t)(bm * 64 + r) * G + kc + c];
            int r2 = idx >> 6, c2 = idx & 63;
            sB[r2][c2] = Wh[(size_t)(kc + r2) * G + bn * 64 + c2];
        }
        __syncthreads();
        #pragma unroll
        for (int kk = 0; kk < 16; kk++) {
            float aa[4], bb[4];
            #pragma unroll
            for (int i = 0; i < 4; i++) aa[i] = sA[kk][ty * 4 + i];
            #pragma unroll
            for (int j = 0; j < 4; j++) bb[j] = sB[kk][tx * 4 + j];
            #pragma unroll
            for (int i = 0; i < 4; i++)
                #pragma unroll
                for (int j = 0; j < 4; j++) acc[i][j] += aa[i] * bb[j];
        }
        __syncthreads();
    }
    #pragma unroll
    for (int i = 0; i < 4; i++)
        #pragma unroll
        for (int j = 0; j < 4; j++) {
            int gn = bm * 64 + ty * 4 + i;
            int dd = gn / M, n = gn % M, mod = n >> 6, ii = n & 63;
            int gc = bn * 64 + tx * 4 + j;
            out[(size_t)(dd * L + ii) * 768 + mod * 256 + gc] =
                fmaxf(acc[i][j] + bh[gc], 0.f);
        }
}

// ---------------- K7: norms, diagonal sims, zero LSE accumulators ----------------
__global__ void k_norm(const float* out) {
    int i = blockIdx.x;
    int tid = threadIdx.x;
    float tv = out[(size_t)i * 768 + tid];
    float av = out[(size_t)i * 768 + 256 + tid];
    float vv = out[(size_t)i * 768 + 512 + tid];
    float q[6] = { tv * tv, av * av, vv * vv, tv * av, tv * vv, av * vv };
    __shared__ float red[6][8];
    int lane = tid & 31, w = tid >> 5;
    #pragma unroll
    for (int o = 16; o; o >>= 1)
        #pragma unroll
        for (int k = 0; k < 6; k++) q[k] += __shfl_down_sync(0xffffffffu, q[k], o);
    if (lane == 0)
        #pragma unroll
        for (int k = 0; k < 6; k++) red[k][w] = q[k];
    __syncthreads();
    if (tid == 0) {
        float s[6];
        #pragma unroll
        for (int k = 0; k < 6; k++) {
            s[k] = 0.f;
            #pragma unroll
            for (int w2 = 0; w2 < 8; w2++) s[k] += red[k][w2];
        }
        float it = 1.f / (sqrtf(s[0]) + 1e-8f);
        float ia = 1.f / (sqrtf(s[1]) + 1e-8f);
        float iv = 1.f / (sqrtf(s[2]) + 1e-8f);
        g_invn[i] = it; g_invn[NROWS + i] = ia; g_invn[2 * NROWS + i] = iv;
        g_diag[i]             = s[3] * it * ia * TAUINV;
        g_diag[NROWS + i]     = s[4] * it * iv * TAUINV;
        g_diag[2 * NROWS + i] = s[5] * ia * iv * TAUINV;
        g_rowsum[i] = 0.f; g_rowsum[NROWS + i] = 0.f; g_rowsum[2 * NROWS + i] = 0.f;
        g_colsum[i] = 0.f; g_colsum[NROWS + i] = 0.f; g_colsum[2 * NROWS + i] = 0.f;
    }
}

// ---------------- K8: similarity tiles + streaming exp-sum (row & col) ----------------
__global__ void k_sim(const float* out) {
    int p = blockIdx.z;
    int mx = (p == 2) ? 1 : 0;
    int my = (p == 0) ? 1 : 2;
    int row0 = blockIdx.y * 128, col0 = blockIdx.x * 128;
    __shared__ float sX[128][17];
    __shared__ float sY[128][17];
    __shared__ float srow[128], scol[128];
    int tid = threadIdx.x, tx = tid & 15, ty = tid >> 4;
    float acc[8][8];
    #pragma unroll
    for (int i = 0; i < 8; i++)
        #pragma unroll
        for (int j = 0; j < 8; j++) acc[i][j] = 0.f;

    const float* xb = out + (size_t)mx * 256;
    const float* yb = out + (size_t)my * 256;
    for (int kc = 0; kc < G; kc += 16) {
        #pragma unroll
        for (int it = 0; it < 8; it++) {
            int idx = tid + it * 256;
            int rr = idx >> 4, k = idx & 15;
            sX[rr][k] = xb[(size_t)(row0 + rr) * 768 + kc + k];
            sY[rr][k] = yb[(size_t)(col0 + rr) * 768 + kc + k];
        }
        __syncthreads();
        #pragma unroll
        for (int kk = 0; kk < 16; kk++) {
            float aa[8], bb[8];
            #pragma unroll
            for (int i = 0; i < 8; i++) aa[i] = sX[ty + 16 * i][kk];
            #pragma unroll
            for (int j = 0; j < 8; j++) bb[j] = sY[tx + 16 * j][kk];
            #pragma unroll
            for (int i = 0; i < 8; i++)
                #pragma unroll
                for (int j = 0; j < 8; j++) acc[i][j] += aa[i] * bb[j];
        }
        __syncthreads();
    }

    float inx[8], iny[8];
    #pragma unroll
    for (int i = 0; i < 8; i++) inx[i] = g_invn[mx * NROWS + row0 + ty + 16 * i];
    #pragma unroll
    for (int j = 0; j < 8; j++) iny[j] = g_invn[my * NROWS + col0 + tx + 16 * j];

    float rowp[8] = {0, 0, 0, 0, 0, 0, 0, 0};
    float colp[8] = {0, 0, 0, 0, 0, 0, 0, 0};
    #pragma unroll
    for (int i = 0; i < 8; i++)
        #pragma unroll
        for (int j = 0; j < 8; j++) {
            float e = __expf(acc[i][j] * inx[i] * iny[j] * TAUINV);
            rowp[i] += e; colp[j] += e;
        }
    if (tid < 128) { srow[tid] = 0.f; scol[tid] = 0.f; }
    __syncthreads();
    #pragma unroll
    for (int i = 0; i < 8; i++) atomicAdd(&srow[ty + 16 * i], rowp[i]);
    #pragma unroll
    for (int j = 0; j < 8; j++) atomicAdd(&scol[tx + 16 * j], colp[j]);
    __syncthreads();
    if (tid < 128) {
        atomicAdd(&g_rowsum[p * NROWS + row0 + tid], srow[tid]);
        atomicAdd(&g_colsum[p * NROWS + col0 + tid], scol[tid]);
    }
}

// ---------------- K9: final loss reduction ----------------
__global__ void k_loss(float* out, int out_size) {
    int tid = threadIdx.x;
    float s = 0.f;
    for (int idx = tid; idx < 3 * NROWS; idx += 256) {
        float dg = g_diag[idx];
        s += 2.f * dg - logf(g_rowsum[idx]) - logf(g_colsum[idx]);
    }
    __shared__ float red[8];
    int lane = tid & 31, w = tid >> 5;
    #pragma unroll
    for (int o = 16; o; o >>= 1) s += __shfl_down_sync(0xffffffffu, s, o);
    if (lane == 0) red[w] = s;
    __syncthreads();
    if (tid == 0) {
        float tot = 0.f;
        #pragma unroll
        for (int w2 = 0; w2 < 8; w2++) tot += red[w2];
        float loss = -tot / (2.f * 3.f * (float)NROWS);
        if (out_size > NROWS * 768) out[NROWS * 768] = loss;
    }
}

// ---------------- launcher ----------------
extern "C" void kernel_launch(void* const* d_in, const int* in_sizes, int n_in,
                              void* d_out, int out_size) {
    const float* t   = (const float*)d_in[0];
    const float* a   = (const float*)d_in[1];
    const float* v   = (const float*)d_in[2];
    const float* Wfc = (const float*)d_in[3];
    const float* bfc = (const float*)d_in[4];
    const float* Wh  = (const float*)d_in[5];
    const float* bh  = (const float*)d_in[6];
    float* out = (float*)d_out;

    k_sq<<<NNODE / 8, 256>>>(t, a, v);
    k_gram_topk<<<D * 6, 256>>>(t, a, v);
    k_fc<<<dim3(4, NNODE / 64), 256>>>(t, a, v, Wfc, bfc);
    k_edge<<<NNODE, 256>>>();
    k_node<<<NNODE, 256>>>();
    k_out<<<dim3(4, NNODE / 64), 256>>>(Wh, bh, out);
    k_norm<<<NROWS, 256>>>(out);
    k_sim<<<dim3(32, 32, 3), 256>>>(out);
    k_loss<<<1, 256>>>(out, out_size);
}

// round 4
// speedup vs baseline: 2.7851x; 2.7851x over previous
#include <cuda_runtime.h>
#include <cuda_bf16.h>
#include <math.h>
#include <float.h>

#define D 64
#define L 64
#define DIMF 512
#define G 256
#define M 192                 // 3*L nodes (= hyperedges) per dialogue
#define KTOP 12
#define NROWS 4096            // D*L
#define NNODE (D*M)           // 12288
#define TAUINV (1.0f/0.07f)
#define SQTAUI 3.7796447300922722f   // sqrt(1/0.07)

// ---- scratch (static device arrays; no allocation allowed) ----
__device__ float    g_sq[NNODE];
__device__ unsigned g_H[NNODE*6];       // 192-bit incidence mask per edge
__device__ float    g_dege[NNODE];
__device__ float    g_X[NNODE*G];
__device__ float    g_E[NNODE*G];
__device__ float    g_Y[NNODE*G];
__device__ float    g_invn[3*NROWS];
__device__ float    g_diag[3*NROWS];
__device__ float    g_rowsum[3*NROWS];
__device__ float    g_colsum[3*NROWS];
__device__ __nv_bfloat16 g_nb[(size_t)3*NROWS*G];   // normalized bf16 features (loss path only)

__device__ __forceinline__ const float* feat_row(int d, int n,
        const float* t, const float* a, const float* v) {
    int mod = n >> 6, i = n & 63;
    const float* base = (mod == 0) ? t : (mod == 1) ? a : v;
    return base + (size_t)(d * L + i) * DIMF;
}

// ---------------- K1: per-node squared norms ----------------
__global__ void k_sq(const float* t, const float* a, const float* v) {
    int warp = (blockIdx.x * blockDim.x + threadIdx.x) >> 5;
    int lane = threadIdx.x & 31;
    if (warp >= NNODE) return;
    int d = warp / M, n = warp % M;
    const float* r = feat_row(d, n, t, a, v);
    float s = 0.f;
    #pragma unroll
    for (int c = lane; c < DIMF; c += 32) { float x = r[c]; s += x * x; }
    #pragma unroll
    for (int o = 16; o; o >>= 1) s += __shfl_down_sync(0xffffffffu, s, o);
    if (lane == 0) g_sq[warp] = s;
}

// ---------------- K2: gram + d2 + top-12 + incidence masks ----------------
#define K2BK 32
__global__ void k_gram_topk(const float* t, const float* a, const float* v) {
    int d  = blockIdx.x / 6;
    int i0 = (blockIdx.x % 6) * 32;
    __shared__ float sA[32][K2BK + 1];
    __shared__ float sB[M * (K2BK + 1)];      // reused as d2 buffer [32][193]
    __shared__ const float* ptrB[M];
    int tid = threadIdx.x;
    int tx = tid & 31, ty = tid >> 5;
    if (tid < M) ptrB[tid] = feat_row(d, tid, t, a, v);
    __syncthreads();

    float acc[4][6];
    #pragma unroll
    for (int i = 0; i < 4; i++)
        #pragma unroll
        for (int c = 0; c < 6; c++) acc[i][c] = 0.f;

    for (int kc = 0; kc < DIMF; kc += K2BK) {
        #pragma unroll
        for (int it = 0; it < 4; it++) {
            int idx = tid + it * 256;
            int r = idx >> 5, c = idx & 31;
            sA[r][c] = ptrB[i0 + r][kc + c];
        }
        #pragma unroll
        for (int it = 0; it < 24; it++) {
            int idx = tid + it * 256;
            int r = idx >> 5, c = idx & 31;
            sB[r * (K2BK + 1) + c] = ptrB[r][kc + c];
        }
        __syncthreads();
        #pragma unroll
        for (int kk = 0; kk < K2BK; kk++) {
            float av[4], bv[6];
            #pragma unroll
            for (int i = 0; i < 4; i++) av[i] = sA[ty * 4 + i][kk];
            #pragma unroll
            for (int c = 0; c < 6; c++) bv[c] = sB[(tx * 6 + c) * (K2BK + 1) + kk];
            #pragma unroll
            for (int i = 0; i < 4; i++)
                #pragma unroll
                for (int c = 0; c < 6; c++) acc[i][c] += av[i] * bv[c];
        }
        __syncthreads();
    }

    // d2 into reused sB buffer, pitch 193
    float* d2s = sB;
    #pragma unroll
    for (int i = 0; i < 4; i++) {
        int row = i0 + ty * 4 + i;
        float sqi = g_sq[d * M + row];
        #pragma unroll
        for (int c = 0; c < 6; c++) {
            int col = tx * 6 + c;
            float v2 = sqi + g_sq[d * M + col] - 2.f * acc[i][c];
            d2s[(ty * 4 + i) * 193 + col] = fmaxf(v2, 0.f);
        }
    }
    __syncthreads();

    // top-12 smallest per row (tie -> lower index), one warp per 4 rows
    for (int q = 0; q < 4; q++) {
        int r = ty * 4 + q;
        float val[6];
        #pragma unroll
        for (int s = 0; s < 6; s++) val[s] = d2s[r * 193 + tx + 32 * s];
        unsigned mask[6] = {0, 0, 0, 0, 0, 0};
        for (int pick = 0; pick < KTOP; pick++) {
            float bv = val[0]; int bi = tx;
            #pragma unroll
            for (int s = 1; s < 6; s++) {
                float vv = val[s];
                if (vv < bv) { bv = vv; bi = tx + 32 * s; }
            }
            #pragma unroll
            for (int o = 16; o; o >>= 1) {
                float ov = __shfl_down_sync(0xffffffffu, bv, o);
                int   oi = __shfl_down_sync(0xffffffffu, bi, o);
                if (ov < bv || (ov == bv && oi < bi)) { bv = ov; bi = oi; }
            }
            bi = __shfl_sync(0xffffffffu, bi, 0);
            if ((bi & 31) == tx) val[bi >> 5] = FLT_MAX;
            mask[bi >> 5] |= 1u << (bi & 31);
        }
        if (tx == 0) {
            int e = i0 + r;
            int u = e / 3;
            mask[u >> 5]           |= 1u << (u & 31);
            mask[(u + 64) >> 5]    |= 1u << ((u + 64) & 31);
            mask[(u + 128) >> 5]   |= 1u << ((u + 128) & 31);
            int deg = 0;
            #pragma unroll
            for (int w = 0; w < 6; w++) {
                g_H[(size_t)(d * M + e) * 6 + w] = mask[w];
                deg += __popc(mask[w]);
            }
            g_dege[d * M + e] = (float)deg;
        }
    }
}

// ---------------- K3: X = feat @ W_fc + b_fc ----------------
__global__ void k_fc(const float* t, const float* a, const float* v,
                     const float* Wfc, const float* bfc) {
    int bn = blockIdx.x, bm = blockIdx.y;
    __shared__ float sA[16][65];
    __shared__ float sB[16][64];
    __shared__ const float* ptrA[64];
    int tid = threadIdx.x, tx = tid & 15, ty = tid >> 4;
    if (tid < 64) { int gn = bm * 64 + tid; ptrA[tid] = feat_row(gn / M, gn % M, t, a, v); }
    __syncthreads();
    float acc[4][4] = {};
    for (int kc = 0; kc < DIMF; kc += 16) {
        #pragma unroll
        for (int it = 0; it < 4; it++) {
            int idx = tid + it * 256;
            int r = idx >> 4, c = idx & 15;
            sA[c][r] = ptrA[r][kc + c];
            int r2 = idx >> 6, c2 = idx & 63;
            sB[r2][c2] = Wfc[(size_t)(kc + r2) * G + bn * 64 + c2];
        }
        __syncthreads();
        #pragma unroll
        for (int kk = 0; kk < 16; kk++) {
            float aa[4], bb[4];
            #pragma unroll
            for (int i = 0; i < 4; i++) aa[i] = sA[kk][ty * 4 + i];
            #pragma unroll
            for (int j = 0; j < 4; j++) bb[j] = sB[kk][tx * 4 + j];
            #pragma unroll
            for (int i = 0; i < 4; i++)
                #pragma unroll
                for (int j = 0; j < 4; j++) acc[i][j] += aa[i] * bb[j];
        }
        __syncthreads();
    }
    #pragma unroll
    for (int i = 0; i < 4; i++)
        #pragma unroll
        for (int j = 0; j < 4; j++) {
            int gn = bm * 64 + ty * 4 + i, gc = bn * 64 + tx * 4 + j;
            g_X[(size_t)gn * G + gc] = acc[i][j] + bfc[gc];
        }
}

// ---------------- K4: edge features E (mean over member nodes) ----------------
// decode mask -> node list (deterministic ascending order), then MLP-friendly loop
__global__ void k_edge() {
    int eg = blockIdx.x;
    __shared__ int lst[16];
    __shared__ int scnt;
    int tid = threadIdx.x;
    if (tid == 0) {
        int pos = 0;
        #pragma unroll
        for (int w = 0; w < 6; w++) {
            unsigned b = g_H[(size_t)eg * 6 + w];
            while (b) { lst[pos++] = w * 32 + __ffs(b) - 1; b &= b - 1; }
        }
        scnt = pos;
    }
    __syncthreads();
    int cnt = scnt;
    int d = eg / M;
    int g = tid;
    const float* Xb = g_X + (size_t)d * M * G;
    float a0 = 0.f, a1 = 0.f;
    int i = 0;
    for (; i + 1 < cnt; i += 2) {
        a0 += Xb[(size_t)lst[i] * G + g];
        a1 += Xb[(size_t)lst[i + 1] * G + g];
    }
    if (i < cnt) a0 += Xb[(size_t)lst[i] * G + g];
    g_E[(size_t)eg * G + g] = (a0 + a1) / (float)cnt;
}

// ---------------- K5: node features Y (mean over incident edges) ----------------
__global__ void k_node() {
    int ng = blockIdx.x;
    int d = ng / M, n = ng % M;
    __shared__ unsigned cm[6];
    __shared__ int lst[192];
    __shared__ int scnt;
    int tid = threadIdx.x;
    int w = tid >> 5, lane = tid & 31;
    if (w < 6) {
        unsigned bit = (g_H[(size_t)(d * M + tid) * 6 + (n >> 5)] >> (n & 31)) & 1u;
        unsigned bal = __ballot_sync(0xffffffffu, bit != 0);
        if (lane == 0) cm[w] = bal;
    }
    __syncthreads();
    if (tid == 0) {
        int pos = 0;
        #pragma unroll
        for (int w2 = 0; w2 < 6; w2++) {
            unsigned b = cm[w2];
            while (b) { lst[pos++] = w2 * 32 + __ffs(b) - 1; b &= b - 1; }
        }
        scnt = pos;
    }
    __syncthreads();
    int cnt = scnt;
    int g = tid;
    const float* Eb = g_E + (size_t)d * M * G;
    float a0 = 0.f, a1 = 0.f;
    int i = 0;
    for (; i + 1 < cnt; i += 2) {
        a0 += Eb[(size_t)lst[i] * G + g];
        a1 += Eb[(size_t)lst[i + 1] * G + g];
    }
    if (i < cnt) a0 += Eb[(size_t)lst[i] * G + g];
    g_Y[(size_t)ng * G + g] = (a0 + a1) / (float)cnt;
}

// ---------------- K6: out = relu(Y @ W_h + b_h), regrouped into d_out ----------------
__global__ void k_out(const float* Wh, const float* bh, float* out) {
    int bn = blockIdx.x, bm = blockIdx.y;
    __shared__ float sA[16][65];
    __shared__ float sB[16][64];
    int tid = threadIdx.x, tx = tid & 15, ty = tid >> 4;
    float acc[4][4] = {};
    for (int kc = 0; kc < G; kc += 16) {
        #pragma unroll
        for (int it = 0; it < 4; it++) {
            int idx = tid + it * 256;
            int r = idx >> 4, c = idx & 15;
            sA[c][r] = g_Y[(size_t)(bm * 64 + r) * G + kc + c];
            int r2 = idx >> 6, c2 = idx & 63;
            sB[r2][c2] = Wh[(size_t)(kc + r2) * G + bn * 64 + c2];
        }
        __syncthreads();
        #pragma unroll
        for (int kk = 0; kk < 16; kk++) {
            float aa[4], bb[4];
            #pragma unroll
            for (int i = 0; i < 4; i++) aa[i] = sA[kk][ty * 4 + i];
            #pragma unroll
            for (int j = 0; j < 4; j++) bb[j] = sB[kk][tx * 4 + j];
            #pragma unroll
            for (int i = 0; i < 4; i++)
                #pragma unroll
                for (int j = 0; j < 4; j++) acc[i][j] += aa[i] * bb[j];
        }
        __syncthreads();
    }
    #pragma unroll
    for (int i = 0; i < 4; i++)
        #pragma unroll
        for (int j = 0; j < 4; j++) {
            int gn = bm * 64 + ty * 4 + i;
            int dd = gn / M, n = gn % M, mod = n >> 6, ii = n & 63;
            int gc = bn * 64 + tx * 4 + j;
            out[(size_t)(dd * L + ii) * 768 + mod * 256 + gc] =
                fmaxf(acc[i][j] + bh[gc], 0.f);
        }
}

// ---------------- K7: norms, diagonal sims, zero LSE accumulators ----------------
__global__ void k_norm(const float* out) {
    int i = blockIdx.x;
    int tid = threadIdx.x;
    float tv = out[(size_t)i * 768 + tid];
    float av = out[(size_t)i * 768 + 256 + tid];
    float vv = out[(size_t)i * 768 + 512 + tid];
    float q[6] = { tv * tv, av * av, vv * vv, tv * av, tv * vv, av * vv };
    __shared__ float red[6][8];
    int lane = tid & 31, w = tid >> 5;
    #pragma unroll
    for (int o = 16; o; o >>= 1)
        #pragma unroll
        for (int k = 0; k < 6; k++) q[k] += __shfl_down_sync(0xffffffffu, q[k], o);
    if (lane == 0)
        #pragma unroll
        for (int k = 0; k < 6; k++) red[k][w] = q[k];
    __syncthreads();
    if (tid == 0) {
        float s[6];
        #pragma unroll
        for (int k = 0; k < 6; k++) {
            s[k] = 0.f;
            #pragma unroll
            for (int w2 = 0; w2 < 8; w2++) s[k] += red[k][w2];
        }
        float it = 1.f / (sqrtf(s[0]) + 1e-8f);
        float ia = 1.f / (sqrtf(s[1]) + 1e-8f);
        float iv = 1.f / (sqrtf(s[2]) + 1e-8f);
        g_invn[i] = it; g_invn[NROWS + i] = ia; g_invn[2 * NROWS + i] = iv;
        g_diag[i]             = s[3] * it * ia * TAUINV;
        g_diag[NROWS + i]     = s[4] * it * iv * TAUINV;
        g_diag[2 * NROWS + i] = s[5] * ia * iv * TAUINV;
        g_rowsum[i] = 0.f; g_rowsum[NROWS + i] = 0.f; g_rowsum[2 * NROWS + i] = 0.f;
        g_colsum[i] = 0.f; g_colsum[NROWS + i] = 0.f; g_colsum[2 * NROWS + i] = 0.f;
    }
}

// ---------------- K7b: bf16 normalized features (loss path) ----------------
// fold invnorm and 1/sqrt(tau) into both operands: dot(xb, yb) = xn.yn / tau
__global__ void k_tobf16(const float* out) {
    int i = blockIdx.x;
    int tid = threadIdx.x;
    #pragma unroll
    for (int m = 0; m < 3; m++) {
        float s = g_invn[m * NROWS + i] * SQTAUI;
        g_nb[((size_t)m * NROWS + i) * G + tid] =
            __float2bfloat16(out[(size_t)i * 768 + m * 256 + tid] * s);
    }
}

// ---------------- K8: bf16 tensor-core sim tiles + streaming exp-sum ----------------
#define SPITCH 40   // bf16 elements per smem row (80B; 8-lane ldmatrix groups conflict-free)
__global__ void __launch_bounds__(256) k_sim_mma() {
    int p = blockIdx.z;
    int mx = (p == 2) ? 1 : 0;
    int my = (p == 0) ? 1 : 2;
    int row0 = blockIdx.y * 128, col0 = blockIdx.x * 128;
    __shared__ __nv_bfloat16 sX[128 * SPITCH];
    __shared__ __nv_bfloat16 sY[128 * SPITCH];
    __shared__ float srow[128], scol[128];
    int tid = threadIdx.x, lane = tid & 31, warp = tid >> 5;
    int wy = warp >> 1, wx = warp & 1;      // warp tile: 32 rows x 64 cols

    const __nv_bfloat16* xg = g_nb + ((size_t)mx * NROWS + row0) * G;
    const __nv_bfloat16* yg = g_nb + ((size_t)my * NROWS + col0) * G;

    float acc[2][8][4];
    #pragma unroll
    for (int mi = 0; mi < 2; mi++)
        #pragma unroll
        for (int ni = 0; ni < 8; ni++)
            #pragma unroll
            for (int r = 0; r < 4; r++) acc[mi][ni][r] = 0.f;

    for (int kc = 0; kc < G; kc += 32) {
        #pragma unroll
        for (int i = 0; i < 2; i++) {
            int idx = tid + i * 256;          // 0..511
            int r = idx >> 2, c = (idx & 3) * 8;
            *(uint4*)(sX + r * SPITCH + c) = *(const uint4*)(xg + (size_t)r * G + kc + c);
            *(uint4*)(sY + r * SPITCH + c) = *(const uint4*)(yg + (size_t)r * G + kc + c);
        }
        __syncthreads();
        #pragma unroll
        for (int ks = 0; ks < 2; ks++) {
            int k0 = ks * 16;
            unsigned A[2][4];
            #pragma unroll
            for (int mi = 0; mi < 2; mi++) {
                int r = wy * 32 + mi * 16 + ((lane >> 3) & 1) * 8 + (lane & 7);
                int cc = k0 + (lane >> 4) * 8;
                unsigned ad = (unsigned)__cvta_generic_to_shared(sX + r * SPITCH + cc);
                asm volatile("ldmatrix.sync.aligned.m8n8.x4.shared.b16 {%0,%1,%2,%3},[%4];"
                    : "=r"(A[mi][0]), "=r"(A[mi][1]), "=r"(A[mi][2]), "=r"(A[mi][3])
                    : "r"(ad));
            }
            unsigned B[8][2];
            #pragma unroll
            for (int nb = 0; nb < 4; nb++) {
                int r = wx * 64 + nb * 16 + (lane >> 4) * 8 + (lane & 7);
                int cc = k0 + ((lane >> 3) & 1) * 8;
                unsigned ad = (unsigned)__cvta_generic_to_shared(sY + r * SPITCH + cc);
                asm volatile("ldmatrix.sync.aligned.m8n8.x4.shared.b16 {%0,%1,%2,%3},[%4];"
                    : "=r"(B[2 * nb][0]), "=r"(B[2 * nb][1]),
                      "=r"(B[2 * nb + 1][0]), "=r"(B[2 * nb + 1][1])
                    : "r"(ad));
            }
            #pragma unroll
            for (int mi = 0; mi < 2; mi++)
                #pragma unroll
                for (int ni = 0; ni < 8; ni++)
                    asm volatile(
                        "mma.sync.aligned.m16n8k16.row.col.f32.bf16.bf16.f32 "
                        "{%0,%1,%2,%3},{%4,%5,%6,%7},{%8,%9},{%0,%1,%2,%3};"
                        : "+f"(acc[mi][ni][0]), "+f"(acc[mi][ni][1]),
                          "+f"(acc[mi][ni][2]), "+f"(acc[mi][ni][3])
                        : "r"(A[mi][0]), "r"(A[mi][1]), "r"(A[mi][2]), "r"(A[mi][3]),
                          "r"(B[ni][0]), "r"(B[ni][1]));
        }
        __syncthreads();
    }

    // epilogue: exp and row/col partial sums
    if (tid < 128) { srow[tid] = 0.f; scol[tid] = 0.f; }
    __syncthreads();

    float rowp[2][2] = {{0.f, 0.f}, {0.f, 0.f}};
    float colp[8][2];
    #pragma unroll
    for (int ni = 0; ni < 8; ni++) { colp[ni][0] = 0.f; colp[ni][1] = 0.f; }
    #pragma unroll
    for (int mi = 0; mi < 2; mi++)
        #pragma unroll
        for (int ni = 0; ni < 8; ni++)
            #pragma unroll
            for (int r = 0; r < 4; r++) {
                float e = __expf(acc[mi][ni][r]);
                rowp[mi][r >> 1] += e;
                colp[ni][r & 1] += e;
            }

    // rows: lanes with same (lane>>2) share rows -> reduce over lane&3
    #pragma unroll
    for (int mi = 0; mi < 2; mi++)
        #pragma unroll
        for (int h = 0; h < 2; h++) {
            float vv = rowp[mi][h];
            vv += __shfl_xor_sync(0xffffffffu, vv, 1);
            vv += __shfl_xor_sync(0xffffffffu, vv, 2);
            if ((lane & 3) == 0)
                atomicAdd(&srow[wy * 32 + mi * 16 + (lane >> 2) + h * 8], vv);
        }
    // cols: lanes with same (lane&3) share cols -> reduce over lane>>2
    #pragma unroll
    for (int ni = 0; ni < 8; ni++)
        #pragma unroll
        for (int s2 = 0; s2 < 2; s2++) {
            float vv = colp[ni][s2];
            vv += __shfl_xor_sync(0xffffffffu, vv, 4);
            vv += __shfl_xor_sync(0xffffffffu, vv, 8);
            vv += __shfl_xor_sync(0xffffffffu, vv, 16);
            if (lane < 4)
                atomicAdd(&scol[wx * 64 + ni * 8 + lane * 2 + s2], vv);
        }
    __syncthreads();
    if (tid < 128) {
        atomicAdd(&g_rowsum[p * NROWS + row0 + tid], srow[tid]);
        atomicAdd(&g_colsum[p * NROWS + col0 + tid], scol[tid]);
    }
}

// ---------------- K9: final loss reduction ----------------
__global__ void k_loss(float* out, int out_size) {
    int tid = threadIdx.x;
    float s = 0.f;
    for (int idx = tid; idx < 3 * NROWS; idx += 256) {
        float dg = g_diag[idx];
        s += 2.f * dg - logf(g_rowsum[idx]) - logf(g_colsum[idx]);
    }
    __shared__ float red[8];
    int lane = tid & 31, w = tid >> 5;
    #pragma unroll
    for (int o = 16; o; o >>= 1) s += __shfl_down_sync(0xffffffffu, s, o);
    if (lane == 0) red[w] = s;
    __syncthreads();
    if (tid == 0) {
        float tot = 0.f;
        #pragma unroll
        for (int w2 = 0; w2 < 8; w2++) tot += red[w2];
        float loss = -tot / (2.f * 3.f * (float)NROWS);
        if (out_size > NROWS * 768) out[NROWS * 768] = loss;
    }
}

// ---------------- launcher ----------------
extern "C" void kernel_launch(void* const* d_in, const int* in_sizes, int n_in,
                              void* d_out, int out_size) {
    const float* t   = (const float*)d_in[0];
    const float* a   = (const float*)d_in[1];
    const float* v   = (const float*)d_in[2];
    const float* Wfc = (const float*)d_in[3];
    const float* bfc = (const float*)d_in[4];
    const float* Wh  = (const float*)d_in[5];
    const float* bh  = (const float*)d_in[6];
    float* out = (float*)d_out;

    k_sq<<<NNODE / 8, 256>>>(t, a, v);
    k_gram_topk<<<D * 6, 256>>>(t, a, v);
    k_fc<<<dim3(4, NNODE / 64), 256>>>(t, a, v, Wfc, bfc);
    k_edge<<<NNODE, 256>>>();
    k_node<<<NNODE, 256>>>();
    k_out<<<dim3(4, NNODE / 64), 256>>>(Wh, bh, out);
    k_norm<<<NROWS, 256>>>(out);
    k_tobf16<<<NROWS, 256>>>(out);
    k_sim_mma<<<dim3(32, 32, 3), 256>>>();
    k_loss<<<1, 256>>>(out, out_size);
}

// round 5
// speedup vs baseline: 2.9142x; 1.0464x over previous
#include <cuda_runtime.h>
#include <cuda_bf16.h>
#include <math.h>
#include <float.h>

#define D 64
#define L 64
#define DIMF 512
#define G 256
#define M 192                 // 3*L nodes (= hyperedges) per dialogue
#define KTOP 12
#define NROWS 4096            // D*L
#define NNODE (D*M)           // 12288
#define TAUINV (1.0f/0.07f)
#define SQTAUI 3.7796447300922722f   // sqrt(1/0.07)

// ---- scratch (static device arrays; no allocation allowed) ----
__device__ float    g_sq[NNODE];
__device__ unsigned g_H[NNODE*6];       // 192-bit incidence mask per edge
__device__ float    g_X[NNODE*G];
__device__ float    g_E[NNODE*G];
__device__ float    g_Y[NNODE*G];
__device__ float    g_diag[3*NROWS];
__device__ float    g_rowsum[3*NROWS];
__device__ float    g_colsum[3*NROWS];
__device__ __nv_bfloat16 g_nb[(size_t)3*NROWS*G];   // normalized bf16 features (loss path only)

__device__ __forceinline__ const float* feat_row(int d, int n,
        const float* t, const float* a, const float* v) {
    int mod = n >> 6, i = n & 63;
    const float* base = (mod == 0) ? t : (mod == 1) ? a : v;
    return base + (size_t)(d * L + i) * DIMF;
}

// ---- tf32 helpers ----
__device__ __forceinline__ unsigned f2tf(float x) {
    unsigned u; asm("cvt.rna.tf32.f32 %0, %1;" : "=r"(u) : "f"(x)); return u;
}
__device__ __forceinline__ void hilo(float x, unsigned& h, unsigned& l) {
    h = f2tf(x);
    l = f2tf(x - __uint_as_float(h));
}
// D = A(16x8,row) * B(8x8,col) + D, tf32
__device__ __forceinline__ void mma8(float* c, const unsigned* a, const unsigned* b) {
    asm volatile("mma.sync.aligned.m16n8k8.row.col.f32.tf32.tf32.f32 "
        "{%0,%1,%2,%3},{%4,%5,%6,%7},{%8,%9},{%0,%1,%2,%3};"
        : "+f"(c[0]), "+f"(c[1]), "+f"(c[2]), "+f"(c[3])
        : "r"(a[0]), "r"(a[1]), "r"(a[2]), "r"(a[3]), "r"(b[0]), "r"(b[1]));
}

// ---------------- K1: per-node squared norms ----------------
__global__ void k_sq(const float* t, const float* a, const float* v) {
    int warp = (blockIdx.x * blockDim.x + threadIdx.x) >> 5;
    int lane = threadIdx.x & 31;
    if (warp >= NNODE) return;
    int d = warp / M, n = warp % M;
    const float* r = feat_row(d, n, t, a, v);
    float s = 0.f;
    #pragma unroll
    for (int c = lane; c < DIMF; c += 32) { float x = r[c]; s += x * x; }
    #pragma unroll
    for (int o = 16; o; o >>= 1) s += __shfl_down_sync(0xffffffffu, s, o);
    if (lane == 0) g_sq[warp] = s;
}

// ---------------- K2: 3xTF32 gram + d2 + top-12 + incidence masks ----------------
// block tile: 32 rows x 192 cols per dialogue; grid (6, 64)
#define GAP 20     // A smem pitch (k chunk 16 + 4) -> conflict-free frag loads
#define GBP 200    // B smem pitch (192 + 8)        -> conflict-free frag loads
__global__ void __launch_bounds__(256) k_gram_mma(const float* t, const float* a,
                                                  const float* v) {
    __shared__ unsigned Ahi[32 * GAP], Alo[32 * GAP];
    __shared__ unsigned Bbuf[2 * 16 * GBP];          // hi | lo ; reused as d2 [32][192]
    __shared__ const float* ptrN[M];
    __shared__ float sq[M];
    unsigned* Bhi = Bbuf;
    unsigned* Blo = Bbuf + 16 * GBP;

    int d = blockIdx.y, i0 = blockIdx.x * 32;
    int tid = threadIdx.x, lane = tid & 31, warp = tid >> 5;
    int gq = lane >> 2, tq = lane & 3;
    if (tid < M) { ptrN[tid] = feat_row(d, tid, t, a, v); sq[tid] = g_sq[d * M + tid]; }
    __syncthreads();

    float acc[2][3][4];
    #pragma unroll
    for (int mi = 0; mi < 2; mi++)
        #pragma unroll
        for (int ni = 0; ni < 3; ni++)
            #pragma unroll
            for (int e = 0; e < 4; e++) acc[mi][ni][e] = 0.f;

    for (int kc = 0; kc < DIMF; kc += 16) {
        // A tile: 32 rows x 16 (rows i0..i0+31)
        {
            int r = tid >> 3, c = (tid & 7) * 2;
            float2 xv = *(const float2*)(ptrN[i0 + r] + kc + c);
            hilo(xv.x, Ahi[r * GAP + c],     Alo[r * GAP + c]);
            hilo(xv.y, Ahi[r * GAP + c + 1], Alo[r * GAP + c + 1]);
        }
        // B tile: all 192 nodes x 16, stored [k][n]
        #pragma unroll
        for (int it = 0; it < 3; it++) {
            int idx = tid + it * 256;
            int n = idx % 192, k4 = (idx / 192) * 4;
            float4 xv = *(const float4*)(ptrN[n] + kc + k4);
            hilo(xv.x, Bhi[(k4 + 0) * GBP + n], Blo[(k4 + 0) * GBP + n]);
            hilo(xv.y, Bhi[(k4 + 1) * GBP + n], Blo[(k4 + 1) * GBP + n]);
            hilo(xv.z, Bhi[(k4 + 2) * GBP + n], Blo[(k4 + 2) * GBP + n]);
            hilo(xv.w, Bhi[(k4 + 3) * GBP + n], Blo[(k4 + 3) * GBP + n]);
        }
        __syncthreads();
        #pragma unroll
        for (int k0 = 0; k0 < 16; k0 += 8) {
            unsigned ah[2][4], al[2][4], bh[3][2], bl[3][2];
            #pragma unroll
            for (int mi = 0; mi < 2; mi++) {
                int row = mi * 16;
                ah[mi][0] = Ahi[(row + gq) * GAP + k0 + tq];
                ah[mi][1] = Ahi[(row + gq + 8) * GAP + k0 + tq];
                ah[mi][2] = Ahi[(row + gq) * GAP + k0 + tq + 4];
                ah[mi][3] = Ahi[(row + gq + 8) * GAP + k0 + tq + 4];
                al[mi][0] = Alo[(row + gq) * GAP + k0 + tq];
                al[mi][1] = Alo[(row + gq + 8) * GAP + k0 + tq];
                al[mi][2] = Alo[(row + gq) * GAP + k0 + tq + 4];
                al[mi][3] = Alo[(row + gq + 8) * GAP + k0 + tq + 4];
            }
            #pragma unroll
            for (int ni = 0; ni < 3; ni++) {
                int c0 = warp * 24 + ni * 8;
                bh[ni][0] = Bhi[(k0 + tq) * GBP + c0 + gq];
                bh[ni][1] = Bhi[(k0 + tq + 4) * GBP + c0 + gq];
                bl[ni][0] = Blo[(k0 + tq) * GBP + c0 + gq];
                bl[ni][1] = Blo[(k0 + tq + 4) * GBP + c0 + gq];
            }
            #pragma unroll
            for (int mi = 0; mi < 2; mi++)
                #pragma unroll
                for (int ni = 0; ni < 3; ni++) {
                    mma8(acc[mi][ni], ah[mi], bh[ni]);
                    mma8(acc[mi][ni], ah[mi], bl[ni]);
                    mma8(acc[mi][ni], al[mi], bh[ni]);
                }
        }
        __syncthreads();
    }

    // d2 into reused B buffer, pitch 192
    float* d2s = (float*)Bbuf;
    #pragma unroll
    for (int mi = 0; mi < 2; mi++)
        #pragma unroll
        for (int ni = 0; ni < 3; ni++)
            #pragma unroll
            for (int e = 0; e < 4; e++) {
                int r = mi * 16 + gq + (e >> 1) * 8;
                int c = warp * 24 + ni * 8 + 2 * tq + (e & 1);
                float v2 = sq[i0 + r] + sq[c] - 2.f * acc[mi][ni][e];
                d2s[r * 192 + c] = fmaxf(v2, 0.f);
            }
    __syncthreads();

    // top-12 smallest per row (tie -> lower index), one warp per 4 rows
    int tx = lane;
    for (int q = 0; q < 4; q++) {
        int r = warp * 4 + q;
        float val[6];
        #pragma unroll
        for (int s = 0; s < 6; s++) val[s] = d2s[r * 192 + tx + 32 * s];
        unsigned mask[6] = {0, 0, 0, 0, 0, 0};
        for (int pick = 0; pick < KTOP; pick++) {
            float bv = val[0]; int bi = tx;
            #pragma unroll
            for (int s = 1; s < 6; s++) {
                float vv = val[s];
                if (vv < bv) { bv = vv; bi = tx + 32 * s; }
            }
            #pragma unroll
            for (int o = 16; o; o >>= 1) {
                float ov = __shfl_down_sync(0xffffffffu, bv, o);
                int   oi = __shfl_down_sync(0xffffffffu, bi, o);
                if (ov < bv || (ov == bv && oi < bi)) { bv = ov; bi = oi; }
            }
            bi = __shfl_sync(0xffffffffu, bi, 0);
            if ((bi & 31) == tx) val[bi >> 5] = FLT_MAX;
            mask[bi >> 5] |= 1u << (bi & 31);
        }
        if (tx == 0) {
            int e = i0 + r;
            int u = e / 3;
            mask[u >> 5]           |= 1u << (u & 31);
            mask[(u + 64) >> 5]    |= 1u << ((u + 64) & 31);
            mask[(u + 128) >> 5]   |= 1u << ((u + 128) & 31);
            #pragma unroll
            for (int w = 0; w < 6; w++)
                g_H[(size_t)(d * M + e) * 6 + w] = mask[w];
        }
    }
}

// ---------------- K3: X = feat @ W_fc + b_fc  (tf32 mma, 128x128 tile) ----------------
#define FAP 36
#define FBP 136
__global__ void __launch_bounds__(256) k_fc_mma(const float* t, const float* a,
        const float* v, const float* Wfc, const float* bfc) {
    __shared__ unsigned sA[128 * FAP];
    __shared__ unsigned sB[32 * FBP];
    __shared__ const float* ptrA[128];
    int bn = blockIdx.x, bm = blockIdx.y;
    int tid = threadIdx.x, lane = tid & 31, warp = tid >> 5;
    int wy = warp >> 1, wx = warp & 1;
    int gq = lane >> 2, tq = lane & 3;
    if (tid < 128) { int gn = bm * 128 + tid; ptrA[tid] = feat_row(gn / M, gn % M, t, a, v); }
    __syncthreads();

    float acc[2][8][4];
    #pragma unroll
    for (int mi = 0; mi < 2; mi++)
        #pragma unroll
        for (int ni = 0; ni < 8; ni++)
            #pragma unroll
            for (int e = 0; e < 4; e++) acc[mi][ni][e] = 0.f;

    for (int kc = 0; kc < DIMF; kc += 32) {
        #pragma unroll
        for (int it = 0; it < 4; it++) {
            int idx = tid + it * 256;
            int r = idx >> 3, c = (idx & 7) * 4;
            float4 xv = *(const float4*)(ptrA[r] + kc + c);
            sA[r * FAP + c]     = f2tf(xv.x);
            sA[r * FAP + c + 1] = f2tf(xv.y);
            sA[r * FAP + c + 2] = f2tf(xv.z);
            sA[r * FAP + c + 3] = f2tf(xv.w);
        }
        #pragma unroll
        for (int it = 0; it < 4; it++) {
            int idx = tid + it * 256;
            int kr = idx >> 5, n4 = (idx & 31) * 4;
            float4 wv = *(const float4*)(Wfc + (size_t)(kc + kr) * G + bn * 128 + n4);
            sB[kr * FBP + n4]     = f2tf(wv.x);
            sB[kr * FBP + n4 + 1] = f2tf(wv.y);
            sB[kr * FBP + n4 + 2] = f2tf(wv.z);
            sB[kr * FBP + n4 + 3] = f2tf(wv.w);
        }
        __syncthreads();
        #pragma unroll
        for (int k0 = 0; k0 < 32; k0 += 8) {
            unsigned af[2][4], bf[8][2];
            #pragma unroll
            for (int mi = 0; mi < 2; mi++) {
                int row = wy * 32 + mi * 16;
                af[mi][0] = sA[(row + gq) * FAP + k0 + tq];
                af[mi][1] = sA[(row + gq + 8) * FAP + k0 + tq];
                af[mi][2] = sA[(row + gq) * FAP + k0 + tq + 4];
                af[mi][3] = sA[(row + gq + 8) * FAP + k0 + tq + 4];
            }
            #pragma unroll
            for (int ni = 0; ni < 8; ni++) {
                int c0 = wx * 64 + ni * 8;
                bf[ni][0] = sB[(k0 + tq) * FBP + c0 + gq];
                bf[ni][1] = sB[(k0 + tq + 4) * FBP + c0 + gq];
            }
            #pragma unroll
            for (int mi = 0; mi < 2; mi++)
                #pragma unroll
                for (int ni = 0; ni < 8; ni++)
                    mma8(acc[mi][ni], af[mi], bf[ni]);
        }
        __syncthreads();
    }
    #pragma unroll
    for (int mi = 0; mi < 2; mi++)
        #pragma unroll
        for (int ni = 0; ni < 8; ni++)
            #pragma unroll
            for (int e = 0; e < 4; e++) {
                int r  = bm * 128 + wy * 32 + mi * 16 + gq + (e >> 1) * 8;
                int cc = bn * 128 + wx * 64 + ni * 8 + 2 * tq + (e & 1);
                g_X[(size_t)r * G + cc] = acc[mi][ni][e] + bfc[cc];
            }
}

// ---------------- K4: edge features E (mean over member nodes) ----------------
__global__ void k_edge() {
    int eg = blockIdx.x;
    __shared__ int lst[16];
    __shared__ int scnt;
    int tid = threadIdx.x;
    if (tid == 0) {
        int pos = 0;
        #pragma unroll
        for (int w = 0; w < 6; w++) {
            unsigned b = g_H[(size_t)eg * 6 + w];
            while (b) { lst[pos++] = w * 32 + __ffs(b) - 1; b &= b - 1; }
        }
        scnt = pos;
    }
    __syncthreads();
    int cnt = scnt;
    int d = eg / M;
    int g = tid;
    const float* Xb = g_X + (size_t)d * M * G;
    float s0 = 0.f, s1 = 0.f, s2 = 0.f, s3 = 0.f;
    int i = 0;
    for (; i + 3 < cnt; i += 4) {
        s0 += Xb[(size_t)lst[i] * G + g];
        s1 += Xb[(size_t)lst[i + 1] * G + g];
        s2 += Xb[(size_t)lst[i + 2] * G + g];
        s3 += Xb[(size_t)lst[i + 3] * G + g];
    }
    for (; i < cnt; i++) s0 += Xb[(size_t)lst[i] * G + g];
    g_E[(size_t)eg * G + g] = ((s0 + s1) + (s2 + s3)) / (float)cnt;
}

// ---------------- K5: node features Y (mean over incident edges) ----------------
__global__ void k_node() {
    int ng = blockIdx.x;
    int d = ng / M, n = ng % M;
    __shared__ unsigned cm[6];
    __shared__ int lst[192];
    __shared__ int scnt;
    int tid = threadIdx.x;
    int w = tid >> 5, lane = tid & 31;
    if (w < 6) {
        unsigned bit = (g_H[(size_t)(d * M + tid) * 6 + (n >> 5)] >> (n & 31)) & 1u;
        unsigned bal = __ballot_sync(0xffffffffu, bit != 0);
        if (lane == 0) cm[w] = bal;
    }
    __syncthreads();
    if (tid == 0) {
        int pos = 0;
        #pragma unroll
        for (int w2 = 0; w2 < 6; w2++) {
            unsigned b = cm[w2];
            while (b) { lst[pos++] = w2 * 32 + __ffs(b) - 1; b &= b - 1; }
        }
        scnt = pos;
    }
    __syncthreads();
    int cnt = scnt;
    int g = tid;
    const float* Eb = g_E + (size_t)d * M * G;
    float s0 = 0.f, s1 = 0.f, s2 = 0.f, s3 = 0.f;
    int i = 0;
    for (; i + 3 < cnt; i += 4) {
        s0 += Eb[(size_t)lst[i] * G + g];
        s1 += Eb[(size_t)lst[i + 1] * G + g];
        s2 += Eb[(size_t)lst[i + 2] * G + g];
        s3 += Eb[(size_t)lst[i + 3] * G + g];
    }
    for (; i < cnt; i++) s0 += Eb[(size_t)lst[i] * G + g];
    g_Y[(size_t)ng * G + g] = ((s0 + s1) + (s2 + s3)) / (float)cnt;
}

// ---------------- K6: out = relu(Y @ W_h + b_h) (tf32 mma), regrouped ----------------
__global__ void __launch_bounds__(256) k_out_mma(const float* Wh, const float* bh,
                                                 float* out) {
    __shared__ unsigned sA[128 * FAP];
    __shared__ unsigned sB[32 * FBP];
    int bn = blockIdx.x, bm = blockIdx.y;
    int tid = threadIdx.x, lane = tid & 31, warp = tid >> 5;
    int wy = warp >> 1, wx = warp & 1;
    int gq = lane >> 2, tq = lane & 3;

    float acc[2][8][4];
    #pragma unroll
    for (int mi = 0; mi < 2; mi++)
        #pragma unroll
        for (int ni = 0; ni < 8; ni++)
            #pragma unroll
            for (int e = 0; e < 4; e++) acc[mi][ni][e] = 0.f;

    for (int kc = 0; kc < G; kc += 32) {
        #pragma unroll
        for (int it = 0; it < 4; it++) {
            int idx = tid + it * 256;
            int r = idx >> 3, c = (idx & 7) * 4;
            float4 xv = *(const float4*)(g_Y + (size_t)(bm * 128 + r) * G + kc + c);
            sA[r * FAP + c]     = f2tf(xv.x);
            sA[r * FAP + c + 1] = f2tf(xv.y);
            sA[r * FAP + c + 2] = f2tf(xv.z);
            sA[r * FAP + c + 3] = f2tf(xv.w);
        }
        #pragma unroll
        for (int it = 0; it < 4; it++) {
            int idx = tid + it * 256;
            int kr = idx >> 5, n4 = (idx & 31) * 4;
            float4 wv = *(const float4*)(Wh + (size_t)(kc + kr) * G + bn * 128 + n4);
            sB[kr * FBP + n4]     = f2tf(wv.x);
            sB[kr * FBP + n4 + 1] = f2tf(wv.y);
            sB[kr * FBP + n4 + 2] = f2tf(wv.z);
            sB[kr * FBP + n4 + 3] = f2tf(wv.w);
        }
        __syncthreads();
        #pragma unroll
        for (int k0 = 0; k0 < 32; k0 += 8) {
            unsigned af[2][4], bf[8][2];
            #pragma unroll
            for (int mi = 0; mi < 2; mi++) {
                int row = wy * 32 + mi * 16;
                af[mi][0] = sA[(row + gq) * FAP + k0 + tq];
                af[mi][1] = sA[(row + gq + 8) * FAP + k0 + tq];
                af[mi][2] = sA[(row + gq) * FAP + k0 + tq + 4];
                af[mi][3] = sA[(row + gq + 8) * FAP + k0 + tq + 4];
            }
            #pragma unroll
            for (int ni = 0; ni < 8; ni++) {
                int c0 = wx * 64 + ni * 8;
                bf[ni][0] = sB[(k0 + tq) * FBP + c0 + gq];
                bf[ni][1] = sB[(k0 + tq + 4) * FBP + c0 + gq];
            }
            #pragma unroll
            for (int mi = 0; mi < 2; mi++)
                #pragma unroll
                for (int ni = 0; ni < 8; ni++)
                    mma8(acc[mi][ni], af[mi], bf[ni]);
        }
        __syncthreads();
    }
    #pragma unroll
    for (int mi = 0; mi < 2; mi++)
        #pragma unroll
        for (int ni = 0; ni < 8; ni++)
            #pragma unroll
            for (int e = 0; e < 4; e++) {
                int gn = bm * 128 + wy * 32 + mi * 16 + gq + (e >> 1) * 8;
                int gc = bn * 128 + wx * 64 + ni * 8 + 2 * tq + (e & 1);
                int dd = gn / M, n = gn % M, mod = n >> 6, ii = n & 63;
                out[(size_t)(dd * L + ii) * 768 + mod * 256 + gc] =
                    fmaxf(acc[mi][ni][e] + bh[gc], 0.f);
            }
}

// ---------------- K7: norms, diag sims, zero LSE accumulators, bf16 convert ----------------
__global__ void k_norm(const float* out) {
    int i = blockIdx.x;
    int tid = threadIdx.x;
    float tv = out[(size_t)i * 768 + tid];
    float av = out[(size_t)i * 768 + 256 + tid];
    float vv = out[(size_t)i * 768 + 512 + tid];
    float q[6] = { tv * tv, av * av, vv * vv, tv * av, tv * vv, av * vv };
    __shared__ float red[6][8];
    __shared__ float sinv[3];
    int lane = tid & 31, w = tid >> 5;
    #pragma unroll
    for (int o = 16; o; o >>= 1)
        #pragma unroll
        for (int k = 0; k < 6; k++) q[k] += __shfl_down_sync(0xffffffffu, q[k], o);
    if (lane == 0)
        #pragma unroll
        for (int k = 0; k < 6; k++) red[k][w] = q[k];
    __syncthreads();
    if (tid == 0) {
        float s[6];
        #pragma unroll
        for (int k = 0; k < 6; k++) {
            s[k] = 0.f;
            #pragma unroll
            for (int w2 = 0; w2 < 8; w2++) s[k] += red[k][w2];
        }
        float it = 1.f / (sqrtf(s[0]) + 1e-8f);
        float ia = 1.f / (sqrtf(s[1]) + 1e-8f);
        float iv = 1.f / (sqrtf(s[2]) + 1e-8f);
        sinv[0] = it * SQTAUI; sinv[1] = ia * SQTAUI; sinv[2] = iv * SQTAUI;
        g_diag[i]             = s[3] * it * ia * TAUINV;
        g_diag[NROWS + i]     = s[4] * it * iv * TAUINV;
        g_diag[2 * NROWS + i] = s[5] * ia * iv * TAUINV;
        g_rowsum[i] = 0.f; g_rowsum[NROWS + i] = 0.f; g_rowsum[2 * NROWS + i] = 0.f;
        g_colsum[i] = 0.f; g_colsum[NROWS + i] = 0.f; g_colsum[2 * NROWS + i] = 0.f;
    }
    __syncthreads();
    g_nb[((size_t)0 * NROWS + i) * G + tid] = __float2bfloat16(tv * sinv[0]);
    g_nb[((size_t)1 * NROWS + i) * G + tid] = __float2bfloat16(av * sinv[1]);
    g_nb[((size_t)2 * NROWS + i) * G + tid] = __float2bfloat16(vv * sinv[2]);
}

// ---------------- K8: bf16 tensor-core sim tiles + streaming exp-sum ----------------
#define SPITCH 40   // bf16 elements per smem row (80B; 8-lane ldmatrix groups conflict-free)
__global__ void __launch_bounds__(256) k_sim_mma() {
    int p = blockIdx.z;
    int mx = (p == 2) ? 1 : 0;
    int my = (p == 0) ? 1 : 2;
    int row0 = blockIdx.y * 128, col0 = blockIdx.x * 128;
    __shared__ __nv_bfloat16 sX[128 * SPITCH];
    __shared__ __nv_bfloat16 sY[128 * SPITCH];
    __shared__ float srow[128], scol[128];
    int tid = threadIdx.x, lane = tid & 31, warp = tid >> 5;
    int wy = warp >> 1, wx = warp & 1;      // warp tile: 32 rows x 64 cols

    const __nv_bfloat16* xg = g_nb + ((size_t)mx * NROWS + row0) * G;
    const __nv_bfloat16* yg = g_nb + ((size_t)my * NROWS + col0) * G;

    float acc[2][8][4];
    #pragma unroll
    for (int mi = 0; mi < 2; mi++)
        #pragma unroll
        for (int ni = 0; ni < 8; ni++)
            #pragma unroll
            for (int r = 0; r < 4; r++) acc[mi][ni][r] = 0.f;

    for (int kc = 0; kc < G; kc += 32) {
        #pragma unroll
        for (int i = 0; i < 2; i++) {
            int idx = tid + i * 256;          // 0..511
            int r = idx >> 2, c = (idx & 3) * 8;
            *(uint4*)(sX + r * SPITCH + c) = *(const uint4*)(xg + (size_t)r * G + kc + c);
            *(uint4*)(sY + r * SPITCH + c) = *(const uint4*)(yg + (size_t)r * G + kc + c);
        }
        __syncthreads();
        #pragma unroll
        for (int ks = 0; ks < 2; ks++) {
            int k0 = ks * 16;
            unsigned A[2][4];
            #pragma unroll
            for (int mi = 0; mi < 2; mi++) {
                int r = wy * 32 + mi * 16 + ((lane >> 3) & 1) * 8 + (lane & 7);
                int cc = k0 + (lane >> 4) * 8;
                unsigned ad = (unsigned)__cvta_generic_to_shared(sX + r * SPITCH + cc);
                asm volatile("ldmatrix.sync.aligned.m8n8.x4.shared.b16 {%0,%1,%2,%3},[%4];"
                    : "=r"(A[mi][0]), "=r"(A[mi][1]), "=r"(A[mi][2]), "=r"(A[mi][3])
                    : "r"(ad));
            }
            unsigned B[8][2];
            #pragma unroll
            for (int nb = 0; nb < 4; nb++) {
                int r = wx * 64 + nb * 16 + (lane >> 4) * 8 + (lane & 7);
                int cc = k0 + ((lane >> 3) & 1) * 8;
                unsigned ad = (unsigned)__cvta_generic_to_shared(sY + r * SPITCH + cc);
                asm volatile("ldmatrix.sync.aligned.m8n8.x4.shared.b16 {%0,%1,%2,%3},[%4];"
                    : "=r"(B[2 * nb][0]), "=r"(B[2 * nb][1]),
                      "=r"(B[2 * nb + 1][0]), "=r"(B[2 * nb + 1][1])
                    : "r"(ad));
            }
            #pragma unroll
            for (int mi = 0; mi < 2; mi++)
                #pragma unroll
                for (int ni = 0; ni < 8; ni++)
                    asm volatile(
                        "mma.sync.aligned.m16n8k16.row.col.f32.bf16.bf16.f32 "
                        "{%0,%1,%2,%3},{%4,%5,%6,%7},{%8,%9},{%0,%1,%2,%3};"
                        : "+f"(acc[mi][ni][0]), "+f"(acc[mi][ni][1]),
                          "+f"(acc[mi][ni][2]), "+f"(acc[mi][ni][3])
                        : "r"(A[mi][0]), "r"(A[mi][1]), "r"(A[mi][2]), "r"(A[mi][3]),
                          "r"(B[ni][0]), "r"(B[ni][1]));
        }
        __syncthreads();
    }

    if (tid < 128) { srow[tid] = 0.f; scol[tid] = 0.f; }
    __syncthreads();

    float rowp[2][2] = {{0.f, 0.f}, {0.f, 0.f}};
    float colp[8][2];
    #pragma unroll
    for (int ni = 0; ni < 8; ni++) { colp[ni][0] = 0.f; colp[ni][1] = 0.f; }
    #pragma unroll
    for (int mi = 0; mi < 2; mi++)
        #pragma unroll
        for (int ni = 0; ni < 8; ni++)
            #pragma unroll
            for (int r = 0; r < 4; r++) {
                float e = __expf(acc[mi][ni][r]);
                rowp[mi][r >> 1] += e;
                colp[ni][r & 1] += e;
            }

    #pragma unroll
    for (int mi = 0; mi < 2; mi++)
        #pragma unroll
        for (int h = 0; h < 2; h++) {
            float vv = rowp[mi][h];
            vv += __shfl_xor_sync(0xffffffffu, vv, 1);
            vv += __shfl_xor_sync(0xffffffffu, vv, 2);
            if ((lane & 3) == 0)
                atomicAdd(&srow[wy * 32 + mi * 16 + (lane >> 2) + h * 8], vv);
        }
    #pragma unroll
    for (int ni = 0; ni < 8; ni++)
        #pragma unroll
        for (int s2 = 0; s2 < 2; s2++) {
            float vv = colp[ni][s2];
            vv += __shfl_xor_sync(0xffffffffu, vv, 4);
            vv += __shfl_xor_sync(0xffffffffu, vv, 8);
            vv += __shfl_xor_sync(0xffffffffu, vv, 16);
            if (lane < 4)
                atomicAdd(&scol[wx * 64 + ni * 8 + lane * 2 + s2], vv);
        }
    __syncthreads();
    if (tid < 128) {
        atomicAdd(&g_rowsum[p * NROWS + row0 + tid], srow[tid]);
        atomicAdd(&g_colsum[p * NROWS + col0 + tid], scol[tid]);
    }
}

// ---------------- K9: final loss reduction ----------------
__global__ void k_loss(float* out, int out_size) {
    int tid = threadIdx.x;
    float s = 0.f;
    for (int idx = tid; idx < 3 * NROWS; idx += 256) {
        float dg = g_diag[idx];
        s += 2.f * dg - logf(g_rowsum[idx]) - logf(g_colsum[idx]);
    }
    __shared__ float red[8];
    int lane = tid & 31, w = tid >> 5;
    #pragma unroll
    for (int o = 16; o; o >>= 1) s += __shfl_down_sync(0xffffffffu, s, o);
    if (lane == 0) red[w] = s;
    __syncthreads();
    if (tid == 0) {
        float tot = 0.f;
        #pragma unroll
        for (int w2 = 0; w2 < 8; w2++) tot += red[w2];
        float loss = -tot / (2.f * 3.f * (float)NROWS);
        if (out_size > NROWS * 768) out[NROWS * 768] = loss;
    }
}

// ---------------- launcher ----------------
extern "C" void kernel_launch(void* const* d_in, const int* in_sizes, int n_in,
                              void* d_out, int out_size) {
    const float* t   = (const float*)d_in[0];
    const float* a   = (const float*)d_in[1];
    const float* v   = (const float*)d_in[2];
    const float* Wfc = (const float*)d_in[3];
    const float* bfc = (const float*)d_in[4];
    const float* Wh  = (const float*)d_in[5];
    const float* bh  = (const float*)d_in[6];
    float* out = (float*)d_out;

    k_sq<<<NNODE / 8, 256>>>(t, a, v);
    k_gram_mma<<<dim3(6, 64), 256>>>(t, a, v);
    k_fc_mma<<<dim3(2, 96), 256>>>(t, a, v, Wfc, bfc);
    k_edge<<<NNODE, 256>>>();
    k_node<<<NNODE, 256>>>();
    k_out_mma<<<dim3(2, 96), 256>>>(Wh, bh, out);
    k_norm<<<NROWS, 256>>>(out);
    k_sim_mma<<<dim3(32, 32, 3), 256>>>();
    k_loss<<<1, 256>>>(out, out_size);
}

// round 6
// speedup vs baseline: 4.7653x; 1.6352x over previous
#include <cuda_runtime.h>
#include <cuda_bf16.h>
#include <math.h>
#include <float.h>

#define D 64
#define L 64
#define DIMF 512
#define G 256
#define M 192                 // 3*L nodes (= hyperedges) per dialogue
#define KTOP 12
#define NROWS 4096            // D*L
#define NNODE (D*M)           // 12288
#define TAUINV (1.0f/0.07f)
#define SQTAUI 3.7796447300922722f   // sqrt(1/0.07)

// ---- scratch (static device arrays; no allocation allowed) ----
__device__ float    g_sq[NNODE];
__device__ unsigned g_H[NNODE*6];       // 192-bit incidence mask per edge
__device__ float    g_X[NNODE*G];
__device__ float    g_E[NNODE*G];
__device__ float    g_Y[NNODE*G];
__device__ float    g_diag[3*NROWS];
__device__ float    g_rowsum[3*NROWS];
__device__ float    g_colsum[3*NROWS];
__device__ __nv_bfloat16 g_nb[(size_t)3*NROWS*G];   // normalized bf16 features (loss path only)

__device__ __forceinline__ const float* feat_row(int d, int n,
        const float* t, const float* a, const float* v) {
    int mod = n >> 6, i = n & 63;
    const float* base = (mod == 0) ? t : (mod == 1) ? a : v;
    return base + (size_t)(d * L + i) * DIMF;
}

// ---- tf32 helpers ----
__device__ __forceinline__ unsigned f2tf(float x) {
    unsigned u; asm("cvt.rna.tf32.f32 %0, %1;" : "=r"(u) : "f"(x)); return u;
}
__device__ __forceinline__ void hilo(float x, unsigned& h, unsigned& l) {
    h = f2tf(x);
    l = f2tf(x - __uint_as_float(h));
}
// D = A(16x8,row) * B(8x8,col) + D, tf32
__device__ __forceinline__ void mma8(float* c, const unsigned* a, const unsigned* b) {
    asm volatile("mma.sync.aligned.m16n8k8.row.col.f32.tf32.tf32.f32 "
        "{%0,%1,%2,%3},{%4,%5,%6,%7},{%8,%9},{%0,%1,%2,%3};"
        : "+f"(c[0]), "+f"(c[1]), "+f"(c[2]), "+f"(c[3])
        : "r"(a[0]), "r"(a[1]), "r"(a[2]), "r"(a[3]), "r"(b[0]), "r"(b[1]));
}

// ---------------- K1: per-node squared norms ----------------
__global__ void k_sq(const float* t, const float* a, const float* v) {
    int warp = (blockIdx.x * blockDim.x + threadIdx.x) >> 5;
    int lane = threadIdx.x & 31;
    if (warp >= NNODE) return;
    int d = warp / M, n = warp % M;
    const float* r = feat_row(d, n, t, a, v);
    float s = 0.f;
    #pragma unroll
    for (int c = lane; c < DIMF; c += 32) { float x = r[c]; s += x * x; }
    #pragma unroll
    for (int o = 16; o; o >>= 1) s += __shfl_down_sync(0xffffffffu, s, o);
    if (lane == 0) g_sq[warp] = s;
}

// ---------------- K2: 3xTF32 gram + d2 + top-12 + incidence masks ----------------
#define GAP 20     // A smem pitch (k chunk 16 + 4) -> conflict-free frag loads
#define GBP 200    // B smem pitch (192 + 8)        -> conflict-free frag loads
__global__ void __launch_bounds__(256) k_gram_mma(const float* t, const float* a,
                                                  const float* v) {
    __shared__ unsigned Ahi[32 * GAP], Alo[32 * GAP];
    __shared__ unsigned Bbuf[2 * 16 * GBP];          // hi | lo ; reused as d2 [32][192]
    __shared__ const float* ptrN[M];
    __shared__ float sq[M];
    unsigned* Bhi = Bbuf;
    unsigned* Blo = Bbuf + 16 * GBP;

    int d = blockIdx.y, i0 = blockIdx.x * 32;
    int tid = threadIdx.x, lane = tid & 31, warp = tid >> 5;
    int gq = lane >> 2, tq = lane & 3;
    if (tid < M) { ptrN[tid] = feat_row(d, tid, t, a, v); sq[tid] = g_sq[d * M + tid]; }
    __syncthreads();

    float acc[2][3][4];
    #pragma unroll
    for (int mi = 0; mi < 2; mi++)
        #pragma unroll
        for (int ni = 0; ni < 3; ni++)
            #pragma unroll
            for (int e = 0; e < 4; e++) acc[mi][ni][e] = 0.f;

    for (int kc = 0; kc < DIMF; kc += 16) {
        {
            int r = tid >> 3, c = (tid & 7) * 2;
            float2 xv = *(const float2*)(ptrN[i0 + r] + kc + c);
            hilo(xv.x, Ahi[r * GAP + c],     Alo[r * GAP + c]);
            hilo(xv.y, Ahi[r * GAP + c + 1], Alo[r * GAP + c + 1]);
        }
        #pragma unroll
        for (int it = 0; it < 3; it++) {
            int idx = tid + it * 256;
            int n = idx % 192, k4 = (idx / 192) * 4;
            float4 xv = *(const float4*)(ptrN[n] + kc + k4);
            hilo(xv.x, Bhi[(k4 + 0) * GBP + n], Blo[(k4 + 0) * GBP + n]);
            hilo(xv.y, Bhi[(k4 + 1) * GBP + n], Blo[(k4 + 1) * GBP + n]);
            hilo(xv.z, Bhi[(k4 + 2) * GBP + n], Blo[(k4 + 2) * GBP + n]);
            hilo(xv.w, Bhi[(k4 + 3) * GBP + n], Blo[(k4 + 3) * GBP + n]);
        }
        __syncthreads();
        #pragma unroll
        for (int k0 = 0; k0 < 16; k0 += 8) {
            unsigned ah[2][4], al[2][4], bh[3][2], bl[3][2];
            #pragma unroll
            for (int mi = 0; mi < 2; mi++) {
                int row = mi * 16;
                ah[mi][0] = Ahi[(row + gq) * GAP + k0 + tq];
                ah[mi][1] = Ahi[(row + gq + 8) * GAP + k0 + tq];
                ah[mi][2] = Ahi[(row + gq) * GAP + k0 + tq + 4];
                ah[mi][3] = Ahi[(row + gq + 8) * GAP + k0 + tq + 4];
                al[mi][0] = Alo[(row + gq) * GAP + k0 + tq];
                al[mi][1] = Alo[(row + gq + 8) * GAP + k0 + tq];
                al[mi][2] = Alo[(row + gq) * GAP + k0 + tq + 4];
                al[mi][3] = Alo[(row + gq + 8) * GAP + k0 + tq + 4];
            }
            #pragma unroll
            for (int ni = 0; ni < 3; ni++) {
                int c0 = warp * 24 + ni * 8;
                bh[ni][0] = Bhi[(k0 + tq) * GBP + c0 + gq];
                bh[ni][1] = Bhi[(k0 + tq + 4) * GBP + c0 + gq];
                bl[ni][0] = Blo[(k0 + tq) * GBP + c0 + gq];
                bl[ni][1] = Blo[(k0 + tq + 4) * GBP + c0 + gq];
            }
            #pragma unroll
            for (int mi = 0; mi < 2; mi++)
                #pragma unroll
                for (int ni = 0; ni < 3; ni++) {
                    mma8(acc[mi][ni], ah[mi], bh[ni]);
                    mma8(acc[mi][ni], ah[mi], bl[ni]);
                    mma8(acc[mi][ni], al[mi], bh[ni]);
                }
        }
        __syncthreads();
    }

    float* d2s = (float*)Bbuf;
    #pragma unroll
    for (int mi = 0; mi < 2; mi++)
        #pragma unroll
        for (int ni = 0; ni < 3; ni++)
            #pragma unroll
            for (int e = 0; e < 4; e++) {
                int r = mi * 16 + gq + (e >> 1) * 8;
                int c = warp * 24 + ni * 8 + 2 * tq + (e & 1);
                float v2 = sq[i0 + r] + sq[c] - 2.f * acc[mi][ni][e];
                d2s[r * 192 + c] = fmaxf(v2, 0.f);
            }
    __syncthreads();

    int tx = lane;
    for (int q = 0; q < 4; q++) {
        int r = warp * 4 + q;
        float val[6];
        #pragma unroll
        for (int s = 0; s < 6; s++) val[s] = d2s[r * 192 + tx + 32 * s];
        unsigned mask[6] = {0, 0, 0, 0, 0, 0};
        for (int pick = 0; pick < KTOP; pick++) {
            float bv = val[0]; int bi = tx;
            #pragma unroll
            for (int s = 1; s < 6; s++) {
                float vv = val[s];
                if (vv < bv) { bv = vv; bi = tx + 32 * s; }
            }
            #pragma unroll
            for (int o = 16; o; o >>= 1) {
                float ov = __shfl_down_sync(0xffffffffu, bv, o);
                int   oi = __shfl_down_sync(0xffffffffu, bi, o);
                if (ov < bv || (ov == bv && oi < bi)) { bv = ov; bi = oi; }
            }
            bi = __shfl_sync(0xffffffffu, bi, 0);
            if ((bi & 31) == tx) val[bi >> 5] = FLT_MAX;
            mask[bi >> 5] |= 1u << (bi & 31);
        }
        if (tx == 0) {
            int e = i0 + r;
            int u = e / 3;
            mask[u >> 5]           |= 1u << (u & 31);
            mask[(u + 64) >> 5]    |= 1u << ((u + 64) & 31);
            mask[(u + 128) >> 5]   |= 1u << ((u + 128) & 31);
            #pragma unroll
            for (int w = 0; w < 6; w++)
                g_H[(size_t)(d * M + e) * 6 + w] = mask[w];
        }
    }
}

// ---------------- K3: X = feat @ W_fc + b_fc  (tf32 mma, 128x128 tile) ----------------
#define FAP 36
#define FBP 136
__global__ void __launch_bounds__(256) k_fc_mma(const float* t, const float* a,
        const float* v, const float* Wfc, const float* bfc) {
    __shared__ unsigned sA[128 * FAP];
    __shared__ unsigned sB[32 * FBP];
    __shared__ const float* ptrA[128];
    int bn = blockIdx.x, bm = blockIdx.y;
    int tid = threadIdx.x, lane = tid & 31, warp = tid >> 5;
    int wy = warp >> 1, wx = warp & 1;
    int gq = lane >> 2, tq = lane & 3;
    if (tid < 128) { int gn = bm * 128 + tid; ptrA[tid] = feat_row(gn / M, gn % M, t, a, v); }
    __syncthreads();

    float acc[2][8][4];
    #pragma unroll
    for (int mi = 0; mi < 2; mi++)
        #pragma unroll
        for (int ni = 0; ni < 8; ni++)
            #pragma unroll
            for (int e = 0; e < 4; e++) acc[mi][ni][e] = 0.f;

    for (int kc = 0; kc < DIMF; kc += 32) {
        #pragma unroll
        for (int it = 0; it < 4; it++) {
            int idx = tid + it * 256;
            int r = idx >> 3, c = (idx & 7) * 4;
            float4 xv = *(const float4*)(ptrA[r] + kc + c);
            sA[r * FAP + c]     = f2tf(xv.x);
            sA[r * FAP + c + 1] = f2tf(xv.y);
            sA[r * FAP + c + 2] = f2tf(xv.z);
            sA[r * FAP + c + 3] = f2tf(xv.w);
        }
        #pragma unroll
        for (int it = 0; it < 4; it++) {
            int idx = tid + it * 256;
            int kr = idx >> 5, n4 = (idx & 31) * 4;
            float4 wv = *(const float4*)(Wfc + (size_t)(kc + kr) * G + bn * 128 + n4);
            sB[kr * FBP + n4]     = f2tf(wv.x);
            sB[kr * FBP + n4 + 1] = f2tf(wv.y);
            sB[kr * FBP + n4 + 2] = f2tf(wv.z);
            sB[kr * FBP + n4 + 3] = f2tf(wv.w);
        }
        __syncthreads();
        #pragma unroll
        for (int k0 = 0; k0 < 32; k0 += 8) {
            unsigned af[2][4], bf[8][2];
            #pragma unroll
            for (int mi = 0; mi < 2; mi++) {
                int row = wy * 32 + mi * 16;
                af[mi][0] = sA[(row + gq) * FAP + k0 + tq];
                af[mi][1] = sA[(row + gq + 8) * FAP + k0 + tq];
                af[mi][2] = sA[(row + gq) * FAP + k0 + tq + 4];
                af[mi][3] = sA[(row + gq + 8) * FAP + k0 + tq + 4];
            }
            #pragma unroll
            for (int ni = 0; ni < 8; ni++) {
                int c0 = wx * 64 + ni * 8;
                bf[ni][0] = sB[(k0 + tq) * FBP + c0 + gq];
                bf[ni][1] = sB[(k0 + tq + 4) * FBP + c0 + gq];
            }
            #pragma unroll
            for (int mi = 0; mi < 2; mi++)
                #pragma unroll
                for (int ni = 0; ni < 8; ni++)
                    mma8(acc[mi][ni], af[mi], bf[ni]);
        }
        __syncthreads();
    }
    #pragma unroll
    for (int mi = 0; mi < 2; mi++)
        #pragma unroll
        for (int ni = 0; ni < 8; ni++)
            #pragma unroll
            for (int e = 0; e < 4; e++) {
                int r  = bm * 128 + wy * 32 + mi * 16 + gq + (e >> 1) * 8;
                int cc = bn * 128 + wx * 64 + ni * 8 + 2 * tq + (e & 1);
                g_X[(size_t)r * G + cc] = acc[mi][ni][e] + bfc[cc];
            }
}

// ---------------- K4: E = (H @ X) / deg_e  (dense tf32 mma per dialogue) ----------------
// A = H [192 e][192 n] 0/1 (exact in tf32); B = X hi/lo [192 n][128 cols]
#define AAP 20     // A pitch for 16-wide K chunk
#define ABP 132    // B pitch
__global__ void __launch_bounds__(256) k_agg_edge() {
    __shared__ unsigned sHw[192 * 6];
    __shared__ float    sdeg[192];
    __shared__ unsigned sA[192 * AAP];
    __shared__ unsigned sB[2 * 16 * ABP];     // hi | lo
    int d = blockIdx.y, n0 = blockIdx.x * 128;
    int tid = threadIdx.x, lane = tid & 31, warp = tid >> 5;
    int wy = warp >> 1, wx = warp & 1;        // wy: 48 rows, wx: 64 cols
    int gq = lane >> 2, tq = lane & 3;

    for (int i = tid; i < 192 * 6; i += 256) sHw[i] = g_H[(size_t)(d * M) * 6 + i];
    __syncthreads();
    if (tid < 192) {
        int deg = 0;
        #pragma unroll
        for (int w = 0; w < 6; w++) deg += __popc(sHw[tid * 6 + w]);
        sdeg[tid] = 1.f / (float)deg;
    }

    float acc[3][8][4];
    #pragma unroll
    for (int mi = 0; mi < 3; mi++)
        #pragma unroll
        for (int ni = 0; ni < 8; ni++)
            #pragma unroll
            for (int e = 0; e < 4; e++) acc[mi][ni][e] = 0.f;

    for (int kc = 0; kc < 192; kc += 16) {
        if (tid < 192) {
            unsigned w = sHw[tid * 6 + (kc >> 5)];
            int sh = kc & 16;
            #pragma unroll
            for (int c = 0; c < 16; c++)
                sA[tid * AAP + c] = ((w >> (sh + c)) & 1u) ? 0x3F800000u : 0u;
        }
        #pragma unroll
        for (int it = 0; it < 2; it++) {
            int idx = tid + it * 256;
            int kr = idx >> 5, c4 = (idx & 31) * 4;
            float4 xv = *(const float4*)(g_X + (size_t)(d * M + kc + kr) * G + n0 + c4);
            hilo(xv.x, sB[kr * ABP + c4],     sB[16 * ABP + kr * ABP + c4]);
            hilo(xv.y, sB[kr * ABP + c4 + 1], sB[16 * ABP + kr * ABP + c4 + 1]);
            hilo(xv.z, sB[kr * ABP + c4 + 2], sB[16 * ABP + kr * ABP + c4 + 2]);
            hilo(xv.w, sB[kr * ABP + c4 + 3], sB[16 * ABP + kr * ABP + c4 + 3]);
        }
        __syncthreads();
        #pragma unroll
        for (int k0 = 0; k0 < 16; k0 += 8) {
            unsigned af[3][4], bh[8][2], bl[8][2];
            #pragma unroll
            for (int mi = 0; mi < 3; mi++) {
                int row = wy * 48 + mi * 16;
                af[mi][0] = sA[(row + gq) * AAP + k0 + tq];
                af[mi][1] = sA[(row + gq + 8) * AAP + k0 + tq];
                af[mi][2] = sA[(row + gq) * AAP + k0 + tq + 4];
                af[mi][3] = sA[(row + gq + 8) * AAP + k0 + tq + 4];
            }
            #pragma unroll
            for (int ni = 0; ni < 8; ni++) {
                int c0 = wx * 64 + ni * 8;
                bh[ni][0] = sB[(k0 + tq) * ABP + c0 + gq];
                bh[ni][1] = sB[(k0 + tq + 4) * ABP + c0 + gq];
                bl[ni][0] = sB[16 * ABP + (k0 + tq) * ABP + c0 + gq];
                bl[ni][1] = sB[16 * ABP + (k0 + tq + 4) * ABP + c0 + gq];
            }
            #pragma unroll
            for (int mi = 0; mi < 3; mi++)
                #pragma unroll
                for (int ni = 0; ni < 8; ni++) {
                    mma8(acc[mi][ni], af[mi], bh[ni]);
                    mma8(acc[mi][ni], af[mi], bl[ni]);
                }
        }
        __syncthreads();
    }
    #pragma unroll
    for (int mi = 0; mi < 3; mi++)
        #pragma unroll
        for (int ni = 0; ni < 8; ni++)
            #pragma unroll
            for (int e = 0; e < 4; e++) {
                int r = wy * 48 + mi * 16 + gq + (e >> 1) * 8;
                int c = n0 + wx * 64 + ni * 8 + 2 * tq + (e & 1);
                g_E[(size_t)(d * M + r) * G + c] = acc[mi][ni][e] * sdeg[r];
            }
}

// ---------------- K5: Y = (H^T @ E) / deg_v  (dense tf32 mma per dialogue) ----------------
__global__ void __launch_bounds__(256) k_agg_node() {
    __shared__ unsigned sHw[192 * 6];
    __shared__ float    sdeg[192];
    __shared__ unsigned sA[192 * AAP];
    __shared__ unsigned sB[2 * 16 * ABP];
    int d = blockIdx.y, n0 = blockIdx.x * 128;
    int tid = threadIdx.x, lane = tid & 31, warp = tid >> 5;
    int wy = warp >> 1, wx = warp & 1;
    int gq = lane >> 2, tq = lane & 3;

    for (int i = tid; i < 192 * 6; i += 256) sHw[i] = g_H[(size_t)(d * M) * 6 + i];
    __syncthreads();
    if (tid < 192) {
        int wsel = tid >> 5, bsel = tid & 31;
        int deg = 0;
        for (int e = 0; e < 192; e++) deg += (sHw[e * 6 + wsel] >> bsel) & 1u;
        sdeg[tid] = 1.f / (float)deg;
    }

    float acc[3][8][4];
    #pragma unroll
    for (int mi = 0; mi < 3; mi++)
        #pragma unroll
        for (int ni = 0; ni < 8; ni++)
            #pragma unroll
            for (int e = 0; e < 4; e++) acc[mi][ni][e] = 0.f;

    for (int kc = 0; kc < 192; kc += 16) {
        if (tid < 192) {
            int wsel = tid >> 5, bsel = tid & 31;
            #pragma unroll
            for (int c = 0; c < 16; c++) {
                unsigned w = sHw[(kc + c) * 6 + wsel];
                sA[tid * AAP + c] = ((w >> bsel) & 1u) ? 0x3F800000u : 0u;
            }
        }
        #pragma unroll
        for (int it = 0; it < 2; it++) {
            int idx = tid + it * 256;
            int kr = idx >> 5, c4 = (idx & 31) * 4;
            float4 xv = *(const float4*)(g_E + (size_t)(d * M + kc + kr) * G + n0 + c4);
            hilo(xv.x, sB[kr * ABP + c4],     sB[16 * ABP + kr * ABP + c4]);
            hilo(xv.y, sB[kr * ABP + c4 + 1], sB[16 * ABP + kr * ABP + c4 + 1]);
            hilo(xv.z, sB[kr * ABP + c4 + 2], sB[16 * ABP + kr * ABP + c4 + 2]);
            hilo(xv.w, sB[kr * ABP + c4 + 3], sB[16 * ABP + kr * ABP + c4 + 3]);
        }
        __syncthreads();
        #pragma unroll
        for (int k0 = 0; k0 < 16; k0 += 8) {
            unsigned af[3][4], bh[8][2], bl[8][2];
            #pragma unroll
            for (int mi = 0; mi < 3; mi++) {
                int row = wy * 48 + mi * 16;
                af[mi][0] = sA[(row + gq) * AAP + k0 + tq];
                af[mi][1] = sA[(row + gq + 8) * AAP + k0 + tq];
                af[mi][2] = sA[(row + gq) * AAP + k0 + tq + 4];
                af[mi][3] = sA[(row + gq + 8) * AAP + k0 + tq + 4];
            }
            #pragma unroll
            for (int ni = 0; ni < 8; ni++) {
                int c0 = wx * 64 + ni * 8;
                bh[ni][0] = sB[(k0 + tq) * ABP + c0 + gq];
                bh[ni][1] = sB[(k0 + tq + 4) * ABP + c0 + gq];
                bl[ni][0] = sB[16 * ABP + (k0 + tq) * ABP + c0 + gq];
                bl[ni][1] = sB[16 * ABP + (k0 + tq + 4) * ABP + c0 + gq];
            }
            #pragma unroll
            for (int mi = 0; mi < 3; mi++)
                #pragma unroll
                for (int ni = 0; ni < 8; ni++) {
                    mma8(acc[mi][ni], af[mi], bh[ni]);
                    mma8(acc[mi][ni], af[mi], bl[ni]);
                }
        }
        __syncthreads();
    }
    #pragma unroll
    for (int mi = 0; mi < 3; mi++)
        #pragma unroll
        for (int ni = 0; ni < 8; ni++)
            #pragma unroll
            for (int e = 0; e < 4; e++) {
                int r = wy * 48 + mi * 16 + gq + (e >> 1) * 8;
                int c = n0 + wx * 64 + ni * 8 + 2 * tq + (e & 1);
                g_Y[(size_t)(d * M + r) * G + c] = acc[mi][ni][e] * sdeg[r];
            }
}

// ---------------- K6: out = relu(Y @ W_h + b_h) (tf32 mma), regrouped ----------------
__global__ void __launch_bounds__(256) k_out_mma(const float* Wh, const float* bh,
                                                 float* out) {
    __shared__ unsigned sA[128 * FAP];
    __shared__ unsigned sB[32 * FBP];
    int bn = blockIdx.x, bm = blockIdx.y;
    int tid = threadIdx.x, lane = tid & 31, warp = tid >> 5;
    int wy = warp >> 1, wx = warp & 1;
    int gq = lane >> 2, tq = lane & 3;

    float acc[2][8][4];
    #pragma unroll
    for (int mi = 0; mi < 2; mi++)
        #pragma unroll
        for (int ni = 0; ni < 8; ni++)
            #pragma unroll
            for (int e = 0; e < 4; e++) acc[mi][ni][e] = 0.f;

    for (int kc = 0; kc < G; kc += 32) {
        #pragma unroll
        for (int it = 0; it < 4; it++) {
            int idx = tid + it * 256;
            int r = idx >> 3, c = (idx & 7) * 4;
            float4 xv = *(const float4*)(g_Y + (size_t)(bm * 128 + r) * G + kc + c);
            sA[r * FAP + c]     = f2tf(xv.x);
            sA[r * FAP + c + 1] = f2tf(xv.y);
            sA[r * FAP + c + 2] = f2tf(xv.z);
            sA[r * FAP + c + 3] = f2tf(xv.w);
        }
        #pragma unroll
        for (int it = 0; it < 4; it++) {
            int idx = tid + it * 256;
            int kr = idx >> 5, n4 = (idx & 31) * 4;
            float4 wv = *(const float4*)(Wh + (size_t)(kc + kr) * G + bn * 128 + n4);
            sB[kr * FBP + n4]     = f2tf(wv.x);
            sB[kr * FBP + n4 + 1] = f2tf(wv.y);
            sB[kr * FBP + n4 + 2] = f2tf(wv.z);
            sB[kr * FBP + n4 + 3] = f2tf(wv.w);
        }
        __syncthreads();
        #pragma unroll
        for (int k0 = 0; k0 < 32; k0 += 8) {
            unsigned af[2][4], bf[8][2];
            #pragma unroll
            for (int mi = 0; mi < 2; mi++) {
                int row = wy * 32 + mi * 16;
                af[mi][0] = sA[(row + gq) * FAP + k0 + tq];
                af[mi][1] = sA[(row + gq + 8) * FAP + k0 + tq];
                af[mi][2] = sA[(row + gq) * FAP + k0 + tq + 4];
                af[mi][3] = sA[(row + gq + 8) * FAP + k0 + tq + 4];
            }
            #pragma unroll
            for (int ni = 0; ni < 8; ni++) {
                int c0 = wx * 64 + ni * 8;
                bf[ni][0] = sB[(k0 + tq) * FBP + c0 + gq];
                bf[ni][1] = sB[(k0 + tq + 4) * FBP + c0 + gq];
            }
            #pragma unroll
            for (int mi = 0; mi < 2; mi++)
                #pragma unroll
                for (int ni = 0; ni < 8; ni++)
                    mma8(acc[mi][ni], af[mi], bf[ni]);
        }
        __syncthreads();
    }
    #pragma unroll
    for (int mi = 0; mi < 2; mi++)
        #pragma unroll
        for (int ni = 0; ni < 8; ni++)
            #pragma unroll
            for (int e = 0; e < 4; e++) {
                int gn = bm * 128 + wy * 32 + mi * 16 + gq + (e >> 1) * 8;
                int gc = bn * 128 + wx * 64 + ni * 8 + 2 * tq + (e & 1);
                int dd = gn / M, n = gn % M, mod = n >> 6, ii = n & 63;
                out[(size_t)(dd * L + ii) * 768 + mod * 256 + gc] =
                    fmaxf(acc[mi][ni][e] + bh[gc], 0.f);
            }
}

// ---------------- K7: norms, diag sims, zero LSE accumulators, bf16 convert ----------------
__global__ void k_norm(const float* out) {
    int i = blockIdx.x;
    int tid = threadIdx.x;
    float tv = out[(size_t)i * 768 + tid];
    float av = out[(size_t)i * 768 + 256 + tid];
    float vv = out[(size_t)i * 768 + 512 + tid];
    float q[6] = { tv * tv, av * av, vv * vv, tv * av, tv * vv, av * vv };
    __shared__ float red[6][8];
    __shared__ float sinv[3];
    int lane = tid & 31, w = tid >> 5;
    #pragma unroll
    for (int o = 16; o; o >>= 1)
        #pragma unroll
        for (int k = 0; k < 6; k++) q[k] += __shfl_down_sync(0xffffffffu, q[k], o);
    if (lane == 0)
        #pragma unroll
        for (int k = 0; k < 6; k++) red[k][w] = q[k];
    __syncthreads();
    if (tid == 0) {
        float s[6];
        #pragma unroll
        for (int k = 0; k < 6; k++) {
            s[k] = 0.f;
            #pragma unroll
            for (int w2 = 0; w2 < 8; w2++) s[k] += red[k][w2];
        }
        float it = 1.f / (sqrtf(s[0]) + 1e-8f);
        float ia = 1.f / (sqrtf(s[1]) + 1e-8f);
        float iv = 1.f / (sqrtf(s[2]) + 1e-8f);
        sinv[0] = it * SQTAUI; sinv[1] = ia * SQTAUI; sinv[2] = iv * SQTAUI;
        g_diag[i]             = s[3] * it * ia * TAUINV;
        g_diag[NROWS + i]     = s[4] * it * iv * TAUINV;
        g_diag[2 * NROWS + i] = s[5] * ia * iv * TAUINV;
        g_rowsum[i] = 0.f; g_rowsum[NROWS + i] = 0.f; g_rowsum[2 * NROWS + i] = 0.f;
        g_colsum[i] = 0.f; g_colsum[NROWS + i] = 0.f; g_colsum[2 * NROWS + i] = 0.f;
    }
    __syncthreads();
    g_nb[((size_t)0 * NROWS + i) * G + tid] = __float2bfloat16(tv * sinv[0]);
    g_nb[((size_t)1 * NROWS + i) * G + tid] = __float2bfloat16(av * sinv[1]);
    g_nb[((size_t)2 * NROWS + i) * G + tid] = __float2bfloat16(vv * sinv[2]);
}

// ---------------- K8: bf16 tensor-core sim tiles + streaming exp-sum ----------------
#define SPITCH 40   // bf16 elements per smem row (80B; 8-lane ldmatrix groups conflict-free)
__global__ void __launch_bounds__(256) k_sim_mma() {
    int p = blockIdx.z;
    int mx = (p == 2) ? 1 : 0;
    int my = (p == 0) ? 1 : 2;
    int row0 = blockIdx.y * 128, col0 = blockIdx.x * 128;
    __shared__ __nv_bfloat16 sX[128 * SPITCH];
    __shared__ __nv_bfloat16 sY[128 * SPITCH];
    __shared__ float srow[128], scol[128];
    int tid = threadIdx.x, lane = tid & 31, warp = tid >> 5;
    int wy = warp >> 1, wx = warp & 1;      // warp tile: 32 rows x 64 cols

    const __nv_bfloat16* xg = g_nb + ((size_t)mx * NROWS + row0) * G;
    const __nv_bfloat16* yg = g_nb + ((size_t)my * NROWS + col0) * G;

    float acc[2][8][4];
    #pragma unroll
    for (int mi = 0; mi < 2; mi++)
        #pragma unroll
        for (int ni = 0; ni < 8; ni++)
            #pragma unroll
            for (int r = 0; r < 4; r++) acc[mi][ni][r] = 0.f;

    for (int kc = 0; kc < G; kc += 32) {
        #pragma unroll
        for (int i = 0; i < 2; i++) {
            int idx = tid + i * 256;          // 0..511
            int r = idx >> 2, c = (idx & 3) * 8;
            *(uint4*)(sX + r * SPITCH + c) = *(const uint4*)(xg + (size_t)r * G + kc + c);
            *(uint4*)(sY + r * SPITCH + c) = *(const uint4*)(yg + (size_t)r * G + kc + c);
        }
        __syncthreads();
        #pragma unroll
        for (int ks = 0; ks < 2; ks++) {
            int k0 = ks * 16;
            unsigned A[2][4];
            #pragma unroll
            for (int mi = 0; mi < 2; mi++) {
                int r = wy * 32 + mi * 16 + ((lane >> 3) & 1) * 8 + (lane & 7);
                int cc = k0 + (lane >> 4) * 8;
                unsigned ad = (unsigned)__cvta_generic_to_shared(sX + r * SPITCH + cc);
                asm volatile("ldmatrix.sync.aligned.m8n8.x4.shared.b16 {%0,%1,%2,%3},[%4];"
                    : "=r"(A[mi][0]), "=r"(A[mi][1]), "=r"(A[mi][2]), "=r"(A[mi][3])
                    : "r"(ad));
            }
            unsigned B[8][2];
            #pragma unroll
            for (int nb = 0; nb < 4; nb++) {
                int r = wx * 64 + nb * 16 + (lane >> 4) * 8 + (lane & 7);
                int cc = k0 + ((lane >> 3) & 1) * 8;
                unsigned ad = (unsigned)__cvta_generic_to_shared(sY + r * SPITCH + cc);
                asm volatile("ldmatrix.sync.aligned.m8n8.x4.shared.b16 {%0,%1,%2,%3},[%4];"
                    : "=r"(B[2 * nb][0]), "=r"(B[2 * nb][1]),
                      "=r"(B[2 * nb + 1][0]), "=r"(B[2 * nb + 1][1])
                    : "r"(ad));
            }
            #pragma unroll
            for (int mi = 0; mi < 2; mi++)
                #pragma unroll
                for (int ni = 0; ni < 8; ni++)
                    asm volatile(
                        "mma.sync.aligned.m16n8k16.row.col.f32.bf16.bf16.f32 "
                        "{%0,%1,%2,%3},{%4,%5,%6,%7},{%8,%9},{%0,%1,%2,%3};"
                        : "+f"(acc[mi][ni][0]), "+f"(acc[mi][ni][1]),
                          "+f"(acc[mi][ni][2]), "+f"(acc[mi][ni][3])
                        : "r"(A[mi][0]), "r"(A[mi][1]), "r"(A[mi][2]), "r"(A[mi][3]),
                          "r"(B[ni][0]), "r"(B[ni][1]));
        }
        __syncthreads();
    }

    if (tid < 128) { srow[tid] = 0.f; scol[tid] = 0.f; }
    __syncthreads();

    float rowp[2][2] = {{0.f, 0.f}, {0.f, 0.f}};
    float colp[8][2];
    #pragma unroll
    for (int ni = 0; ni < 8; ni++) { colp[ni][0] = 0.f; colp[ni][1] = 0.f; }
    #pragma unroll
    for (int mi = 0; mi < 2; mi++)
        #pragma unroll
        for (int ni = 0; ni < 8; ni++)
            #pragma unroll
            for (int r = 0; r < 4; r++) {
                float e = __expf(acc[mi][ni][r]);
                rowp[mi][r >> 1] += e;
                colp[ni][r & 1] += e;
            }

    #pragma unroll
    for (int mi = 0; mi < 2; mi++)
        #pragma unroll
        for (int h = 0; h < 2; h++) {
            float vv = rowp[mi][h];
            vv += __shfl_xor_sync(0xffffffffu, vv, 1);
            vv += __shfl_xor_sync(0xffffffffu, vv, 2);
            if ((lane & 3) == 0)
                atomicAdd(&srow[wy * 32 + mi * 16 + (lane >> 2) + h * 8], vv);
        }
    #pragma unroll
    for (int ni = 0; ni < 8; ni++)
        #pragma unroll
        for (int s2 = 0; s2 < 2; s2++) {
            float vv = colp[ni][s2];
            vv += __shfl_xor_sync(0xffffffffu, vv, 4);
            vv += __shfl_xor_sync(0xffffffffu, vv, 8);
            vv += __shfl_xor_sync(0xffffffffu, vv, 16);
            if (lane < 4)
                atomicAdd(&scol[wx * 64 + ni * 8 + lane * 2 + s2], vv);
        }
    __syncthreads();
    if (tid < 128) {
        atomicAdd(&g_rowsum[p * NROWS + row0 + tid], srow[tid]);
        atomicAdd(&g_colsum[p * NROWS + col0 + tid], scol[tid]);
    }
}

// ---------------- K9: final loss reduction ----------------
__global__ void k_loss(float* out, int out_size) {
    int tid = threadIdx.x;
    float s = 0.f;
    for (int idx = tid; idx < 3 * NROWS; idx += 256) {
        float dg = g_diag[idx];
        s += 2.f * dg - logf(g_rowsum[idx]) - logf(g_colsum[idx]);
    }
    __shared__ float red[8];
    int lane = tid & 31, w = tid >> 5;
    #pragma unroll
    for (int o = 16; o; o >>= 1) s += __shfl_down_sync(0xffffffffu, s, o);
    if (lane == 0) red[w] = s;
    __syncthreads();
    if (tid == 0) {
        float tot = 0.f;
        #pragma unroll
        for (int w2 = 0; w2 < 8; w2++) tot += red[w2];
        float loss = -tot / (2.f * 3.f * (float)NROWS);
        if (out_size > NROWS * 768) out[NROWS * 768] = loss;
    }
}

// ---------------- launcher ----------------
extern "C" void kernel_launch(void* const* d_in, const int* in_sizes, int n_in,
                              void* d_out, int out_size) {
    const float* t   = (const float*)d_in[0];
    const float* a   = (const float*)d_in[1];
    const float* v   = (const float*)d_in[2];
    const float* Wfc = (const float*)d_in[3];
    const float* bfc = (const float*)d_in[4];
    const float* Wh  = (const float*)d_in[5];
    const float* bh  = (const float*)d_in[6];
    float* out = (float*)d_out;

    k_sq<<<NNODE / 8, 256>>>(t, a, v);
    k_gram_mma<<<dim3(6, 64), 256>>>(t, a, v);
    k_fc_mma<<<dim3(2, 96), 256>>>(t, a, v, Wfc, bfc);
    k_agg_edge<<<dim3(2, 64), 256>>>();
    k_agg_node<<<dim3(2, 64), 256>>>();
    k_out_mma<<<dim3(2, 96), 256>>>(Wh, bh, out);
    k_norm<<<NROWS, 256>>>(out);
    k_sim_mma<<<dim3(32, 32, 3), 256>>>();
    k_loss<<<1, 256>>>(out, out_size);
}

// round 7
// speedup vs baseline: 5.1838x; 1.0878x over previous
#include <cuda_runtime.h>
#include <cuda_bf16.h>
#include <math.h>
#include <float.h>

#define D 64
#define L 64
#define DIMF 512
#define G 256
#define M 192                 // 3*L nodes (= hyperedges) per dialogue
#define KTOP 12
#define NROWS 4096            // D*L
#define NNODE (D*M)           // 12288
#define TAUINV (1.0f/0.07f)
#define SQTAUI 3.7796447300922722f   // sqrt(1/0.07)

// ---- scratch (static device arrays; no allocation allowed) ----
__device__ float    g_sq[NNODE];
__device__ unsigned g_H[NNODE*6];       // 192-bit incidence mask per edge
__device__ float    g_X[NNODE*G];
__device__ float    g_E[NNODE*G];
__device__ float    g_Y[NNODE*G];
__device__ float    g_diag[3*NROWS];
__device__ float    g_rowsum[3*NROWS];
__device__ float    g_colsum[3*NROWS];
__device__ __nv_bfloat16 g_nb[(size_t)3*NROWS*G];   // normalized bf16 features (loss path only)

__device__ __forceinline__ const float* feat_row(int d, int n,
        const float* t, const float* a, const float* v) {
    int mod = n >> 6, i = n & 63;
    const float* base = (mod == 0) ? t : (mod == 1) ? a : v;
    return base + (size_t)(d * L + i) * DIMF;
}

// ---- tf32 helpers ----
__device__ __forceinline__ unsigned f2tf(float x) {
    unsigned u; asm("cvt.rna.tf32.f32 %0, %1;" : "=r"(u) : "f"(x)); return u;
}
__device__ __forceinline__ void hilo(float x, unsigned& h, unsigned& l) {
    h = f2tf(x);
    l = f2tf(x - __uint_as_float(h));
}
__device__ __forceinline__ void mma8(float* c, const unsigned* a, const unsigned* b) {
    asm volatile("mma.sync.aligned.m16n8k8.row.col.f32.tf32.tf32.f32 "
        "{%0,%1,%2,%3},{%4,%5,%6,%7},{%8,%9},{%0,%1,%2,%3};"
        : "+f"(c[0]), "+f"(c[1]), "+f"(c[2]), "+f"(c[3])
        : "r"(a[0]), "r"(a[1]), "r"(a[2]), "r"(a[3]), "r"(b[0]), "r"(b[1]));
}

// ---- cp.async helpers ----
__device__ __forceinline__ void cp16(void* dst_smem, const void* src) {
    unsigned ad = (unsigned)__cvta_generic_to_shared(dst_smem);
    asm volatile("cp.async.cg.shared.global [%0],[%1],16;" :: "r"(ad), "l"(src));
}
__device__ __forceinline__ void cp_commit() {
    asm volatile("cp.async.commit_group;");
}

// ---------------- K1: per-node squared norms ----------------
__global__ void k_sq(const float* t, const float* a, const float* v) {
    int warp = (blockIdx.x * blockDim.x + threadIdx.x) >> 5;
    int lane = threadIdx.x & 31;
    if (warp >= NNODE) return;
    int d = warp / M, n = warp % M;
    const float* r = feat_row(d, n, t, a, v);
    float s = 0.f;
    #pragma unroll
    for (int c = lane; c < DIMF; c += 32) { float x = r[c]; s += x * x; }
    #pragma unroll
    for (int o = 16; o; o >>= 1) s += __shfl_down_sync(0xffffffffu, s, o);
    if (lane == 0) g_sq[warp] = s;
}

// ---------------- K2: 3xTF32 gram + d2 + top-12 + incidence masks ----------------
#define GAP 20
#define GBP 200
__global__ void __launch_bounds__(256) k_gram_mma(const float* t, const float* a,
                                                  const float* v) {
    __shared__ unsigned Ahi[32 * GAP], Alo[32 * GAP];
    __shared__ unsigned Bbuf[2 * 16 * GBP];          // hi | lo ; reused as d2 [32][192]
    __shared__ const float* ptrN[M];
    __shared__ float sq[M];
    unsigned* Bhi = Bbuf;
    unsigned* Blo = Bbuf + 16 * GBP;

    int d = blockIdx.y, i0 = blockIdx.x * 32;
    int tid = threadIdx.x, lane = tid & 31, warp = tid >> 5;
    int gq = lane >> 2, tq = lane & 3;
    if (tid < M) { ptrN[tid] = feat_row(d, tid, t, a, v); sq[tid] = g_sq[d * M + tid]; }
    __syncthreads();

    float acc[2][3][4];
    #pragma unroll
    for (int mi = 0; mi < 2; mi++)
        #pragma unroll
        for (int ni = 0; ni < 3; ni++)
            #pragma unroll
            for (int e = 0; e < 4; e++) acc[mi][ni][e] = 0.f;

    for (int kc = 0; kc < DIMF; kc += 16) {
        {
            int r = tid >> 3, c = (tid & 7) * 2;
            float2 xv = *(const float2*)(ptrN[i0 + r] + kc + c);
            hilo(xv.x, Ahi[r * GAP + c],     Alo[r * GAP + c]);
            hilo(xv.y, Ahi[r * GAP + c + 1], Alo[r * GAP + c + 1]);
        }
        #pragma unroll
        for (int it = 0; it < 3; it++) {
            int idx = tid + it * 256;
            int n = idx % 192, k4 = (idx / 192) * 4;
            float4 xv = *(const float4*)(ptrN[n] + kc + k4);
            hilo(xv.x, Bhi[(k4 + 0) * GBP + n], Blo[(k4 + 0) * GBP + n]);
            hilo(xv.y, Bhi[(k4 + 1) * GBP + n], Blo[(k4 + 1) * GBP + n]);
            hilo(xv.z, Bhi[(k4 + 2) * GBP + n], Blo[(k4 + 2) * GBP + n]);
            hilo(xv.w, Bhi[(k4 + 3) * GBP + n], Blo[(k4 + 3) * GBP + n]);
        }
        __syncthreads();
        #pragma unroll
        for (int k0 = 0; k0 < 16; k0 += 8) {
            unsigned ah[2][4], al[2][4], bh[3][2], bl[3][2];
            #pragma unroll
            for (int mi = 0; mi < 2; mi++) {
                int row = mi * 16;
                ah[mi][0] = Ahi[(row + gq) * GAP + k0 + tq];
                ah[mi][1] = Ahi[(row + gq + 8) * GAP + k0 + tq];
                ah[mi][2] = Ahi[(row + gq) * GAP + k0 + tq + 4];
                ah[mi][3] = Ahi[(row + gq + 8) * GAP + k0 + tq + 4];
                al[mi][0] = Alo[(row + gq) * GAP + k0 + tq];
                al[mi][1] = Alo[(row + gq + 8) * GAP + k0 + tq];
                al[mi][2] = Alo[(row + gq) * GAP + k0 + tq + 4];
                al[mi][3] = Alo[(row + gq + 8) * GAP + k0 + tq + 4];
            }
            #pragma unroll
            for (int ni = 0; ni < 3; ni++) {
                int c0 = warp * 24 + ni * 8;
                bh[ni][0] = Bhi[(k0 + tq) * GBP + c0 + gq];
                bh[ni][1] = Bhi[(k0 + tq + 4) * GBP + c0 + gq];
                bl[ni][0] = Blo[(k0 + tq) * GBP + c0 + gq];
                bl[ni][1] = Blo[(k0 + tq + 4) * GBP + c0 + gq];
            }
            #pragma unroll
            for (int mi = 0; mi < 2; mi++)
                #pragma unroll
                for (int ni = 0; ni < 3; ni++) {
                    mma8(acc[mi][ni], ah[mi], bh[ni]);
                    mma8(acc[mi][ni], ah[mi], bl[ni]);
                    mma8(acc[mi][ni], al[mi], bh[ni]);
                }
        }
        __syncthreads();
    }

    float* d2s = (float*)Bbuf;
    #pragma unroll
    for (int mi = 0; mi < 2; mi++)
        #pragma unroll
        for (int ni = 0; ni < 3; ni++)
            #pragma unroll
            for (int e = 0; e < 4; e++) {
                int r = mi * 16 + gq + (e >> 1) * 8;
                int c = warp * 24 + ni * 8 + 2 * tq + (e & 1);
                float v2 = sq[i0 + r] + sq[c] - 2.f * acc[mi][ni][e];
                d2s[r * 192 + c] = fmaxf(v2, 0.f);
            }
    __syncthreads();

    int tx = lane;
    for (int q = 0; q < 4; q++) {
        int r = warp * 4 + q;
        float val[6];
        #pragma unroll
        for (int s = 0; s < 6; s++) val[s] = d2s[r * 192 + tx + 32 * s];
        unsigned mask[6] = {0, 0, 0, 0, 0, 0};
        for (int pick = 0; pick < KTOP; pick++) {
            float bv = val[0]; int bi = tx;
            #pragma unroll
            for (int s = 1; s < 6; s++) {
                float vv = val[s];
                if (vv < bv) { bv = vv; bi = tx + 32 * s; }
            }
            #pragma unroll
            for (int o = 16; o; o >>= 1) {
                float ov = __shfl_down_sync(0xffffffffu, bv, o);
                int   oi = __shfl_down_sync(0xffffffffu, bi, o);
                if (ov < bv || (ov == bv && oi < bi)) { bv = ov; bi = oi; }
            }
            bi = __shfl_sync(0xffffffffu, bi, 0);
            if ((bi & 31) == tx) val[bi >> 5] = FLT_MAX;
            mask[bi >> 5] |= 1u << (bi & 31);
        }
        if (tx == 0) {
            int e = i0 + r;
            int u = e / 3;
            mask[u >> 5]           |= 1u << (u & 31);
            mask[(u + 64) >> 5]    |= 1u << ((u + 64) & 31);
            mask[(u + 128) >> 5]   |= 1u << ((u + 128) & 31);
            #pragma unroll
            for (int w = 0; w < 6; w++)
                g_H[(size_t)(d * M + e) * 6 + w] = mask[w];
        }
    }
}

// ---------------- K3: X = feat @ W_fc + b_fc  (tf32 mma, 128x128 tile) ----------------
#define FAP 36
#define FBP 136
__global__ void __launch_bounds__(256) k_fc_mma(const float* t, const float* a,
        const float* v, const float* Wfc, const float* bfc) {
    __shared__ unsigned sA[128 * FAP];
    __shared__ unsigned sB[32 * FBP];
    __shared__ const float* ptrA[128];
    int bn = blockIdx.x, bm = blockIdx.y;
    int tid = threadIdx.x, lane = tid & 31, warp = tid >> 5;
    int wy = warp >> 1, wx = warp & 1;
    int gq = lane >> 2, tq = lane & 3;
    if (tid < 128) { int gn = bm * 128 + tid; ptrA[tid] = feat_row(gn / M, gn % M, t, a, v); }
    __syncthreads();

    float acc[2][8][4];
    #pragma unroll
    for (int mi = 0; mi < 2; mi++)
        #pragma unroll
        for (int ni = 0; ni < 8; ni++)
            #pragma unroll
            for (int e = 0; e < 4; e++) acc[mi][ni][e] = 0.f;

    for (int kc = 0; kc < DIMF; kc += 32) {
        #pragma unroll
        for (int it = 0; it < 4; it++) {
            int idx = tid + it * 256;
            int r = idx >> 3, c = (idx & 7) * 4;
            float4 xv = *(const float4*)(ptrA[r] + kc + c);
            sA[r * FAP + c]     = f2tf(xv.x);
            sA[r * FAP + c + 1] = f2tf(xv.y);
            sA[r * FAP + c + 2] = f2tf(xv.z);
            sA[r * FAP + c + 3] = f2tf(xv.w);
        }
        #pragma unroll
        for (int it = 0; it < 4; it++) {
            int idx = tid + it * 256;
            int kr = idx >> 5, n4 = (idx & 31) * 4;
            float4 wv = *(const float4*)(Wfc + (size_t)(kc + kr) * G + bn * 128 + n4);
            sB[kr * FBP + n4]     = f2tf(wv.x);
            sB[kr * FBP + n4 + 1] = f2tf(wv.y);
            sB[kr * FBP + n4 + 2] = f2tf(wv.z);
            sB[kr * FBP + n4 + 3] = f2tf(wv.w);
        }
        __syncthreads();
        #pragma unroll
        for (int k0 = 0; k0 < 32; k0 += 8) {
            unsigned af[2][4], bf[8][2];
            #pragma unroll
            for (int mi = 0; mi < 2; mi++) {
                int row = wy * 32 + mi * 16;
                af[mi][0] = sA[(row + gq) * FAP + k0 + tq];
                af[mi][1] = sA[(row + gq + 8) * FAP + k0 + tq];
                af[mi][2] = sA[(row + gq) * FAP + k0 + tq + 4];
                af[mi][3] = sA[(row + gq + 8) * FAP + k0 + tq + 4];
            }
            #pragma unroll
            for (int ni = 0; ni < 8; ni++) {
                int c0 = wx * 64 + ni * 8;
                bf[ni][0] = sB[(k0 + tq) * FBP + c0 + gq];
                bf[ni][1] = sB[(k0 + tq + 4) * FBP + c0 + gq];
            }
            #pragma unroll
            for (int mi = 0; mi < 2; mi++)
                #pragma unroll
                for (int ni = 0; ni < 8; ni++)
                    mma8(acc[mi][ni], af[mi], bf[ni]);
        }
        __syncthreads();
    }
    #pragma unroll
    for (int mi = 0; mi < 2; mi++)
        #pragma unroll
        for (int ni = 0; ni < 8; ni++)
            #pragma unroll
            for (int e = 0; e < 4; e++) {
                int r  = bm * 128 + wy * 32 + mi * 16 + gq + (e >> 1) * 8;
                int cc = bn * 128 + wx * 64 + ni * 8 + 2 * tq + (e & 1);
                g_X[(size_t)r * G + cc] = acc[mi][ni][e] + bfc[cc];
            }
}

// ---------------- K4/K5: hypergraph hops as dense tf32 mma, 64-col blocks ----------------
// grid (4, 64): 256 blocks -> 2 blocks/SM; register-prefetch of next B chunk.
#define AAP 20     // A pitch (k chunk 16 + 4)
#define BP2 72     // B pitch (64 + 8): 8*tq+gq hits all 32 banks -> conflict-free
template<int SRC>  // 0: B=g_X -> g_E (H @ X);  1: B=g_E -> g_Y (H^T @ E)
__global__ void __launch_bounds__(256) k_agg() {
    __shared__ unsigned sHw[192 * 6];
    __shared__ float    sdeg[192];
    __shared__ unsigned sA[192 * AAP];
    __shared__ unsigned sB[2 * 16 * BP2];     // hi | lo
    int d = blockIdx.y, n0 = blockIdx.x * 64;
    int tid = threadIdx.x, lane = tid & 31, warp = tid >> 5;
    int wy = warp >> 1, wx = warp & 1;        // wy: 48 rows, wx: 32 cols
    int gq = lane >> 2, tq = lane & 3;

    for (int i = tid; i < 192 * 6; i += 256) sHw[i] = g_H[(size_t)(d * M) * 6 + i];
    __syncthreads();
    if (tid < 192) {
        int deg = 0;
        if (SRC == 0) {
            #pragma unroll
            for (int w = 0; w < 6; w++) deg += __popc(sHw[tid * 6 + w]);
        } else {
            int wsel = tid >> 5, bsel = tid & 31;
            for (int e = 0; e < 192; e++) deg += (sHw[e * 6 + wsel] >> bsel) & 1u;
        }
        sdeg[tid] = 1.f / (float)deg;
    }

    float acc[3][4][4];
    #pragma unroll
    for (int mi = 0; mi < 3; mi++)
        #pragma unroll
        for (int ni = 0; ni < 4; ni++)
            #pragma unroll
            for (int e = 0; e < 4; e++) acc[mi][ni][e] = 0.f;

    const float* src = (SRC == 0) ? g_X : g_E;
    int kr = tid >> 4, c4 = (tid & 15) * 4;   // 16 rows x 64 cols, 1 float4/thread
    float4 nxt = *(const float4*)(src + (size_t)(d * M + kr) * G + n0 + c4);

    for (int kc = 0; kc < 192; kc += 16) {
        // expand A bits for this K chunk
        if (tid < 192) {
            if (SRC == 0) {
                unsigned w = sHw[tid * 6 + (kc >> 5)];
                int sh = kc & 16;
                #pragma unroll
                for (int c = 0; c < 16; c++)
                    sA[tid * AAP + c] = ((w >> (sh + c)) & 1u) ? 0x3F800000u : 0u;
            } else {
                int wsel = tid >> 5, bsel = tid & 31;
                #pragma unroll
                for (int c = 0; c < 16; c++) {
                    unsigned w = sHw[(kc + c) * 6 + wsel];
                    sA[tid * AAP + c] = ((w >> bsel) & 1u) ? 0x3F800000u : 0u;
                }
            }
        }
        // convert prefetched B chunk
        hilo(nxt.x, sB[kr * BP2 + c4],     sB[16 * BP2 + kr * BP2 + c4]);
        hilo(nxt.y, sB[kr * BP2 + c4 + 1], sB[16 * BP2 + kr * BP2 + c4 + 1]);
        hilo(nxt.z, sB[kr * BP2 + c4 + 2], sB[16 * BP2 + kr * BP2 + c4 + 2]);
        hilo(nxt.w, sB[kr * BP2 + c4 + 3], sB[16 * BP2 + kr * BP2 + c4 + 3]);
        __syncthreads();
        // prefetch next chunk while mma runs
        if (kc + 16 < 192)
            nxt = *(const float4*)(src + (size_t)(d * M + kc + 16 + kr) * G + n0 + c4);
        #pragma unroll
        for (int k0 = 0; k0 < 16; k0 += 8) {
            unsigned af[3][4], bh[4][2], bl[4][2];
            #pragma unroll
            for (int mi = 0; mi < 3; mi++) {
                int row = wy * 48 + mi * 16;
                af[mi][0] = sA[(row + gq) * AAP + k0 + tq];
                af[mi][1] = sA[(row + gq + 8) * AAP + k0 + tq];
                af[mi][2] = sA[(row + gq) * AAP + k0 + tq + 4];
                af[mi][3] = sA[(row + gq + 8) * AAP + k0 + tq + 4];
            }
            #pragma unroll
            for (int ni = 0; ni < 4; ni++) {
                int c0 = wx * 32 + ni * 8;
                bh[ni][0] = sB[(k0 + tq) * BP2 + c0 + gq];
                bh[ni][1] = sB[(k0 + tq + 4) * BP2 + c0 + gq];
                bl[ni][0] = sB[16 * BP2 + (k0 + tq) * BP2 + c0 + gq];
                bl[ni][1] = sB[16 * BP2 + (k0 + tq + 4) * BP2 + c0 + gq];
            }
            #pragma unroll
            for (int mi = 0; mi < 3; mi++)
                #pragma unroll
                for (int ni = 0; ni < 4; ni++) {
                    mma8(acc[mi][ni], af[mi], bh[ni]);
                    mma8(acc[mi][ni], af[mi], bl[ni]);
                }
        }
        __syncthreads();
    }
    float* dst = (SRC == 0) ? g_E : g_Y;
    #pragma unroll
    for (int mi = 0; mi < 3; mi++)
        #pragma unroll
        for (int ni = 0; ni < 4; ni++)
            #pragma unroll
            for (int e = 0; e < 4; e++) {
                int r = wy * 48 + mi * 16 + gq + (e >> 1) * 8;
                int c = n0 + wx * 32 + ni * 8 + 2 * tq + (e & 1);
                dst[(size_t)(d * M + r) * G + c] = acc[mi][ni][e] * sdeg[r];
            }
}

// ---------------- K6: out = relu(Y @ W_h + b_h) (tf32 mma), regrouped ----------------
__global__ void __launch_bounds__(256) k_out_mma(const float* Wh, const float* bh,
                                                 float* out) {
    __shared__ unsigned sA[128 * FAP];
    __shared__ unsigned sB[32 * FBP];
    int bn = blockIdx.x, bm = blockIdx.y;
    int tid = threadIdx.x, lane = tid & 31, warp = tid >> 5;
    int wy = warp >> 1, wx = warp & 1;
    int gq = lane >> 2, tq = lane & 3;

    float acc[2][8][4];
    #pragma unroll
    for (int mi = 0; mi < 2; mi++)
        #pragma unroll
        for (int ni = 0; ni < 8; ni++)
            #pragma unroll
            for (int e = 0; e < 4; e++) acc[mi][ni][e] = 0.f;

    for (int kc = 0; kc < G; kc += 32) {
        #pragma unroll
        for (int it = 0; it < 4; it++) {
            int idx = tid + it * 256;
            int r = idx >> 3, c = (idx & 7) * 4;
            float4 xv = *(const float4*)(g_Y + (size_t)(bm * 128 + r) * G + kc + c);
            sA[r * FAP + c]     = f2tf(xv.x);
            sA[r * FAP + c + 1] = f2tf(xv.y);
            sA[r * FAP + c + 2] = f2tf(xv.z);
            sA[r * FAP + c + 3] = f2tf(xv.w);
        }
        #pragma unroll
        for (int it = 0; it < 4; it++) {
            int idx = tid + it * 256;
            int kr = idx >> 5, n4 = (idx & 31) * 4;
            float4 wv = *(const float4*)(Wh + (size_t)(kc + kr) * G + bn * 128 + n4);
            sB[kr * FBP + n4]     = f2tf(wv.x);
            sB[kr * FBP + n4 + 1] = f2tf(wv.y);
            sB[kr * FBP + n4 + 2] = f2tf(wv.z);
            sB[kr * FBP + n4 + 3] = f2tf(wv.w);
        }
        __syncthreads();
        #pragma unroll
        for (int k0 = 0; k0 < 32; k0 += 8) {
            unsigned af[2][4], bf[8][2];
            #pragma unroll
            for (int mi = 0; mi < 2; mi++) {
                int row = wy * 32 + mi * 16;
                af[mi][0] = sA[(row + gq) * FAP + k0 + tq];
                af[mi][1] = sA[(row + gq + 8) * FAP + k0 + tq];
                af[mi][2] = sA[(row + gq) * FAP + k0 + tq + 4];
                af[mi][3] = sA[(row + gq + 8) * FAP + k0 + tq + 4];
            }
            #pragma unroll
            for (int ni = 0; ni < 8; ni++) {
                int c0 = wx * 64 + ni * 8;
                bf[ni][0] = sB[(k0 + tq) * FBP + c0 + gq];
                bf[ni][1] = sB[(k0 + tq + 4) * FBP + c0 + gq];
            }
            #pragma unroll
            for (int mi = 0; mi < 2; mi++)
                #pragma unroll
                for (int ni = 0; ni < 8; ni++)
                    mma8(acc[mi][ni], af[mi], bf[ni]);
        }
        __syncthreads();
    }
    #pragma unroll
    for (int mi = 0; mi < 2; mi++)
        #pragma unroll
        for (int ni = 0; ni < 8; ni++)
            #pragma unroll
            for (int e = 0; e < 4; e++) {
                int gn = bm * 128 + wy * 32 + mi * 16 + gq + (e >> 1) * 8;
                int gc = bn * 128 + wx * 64 + ni * 8 + 2 * tq + (e & 1);
                int dd = gn / M, n = gn % M, mod = n >> 6, ii = n & 63;
                out[(size_t)(dd * L + ii) * 768 + mod * 256 + gc] =
                    fmaxf(acc[mi][ni][e] + bh[gc], 0.f);
            }
}

// ---------------- K7: norms, diag sims, zero LSE accumulators, bf16 convert ----------------
__global__ void k_norm(const float* out) {
    int i = blockIdx.x;
    int tid = threadIdx.x;
    float tv = out[(size_t)i * 768 + tid];
    float av = out[(size_t)i * 768 + 256 + tid];
    float vv = out[(size_t)i * 768 + 512 + tid];
    float q[6] = { tv * tv, av * av, vv * vv, tv * av, tv * vv, av * vv };
    __shared__ float red[6][8];
    __shared__ float sinv[3];
    int lane = tid & 31, w = tid >> 5;
    #pragma unroll
    for (int o = 16; o; o >>= 1)
        #pragma unroll
        for (int k = 0; k < 6; k++) q[k] += __shfl_down_sync(0xffffffffu, q[k], o);
    if (lane == 0)
        #pragma unroll
        for (int k = 0; k < 6; k++) red[k][w] = q[k];
    __syncthreads();
    if (tid == 0) {
        float s[6];
        #pragma unroll
        for (int k = 0; k < 6; k++) {
            s[k] = 0.f;
            #pragma unroll
            for (int w2 = 0; w2 < 8; w2++) s[k] += red[k][w2];
        }
        float it = 1.f / (sqrtf(s[0]) + 1e-8f);
        float ia = 1.f / (sqrtf(s[1]) + 1e-8f);
        float iv = 1.f / (sqrtf(s[2]) + 1e-8f);
        sinv[0] = it * SQTAUI; sinv[1] = ia * SQTAUI; sinv[2] = iv * SQTAUI;
        g_diag[i]             = s[3] * it * ia * TAUINV;
        g_diag[NROWS + i]     = s[4] * it * iv * TAUINV;
        g_diag[2 * NROWS + i] = s[5] * ia * iv * TAUINV;
        g_rowsum[i] = 0.f; g_rowsum[NROWS + i] = 0.f; g_rowsum[2 * NROWS + i] = 0.f;
        g_colsum[i] = 0.f; g_colsum[NROWS + i] = 0.f; g_colsum[2 * NROWS + i] = 0.f;
    }
    __syncthreads();
    g_nb[((size_t)0 * NROWS + i) * G + tid] = __float2bfloat16(tv * sinv[0]);
    g_nb[((size_t)1 * NROWS + i) * G + tid] = __float2bfloat16(av * sinv[1]);
    g_nb[((size_t)2 * NROWS + i) * G + tid] = __float2bfloat16(vv * sinv[2]);
}

// ---------------- K8: bf16 tensor-core sim tiles, cp.async double-buffered ----------------
#define SPITCH 40
__global__ void __launch_bounds__(256) k_sim_mma() {
    int p = blockIdx.z;
    int mx = (p == 2) ? 1 : 0;
    int my = (p == 0) ? 1 : 2;
    int row0 = blockIdx.y * 128, col0 = blockIdx.x * 128;
    __shared__ __nv_bfloat16 sX[2][128 * SPITCH];
    __shared__ __nv_bfloat16 sY[2][128 * SPITCH];
    __shared__ float srow[128], scol[128];
    int tid = threadIdx.x, lane = tid & 31, warp = tid >> 5;
    int wy = warp >> 1, wx = warp & 1;      // warp tile: 32 rows x 64 cols

    const __nv_bfloat16* xg = g_nb + ((size_t)mx * NROWS + row0) * G;
    const __nv_bfloat16* yg = g_nb + ((size_t)my * NROWS + col0) * G;

    int lr = tid >> 2, lc = (tid & 3) * 8;      // load indices (2 rounds of 256)
    int lr2 = lr + 64;

    float acc[2][8][4];
    #pragma unroll
    for (int mi = 0; mi < 2; mi++)
        #pragma unroll
        for (int ni = 0; ni < 8; ni++)
            #pragma unroll
            for (int r = 0; r < 4; r++) acc[mi][ni][r] = 0.f;

    // prologue: async-load chunk 0 into buffer 0
    cp16(&sX[0][lr * SPITCH + lc],  xg + (size_t)lr * G + lc);
    cp16(&sX[0][lr2 * SPITCH + lc], xg + (size_t)lr2 * G + lc);
    cp16(&sY[0][lr * SPITCH + lc],  yg + (size_t)lr * G + lc);
    cp16(&sY[0][lr2 * SPITCH + lc], yg + (size_t)lr2 * G + lc);
    cp_commit();

    #pragma unroll
    for (int c = 0; c < 8; c++) {
        int cur = c & 1;
        if (c < 7) {
            int nb = (c + 1) & 1, kc = (c + 1) * 32;
            cp16(&sX[nb][lr * SPITCH + lc],  xg + (size_t)lr * G + kc + lc);
            cp16(&sX[nb][lr2 * SPITCH + lc], xg + (size_t)lr2 * G + kc + lc);
            cp16(&sY[nb][lr * SPITCH + lc],  yg + (size_t)lr * G + kc + lc);
            cp16(&sY[nb][lr2 * SPITCH + lc], yg + (size_t)lr2 * G + kc + lc);
            cp_commit();
            asm volatile("cp.async.wait_group 1;");
        } else {
            asm volatile("cp.async.wait_group 0;");
        }
        __syncthreads();
        #pragma unroll
        for (int ks = 0; ks < 2; ks++) {
            int k0 = ks * 16;
            unsigned A[2][4];
            #pragma unroll
            for (int mi = 0; mi < 2; mi++) {
                int r = wy * 32 + mi * 16 + ((lane >> 3) & 1) * 8 + (lane & 7);
                int cc = k0 + (lane >> 4) * 8;
                unsigned ad = (unsigned)__cvta_generic_to_shared(&sX[cur][r * SPITCH + cc]);
                asm volatile("ldmatrix.sync.aligned.m8n8.x4.shared.b16 {%0,%1,%2,%3},[%4];"
                    : "=r"(A[mi][0]), "=r"(A[mi][1]), "=r"(A[mi][2]), "=r"(A[mi][3])
                    : "r"(ad));
            }
            unsigned B[8][2];
            #pragma unroll
            for (int nb2 = 0; nb2 < 4; nb2++) {
                int r = wx * 64 + nb2 * 16 + (lane >> 4) * 8 + (lane & 7);
                int cc = k0 + ((lane >> 3) & 1) * 8;
                unsigned ad = (unsigned)__cvta_generic_to_shared(&sY[cur][r * SPITCH + cc]);
                asm volatile("ldmatrix.sync.aligned.m8n8.x4.shared.b16 {%0,%1,%2,%3},[%4];"
                    : "=r"(B[2 * nb2][0]), "=r"(B[2 * nb2][1]),
                      "=r"(B[2 * nb2 + 1][0]), "=r"(B[2 * nb2 + 1][1])
                    : "r"(ad));
            }
            #pragma unroll
            for (int mi = 0; mi < 2; mi++)
                #pragma unroll
                for (int ni = 0; ni < 8; ni++)
                    asm volatile(
                        "mma.sync.aligned.m16n8k16.row.col.f32.bf16.bf16.f32 "
                        "{%0,%1,%2,%3},{%4,%5,%6,%7},{%8,%9},{%0,%1,%2,%3};"
                        : "+f"(acc[mi][ni][0]), "+f"(acc[mi][ni][1]),
                          "+f"(acc[mi][ni][2]), "+f"(acc[mi][ni][3])
                        : "r"(A[mi][0]), "r"(A[mi][1]), "r"(A[mi][2]), "r"(A[mi][3]),
                          "r"(B[ni][0]), "r"(B[ni][1]));
        }
        __syncthreads();
    }

    if (tid < 128) { srow[tid] = 0.f; scol[tid] = 0.f; }
    __syncthreads();

    float rowp[2][2] = {{0.f, 0.f}, {0.f, 0.f}};
    float colp[8][2];
    #pragma unroll
    for (int ni = 0; ni < 8; ni++) { colp[ni][0] = 0.f; colp[ni][1] = 0.f; }
    #pragma unroll
    for (int mi = 0; mi < 2; mi++)
        #pragma unroll
        for (int ni = 0; ni < 8; ni++)
            #pragma unroll
            for (int r = 0; r < 4; r++) {
                float e = __expf(acc[mi][ni][r]);
                rowp[mi][r >> 1] += e;
                colp[ni][r & 1] += e;
            }

    #pragma unroll
    for (int mi = 0; mi < 2; mi++)
        #pragma unroll
        for (int h = 0; h < 2; h++) {
            float vv = rowp[mi][h];
            vv += __shfl_xor_sync(0xffffffffu, vv, 1);
            vv += __shfl_xor_sync(0xffffffffu, vv, 2);
            if ((lane & 3) == 0)
                atomicAdd(&srow[wy * 32 + mi * 16 + (lane >> 2) + h * 8], vv);
        }
    #pragma unroll
    for (int ni = 0; ni < 8; ni++)
        #pragma unroll
        for (int s2 = 0; s2 < 2; s2++) {
            float vv = colp[ni][s2];
            vv += __shfl_xor_sync(0xffffffffu, vv, 4);
            vv += __shfl_xor_sync(0xffffffffu, vv, 8);
            vv += __shfl_xor_sync(0xffffffffu, vv, 16);
            if (lane < 4)
                atomicAdd(&scol[wx * 64 + ni * 8 + lane * 2 + s2], vv);
        }
    __syncthreads();
    if (tid < 128) {
        atomicAdd(&g_rowsum[p * NROWS + row0 + tid], srow[tid]);
        atomicAdd(&g_colsum[p * NROWS + col0 + tid], scol[tid]);
    }
}

// ---------------- K9: final loss reduction ----------------
__global__ void k_loss(float* out, int out_size) {
    int tid = threadIdx.x;
    float s = 0.f;
    for (int idx = tid; idx < 3 * NROWS; idx += 256) {
        float dg = g_diag[idx];
        s += 2.f * dg - logf(g_rowsum[idx]) - logf(g_colsum[idx]);
    }
    __shared__ float red[8];
    int lane = tid & 31, w = tid >> 5;
    #pragma unroll
    for (int o = 16; o; o >>= 1) s += __shfl_down_sync(0xffffffffu, s, o);
    if (lane == 0) red[w] = s;
    __syncthreads();
    if (tid == 0) {
        float tot = 0.f;
        #pragma unroll
        for (int w2 = 0; w2 < 8; w2++) tot += red[w2];
        float loss = -tot / (2.f * 3.f * (float)NROWS);
        if (out_size > NROWS * 768) out[NROWS * 768] = loss;
    }
}

// ---------------- launcher ----------------
extern "C" void kernel_launch(void* const* d_in, const int* in_sizes, int n_in,
                              void* d_out, int out_size) {
    const float* t   = (const float*)d_in[0];
    const float* a   = (const float*)d_in[1];
    const float* v   = (const float*)d_in[2];
    const float* Wfc = (const float*)d_in[3];
    const float* bfc = (const float*)d_in[4];
    const float* Wh  = (const float*)d_in[5];
    const float* bh  = (const float*)d_in[6];
    float* out = (float*)d_out;

    k_sq<<<NNODE / 8, 256>>>(t, a, v);
    k_gram_mma<<<dim3(6, 64), 256>>>(t, a, v);
    k_fc_mma<<<dim3(2, 96), 256>>>(t, a, v, Wfc, bfc);
    k_agg<0><<<dim3(4, 64), 256>>>();
    k_agg<1><<<dim3(4, 64), 256>>>();
    k_out_mma<<<dim3(2, 96), 256>>>(Wh, bh, out);
    k_norm<<<NROWS, 256>>>(out);
    k_sim_mma<<<dim3(32, 32, 3), 256>>>();
    k_loss<<<1, 256>>>(out, out_size);
}

// round 8
// speedup vs baseline: 5.4214x; 1.0458x over previous
#include <cuda_runtime.h>
#include <cuda_bf16.h>
#include <math.h>
#include <float.h>

#define D 64
#define L 64
#define DIMF 512
#define G 256
#define M 192                 // 3*L nodes (= hyperedges) per dialogue
#define KTOP 12
#define NROWS 4096            // D*L
#define NNODE (D*M)           // 12288
#define TAUINV (1.0f/0.07f)
#define SQTAUI 3.7796447300922722f   // sqrt(1/0.07)

// ---- scratch (static device arrays; no allocation allowed) ----
__device__ float    g_sq[NNODE];
__device__ unsigned g_H[NNODE*6];       // 192-bit incidence mask per edge
__device__ float    g_X[NNODE*G];
__device__ float    g_Y[NNODE*G];
__device__ float    g_diag[3*NROWS];
__device__ float    g_rowsum[3*NROWS];
__device__ float    g_colsum[3*NROWS];
__device__ __nv_bfloat16 g_nb[(size_t)3*NROWS*G];   // normalized bf16 features (loss path only)

__device__ __forceinline__ const float* feat_row(int d, int n,
        const float* t, const float* a, const float* v) {
    int mod = n >> 6, i = n & 63;
    const float* base = (mod == 0) ? t : (mod == 1) ? a : v;
    return base + (size_t)(d * L + i) * DIMF;
}

// ---- tf32 helpers ----
__device__ __forceinline__ unsigned f2tf(float x) {
    unsigned u; asm("cvt.rna.tf32.f32 %0, %1;" : "=r"(u) : "f"(x)); return u;
}
__device__ __forceinline__ void hilo(float x, unsigned& h, unsigned& l) {
    h = f2tf(x);
    l = f2tf(x - __uint_as_float(h));
}
__device__ __forceinline__ void mma8(float* c, const unsigned* a, const unsigned* b) {
    asm volatile("mma.sync.aligned.m16n8k8.row.col.f32.tf32.tf32.f32 "
        "{%0,%1,%2,%3},{%4,%5,%6,%7},{%8,%9},{%0,%1,%2,%3};"
        : "+f"(c[0]), "+f"(c[1]), "+f"(c[2]), "+f"(c[3])
        : "r"(a[0]), "r"(a[1]), "r"(a[2]), "r"(a[3]), "r"(b[0]), "r"(b[1]));
}

// ---- cp.async helpers ----
__device__ __forceinline__ void cp16(void* dst_smem, const void* src) {
    unsigned ad = (unsigned)__cvta_generic_to_shared(dst_smem);
    asm volatile("cp.async.cg.shared.global [%0],[%1],16;" :: "r"(ad), "l"(src));
}
__device__ __forceinline__ void cp_commit() {
    asm volatile("cp.async.commit_group;");
}

// ---------------- K1: per-node squared norms ----------------
__global__ void k_sq(const float* t, const float* a, const float* v) {
    int warp = (blockIdx.x * blockDim.x + threadIdx.x) >> 5;
    int lane = threadIdx.x & 31;
    if (warp >= NNODE) return;
    int d = warp / M, n = warp % M;
    const float* r = feat_row(d, n, t, a, v);
    float s = 0.f;
    #pragma unroll
    for (int c = lane; c < DIMF; c += 32) { float x = r[c]; s += x * x; }
    #pragma unroll
    for (int o = 16; o; o >>= 1) s += __shfl_down_sync(0xffffffffu, s, o);
    if (lane == 0) g_sq[warp] = s;
}

// ---------------- K2: 3xTF32 gram + d2 + top-12 + incidence masks ----------------
// A fragments are read from the B tile transposed (A[m][k] = B[k][i0+m]).
#define GBP 200
__global__ void __launch_bounds__(256) k_gram_mma(const float* t, const float* a,
                                                  const float* v) {
    __shared__ unsigned Bbuf[2 * 16 * GBP];          // hi | lo ; reused as d2 [32][192]
    __shared__ const float* ptrN[M];
    __shared__ float sq[M];
    unsigned* Bhi = Bbuf;
    unsigned* Blo = Bbuf + 16 * GBP;

    int d = blockIdx.y, i0 = blockIdx.x * 32;
    int tid = threadIdx.x, lane = tid & 31, warp = tid >> 5;
    int gq = lane >> 2, tq = lane & 3;
    if (tid < M) { ptrN[tid] = feat_row(d, tid, t, a, v); sq[tid] = g_sq[d * M + tid]; }
    __syncthreads();

    float acc[2][3][4];
    #pragma unroll
    for (int mi = 0; mi < 2; mi++)
        #pragma unroll
        for (int ni = 0; ni < 3; ni++)
            #pragma unroll
            for (int e = 0; e < 4; e++) acc[mi][ni][e] = 0.f;

    for (int kc = 0; kc < DIMF; kc += 16) {
        #pragma unroll
        for (int it = 0; it < 3; it++) {
            int idx = tid + it * 256;
            int n = idx % 192, k4 = (idx / 192) * 4;
            float4 xv = *(const float4*)(ptrN[n] + kc + k4);
            hilo(xv.x, Bhi[(k4 + 0) * GBP + n], Blo[(k4 + 0) * GBP + n]);
            hilo(xv.y, Bhi[(k4 + 1) * GBP + n], Blo[(k4 + 1) * GBP + n]);
            hilo(xv.z, Bhi[(k4 + 2) * GBP + n], Blo[(k4 + 2) * GBP + n]);
            hilo(xv.w, Bhi[(k4 + 3) * GBP + n], Blo[(k4 + 3) * GBP + n]);
        }
        __syncthreads();
        #pragma unroll
        for (int k0 = 0; k0 < 16; k0 += 8) {
            unsigned ah[2][4], al[2][4], bh[3][2], bl[3][2];
            #pragma unroll
            for (int mi = 0; mi < 2; mi++) {
                int row = i0 + mi * 16 + gq;
                ah[mi][0] = Bhi[(k0 + tq) * GBP + row];
                ah[mi][1] = Bhi[(k0 + tq) * GBP + row + 8];
                ah[mi][2] = Bhi[(k0 + tq + 4) * GBP + row];
                ah[mi][3] = Bhi[(k0 + tq + 4) * GBP + row + 8];
                al[mi][0] = Blo[(k0 + tq) * GBP + row];
                al[mi][1] = Blo[(k0 + tq) * GBP + row + 8];
                al[mi][2] = Blo[(k0 + tq + 4) * GBP + row];
                al[mi][3] = Blo[(k0 + tq + 4) * GBP + row + 8];
            }
            #pragma unroll
            for (int ni = 0; ni < 3; ni++) {
                int c0 = warp * 24 + ni * 8;
                bh[ni][0] = Bhi[(k0 + tq) * GBP + c0 + gq];
                bh[ni][1] = Bhi[(k0 + tq + 4) * GBP + c0 + gq];
                bl[ni][0] = Blo[(k0 + tq) * GBP + c0 + gq];
                bl[ni][1] = Blo[(k0 + tq + 4) * GBP + c0 + gq];
            }
            #pragma unroll
            for (int mi = 0; mi < 2; mi++)
                #pragma unroll
                for (int ni = 0; ni < 3; ni++) {
                    mma8(acc[mi][ni], ah[mi], bh[ni]);
                    mma8(acc[mi][ni], ah[mi], bl[ni]);
                    mma8(acc[mi][ni], al[mi], bh[ni]);
                }
        }
        __syncthreads();
    }

    float* d2s = (float*)Bbuf;
    #pragma unroll
    for (int mi = 0; mi < 2; mi++)
        #pragma unroll
        for (int ni = 0; ni < 3; ni++)
            #pragma unroll
            for (int e = 0; e < 4; e++) {
                int r = mi * 16 + gq + (e >> 1) * 8;
                int c = warp * 24 + ni * 8 + 2 * tq + (e & 1);
                float v2 = sq[i0 + r] + sq[c] - 2.f * acc[mi][ni][e];
                d2s[r * 192 + c] = fmaxf(v2, 0.f);
            }
    __syncthreads();

    int tx = lane;
    for (int q = 0; q < 4; q++) {
        int r = warp * 4 + q;
        float val[6];
        #pragma unroll
        for (int s = 0; s < 6; s++) val[s] = d2s[r * 192 + tx + 32 * s];
        unsigned mask[6] = {0, 0, 0, 0, 0, 0};
        for (int pick = 0; pick < KTOP; pick++) {
            float bv = val[0]; int bi = tx;
            #pragma unroll
            for (int s = 1; s < 6; s++) {
                float vv = val[s];
                if (vv < bv) { bv = vv; bi = tx + 32 * s; }
            }
            #pragma unroll
            for (int o = 16; o; o >>= 1) {
                float ov = __shfl_down_sync(0xffffffffu, bv, o);
                int   oi = __shfl_down_sync(0xffffffffu, bi, o);
                if (ov < bv || (ov == bv && oi < bi)) { bv = ov; bi = oi; }
            }
            bi = __shfl_sync(0xffffffffu, bi, 0);
            if ((bi & 31) == tx) val[bi >> 5] = FLT_MAX;
            mask[bi >> 5] |= 1u << (bi & 31);
        }
        if (tx == 0) {
            int e = i0 + r;
            int u = e / 3;
            mask[u >> 5]           |= 1u << (u & 31);
            mask[(u + 64) >> 5]    |= 1u << ((u + 64) & 31);
            mask[(u + 128) >> 5]   |= 1u << ((u + 128) & 31);
            #pragma unroll
            for (int w = 0; w < 6; w++)
                g_H[(size_t)(d * M + e) * 6 + w] = mask[w];
        }
    }
}

// ---------------- K3: X = feat @ W_fc + b_fc  (tf32 mma, 128x128 tile) ----------------
#define FAP 36
#define FBP 136
__global__ void __launch_bounds__(256) k_fc_mma(const float* t, const float* a,
        const float* v, const float* Wfc, const float* bfc) {
    __shared__ unsigned sA[128 * FAP];
    __shared__ unsigned sB[32 * FBP];
    __shared__ const float* ptrA[128];
    int bn = blockIdx.x, bm = blockIdx.y;
    int tid = threadIdx.x, lane = tid & 31, warp = tid >> 5;
    int wy = warp >> 1, wx = warp & 1;
    int gq = lane >> 2, tq = lane & 3;
    if (tid < 128) { int gn = bm * 128 + tid; ptrA[tid] = feat_row(gn / M, gn % M, t, a, v); }
    __syncthreads();

    float acc[2][8][4];
    #pragma unroll
    for (int mi = 0; mi < 2; mi++)
        #pragma unroll
        for (int ni = 0; ni < 8; ni++)
            #pragma unroll
            for (int e = 0; e < 4; e++) acc[mi][ni][e] = 0.f;

    for (int kc = 0; kc < DIMF; kc += 32) {
        #pragma unroll
        for (int it = 0; it < 4; it++) {
            int idx = tid + it * 256;
            int r = idx >> 3, c = (idx & 7) * 4;
            float4 xv = *(const float4*)(ptrA[r] + kc + c);
            sA[r * FAP + c]     = f2tf(xv.x);
            sA[r * FAP + c + 1] = f2tf(xv.y);
            sA[r * FAP + c + 2] = f2tf(xv.z);
            sA[r * FAP + c + 3] = f2tf(xv.w);
        }
        #pragma unroll
        for (int it = 0; it < 4; it++) {
            int idx = tid + it * 256;
            int kr = idx >> 5, n4 = (idx & 31) * 4;
            float4 wv = *(const float4*)(Wfc + (size_t)(kc + kr) * G + bn * 128 + n4);
            sB[kr * FBP + n4]     = f2tf(wv.x);
            sB[kr * FBP + n4 + 1] = f2tf(wv.y);
            sB[kr * FBP + n4 + 2] = f2tf(wv.z);
            sB[kr * FBP + n4 + 3] = f2tf(wv.w);
        }
        __syncthreads();
        #pragma unroll
        for (int k0 = 0; k0 < 32; k0 += 8) {
            unsigned af[2][4], bf[8][2];
            #pragma unroll
            for (int mi = 0; mi < 2; mi++) {
                int row = wy * 32 + mi * 16;
                af[mi][0] = sA[(row + gq) * FAP + k0 + tq];
                af[mi][1] = sA[(row + gq + 8) * FAP + k0 + tq];
                af[mi][2] = sA[(row + gq) * FAP + k0 + tq + 4];
                af[mi][3] = sA[(row + gq + 8) * FAP + k0 + tq + 4];
            }
            #pragma unroll
            for (int ni = 0; ni < 8; ni++) {
                int c0 = wx * 64 + ni * 8;
                bf[ni][0] = sB[(k0 + tq) * FBP + c0 + gq];
                bf[ni][1] = sB[(k0 + tq + 4) * FBP + c0 + gq];
            }
            #pragma unroll
            for (int mi = 0; mi < 2; mi++)
                #pragma unroll
                for (int ni = 0; ni < 8; ni++)
                    mma8(acc[mi][ni], af[mi], bf[ni]);
        }
        __syncthreads();
    }
    #pragma unroll
    for (int mi = 0; mi < 2; mi++)
        #pragma unroll
        for (int ni = 0; ni < 8; ni++)
            #pragma unroll
            for (int e = 0; e < 4; e++) {
                int r  = bm * 128 + wy * 32 + mi * 16 + gq + (e >> 1) * 8;
                int cc = bn * 128 + wx * 64 + ni * 8 + 2 * tq + (e & 1);
                g_X[(size_t)r * G + cc] = acc[mi][ni][e] + bfc[cc];
            }
}

// ---------------- K4: fused hypergraph hops  Y = H^T ((H X)/deg_e) / deg_v ----------------
// block = (32-col slice, dialogue); E tile lives in smem, never in global.
// A fragments (0/1) extracted from mask words on the fly (no sA buffer).
#define BP3 40     // B pitch (32 + 8)
#define SEP 33     // E tile pitch
__global__ void __launch_bounds__(256) k_agg_f() {
    __shared__ unsigned sHw[192 * 6];
    __shared__ float    sdegE[192], sdegV[192];
    __shared__ unsigned sB[2 * 16 * BP3];     // hi | lo
    __shared__ float    sE[192 * SEP];
    int d = blockIdx.y, n0 = blockIdx.x * 32;
    int tid = threadIdx.x, lane = tid & 31, warp = tid >> 5;
    int wy = warp >> 1, wx = warp & 1;        // wy: 48 rows, wx: 16 cols
    int gq = lane >> 2, tq = lane & 3;

    for (int i = tid; i < 192 * 6; i += 256) sHw[i] = g_H[(size_t)(d * M) * 6 + i];
    __syncthreads();
    if (tid < 192) {
        int dege = 0;
        #pragma unroll
        for (int w = 0; w < 6; w++) dege += __popc(sHw[tid * 6 + w]);
        sdegE[tid] = 1.f / (float)dege;
        int wsel = tid >> 5, bsel = tid & 31;
        int degv = 0;
        for (int e = 0; e < 192; e++) degv += (sHw[e * 6 + wsel] >> bsel) & 1u;
        sdegV[tid] = 1.f / (float)degv;
    }

    float acc[3][2][4];
    #pragma unroll
    for (int mi = 0; mi < 3; mi++)
        #pragma unroll
        for (int ni = 0; ni < 2; ni++)
            #pragma unroll
            for (int e = 0; e < 4; e++) acc[mi][ni][e] = 0.f;

    int kr = tid >> 4, c2 = (tid & 15) * 2;   // 16 rows x 32 cols, float2/thread
    float2 nxt = *(const float2*)(g_X + (size_t)(d * M + kr) * G + n0 + c2);

    // ---- hop 0: E = (H @ X) / deg_e ----
    for (int kc = 0; kc < 192; kc += 16) {
        hilo(nxt.x, sB[kr * BP3 + c2],     sB[16 * BP3 + kr * BP3 + c2]);
        hilo(nxt.y, sB[kr * BP3 + c2 + 1], sB[16 * BP3 + kr * BP3 + c2 + 1]);
        __syncthreads();
        if (kc + 16 < 192)
            nxt = *(const float2*)(g_X + (size_t)(d * M + kc + 16 + kr) * G + n0 + c2);
        #pragma unroll
        for (int k0 = 0; k0 < 16; k0 += 8) {
            unsigned af[3][4], bh[2][2], bl[2][2];
            int kk  = kc + k0 + tq;
            int kk2 = kk + 4;
            #pragma unroll
            for (int mi = 0; mi < 3; mi++) {
                int e0 = wy * 48 + mi * 16 + gq;
                af[mi][0] = ((sHw[e0 * 6       + (kk  >> 5)] >> (kk  & 31)) & 1u) ? 0x3F800000u : 0u;
                af[mi][1] = ((sHw[(e0 + 8) * 6 + (kk  >> 5)] >> (kk  & 31)) & 1u) ? 0x3F800000u : 0u;
                af[mi][2] = ((sHw[e0 * 6       + (kk2 >> 5)] >> (kk2 & 31)) & 1u) ? 0x3F800000u : 0u;
                af[mi][3] = ((sHw[(e0 + 8) * 6 + (kk2 >> 5)] >> (kk2 & 31)) & 1u) ? 0x3F800000u : 0u;
            }
            #pragma unroll
            for (int ni = 0; ni < 2; ni++) {
                int c0 = wx * 16 + ni * 8;
                bh[ni][0] = sB[(k0 + tq) * BP3 + c0 + gq];
                bh[ni][1] = sB[(k0 + tq + 4) * BP3 + c0 + gq];
                bl[ni][0] = sB[16 * BP3 + (k0 + tq) * BP3 + c0 + gq];
                bl[ni][1] = sB[16 * BP3 + (k0 + tq + 4) * BP3 + c0 + gq];
            }
            #pragma unroll
            for (int mi = 0; mi < 3; mi++)
                #pragma unroll
                for (int ni = 0; ni < 2; ni++) {
                    mma8(acc[mi][ni], af[mi], bh[ni]);
                    mma8(acc[mi][ni], af[mi], bl[ni]);
                }
        }
        __syncthreads();
    }
    // E tile -> smem (scaled)
    #pragma unroll
    for (int mi = 0; mi < 3; mi++)
        #pragma unroll
        for (int ni = 0; ni < 2; ni++)
            #pragma unroll
            for (int e = 0; e < 4; e++) {
                int r = wy * 48 + mi * 16 + gq + (e >> 1) * 8;
                int c = wx * 16 + ni * 8 + 2 * tq + (e & 1);
                sE[r * SEP + c] = acc[mi][ni][e] * sdegE[r];
            }
    #pragma unroll
    for (int mi = 0; mi < 3; mi++)
        #pragma unroll
        for (int ni = 0; ni < 2; ni++)
            #pragma unroll
            for (int e = 0; e < 4; e++) acc[mi][ni][e] = 0.f;
    __syncthreads();

    // ---- hop 1: Y = (H^T @ E) / deg_v ----
    for (int kc = 0; kc < 192; kc += 16) {
        float e0v = sE[(kc + kr) * SEP + c2];
        float e1v = sE[(kc + kr) * SEP + c2 + 1];
        hilo(e0v, sB[kr * BP3 + c2],     sB[16 * BP3 + kr * BP3 + c2]);
        hilo(e1v, sB[kr * BP3 + c2 + 1], sB[16 * BP3 + kr * BP3 + c2 + 1]);
        __syncthreads();
        #pragma unroll
        for (int k0 = 0; k0 < 16; k0 += 8) {
            unsigned af[3][4], bh[2][2], bl[2][2];
            int kk  = kc + k0 + tq;       // edge index
            int kk2 = kk + 4;
            #pragma unroll
            for (int mi = 0; mi < 3; mi++) {
                int nrow = wy * 48 + mi * 16 + gq;    // node index
                af[mi][0] = ((sHw[kk  * 6 + (nrow >> 5)]       >> (nrow & 31))       & 1u) ? 0x3F800000u : 0u;
                af[mi][1] = ((sHw[kk  * 6 + ((nrow + 8) >> 5)] >> ((nrow + 8) & 31)) & 1u) ? 0x3F800000u : 0u;
                af[mi][2] = ((sHw[kk2 * 6 + (nrow >> 5)]       >> (nrow & 31))       & 1u) ? 0x3F800000u : 0u;
                af[mi][3] = ((sHw[kk2 * 6 + ((nrow + 8) >> 5)] >> ((nrow + 8) & 31)) & 1u) ? 0x3F800000u : 0u;
            }
            #pragma unroll
            for (int ni = 0; ni < 2; ni++) {
                int c0 = wx * 16 + ni * 8;
                bh[ni][0] = sB[(k0 + tq) * BP3 + c0 + gq];
                bh[ni][1] = sB[(k0 + tq + 4) * BP3 + c0 + gq];
                bl[ni][0] = sB[16 * BP3 + (k0 + tq) * BP3 + c0 + gq];
                bl[ni][1] = sB[16 * BP3 + (k0 + tq + 4) * BP3 + c0 + gq];
            }
            #pragma unroll
            for (int mi = 0; mi < 3; mi++)
                #pragma unroll
                for (int ni = 0; ni < 2; ni++) {
                    mma8(acc[mi][ni], af[mi], bh[ni]);
                    mma8(acc[mi][ni], af[mi], bl[ni]);
                }
        }
        __syncthreads();
    }
    #pragma unroll
    for (int mi = 0; mi < 3; mi++)
        #pragma unroll
        for (int ni = 0; ni < 2; ni++)
            #pragma unroll
            for (int e = 0; e < 4; e++) {
                int r = wy * 48 + mi * 16 + gq + (e >> 1) * 8;
                int c = n0 + wx * 16 + ni * 8 + 2 * tq + (e & 1);
                g_Y[(size_t)(d * M + r) * G + c] = acc[mi][ni][e] * sdegV[r];
            }
}

// ---------------- K6: out = relu(Y @ W_h + b_h) (tf32 mma), regrouped ----------------
__global__ void __launch_bounds__(256) k_out_mma(const float* Wh, const float* bh,
                                                 float* out) {
    __shared__ unsigned sA[128 * FAP];
    __shared__ unsigned sB[32 * FBP];
    int bn = blockIdx.x, bm = blockIdx.y;
    int tid = threadIdx.x, lane = tid & 31, warp = tid >> 5;
    int wy = warp >> 1, wx = warp & 1;
    int gq = lane >> 2, tq = lane & 3;

    float acc[2][8][4];
    #pragma unroll
    for (int mi = 0; mi < 2; mi++)
        #pragma unroll
        for (int ni = 0; ni < 8; ni++)
            #pragma unroll
            for (int e = 0; e < 4; e++) acc[mi][ni][e] = 0.f;

    for (int kc = 0; kc < G; kc += 32) {
        #pragma unroll
        for (int it = 0; it < 4; it++) {
            int idx = tid + it * 256;
            int r = idx >> 3, c = (idx & 7) * 4;
            float4 xv = *(const float4*)(g_Y + (size_t)(bm * 128 + r) * G + kc + c);
            sA[r * FAP + c]     = f2tf(xv.x);
            sA[r * FAP + c + 1] = f2tf(xv.y);
            sA[r * FAP + c + 2] = f2tf(xv.z);
            sA[r * FAP + c + 3] = f2tf(xv.w);
        }
        #pragma unroll
        for (int it = 0; it < 4; it++) {
            int idx = tid + it * 256;
            int kr = idx >> 5, n4 = (idx & 31) * 4;
            float4 wv = *(const float4*)(Wh + (size_t)(kc + kr) * G + bn * 128 + n4);
            sB[kr * FBP + n4]     = f2tf(wv.x);
            sB[kr * FBP + n4 + 1] = f2tf(wv.y);
            sB[kr * FBP + n4 + 2] = f2tf(wv.z);
            sB[kr * FBP + n4 + 3] = f2tf(wv.w);
        }
        __syncthreads();
        #pragma unroll
        for (int k0 = 0; k0 < 32; k0 += 8) {
            unsigned af[2][4], bf[8][2];
            #pragma unroll
            for (int mi = 0; mi < 2; mi++) {
                int row = wy * 32 + mi * 16;
                af[mi][0] = sA[(row + gq) * FAP + k0 + tq];
                af[mi][1] = sA[(row + gq + 8) * FAP + k0 + tq];
                af[mi][2] = sA[(row + gq) * FAP + k0 + tq + 4];
                af[mi][3] = sA[(row + gq + 8) * FAP + k0 + tq + 4];
            }
            #pragma unroll
            for (int ni = 0; ni < 8; ni++) {
                int c0 = wx * 64 + ni * 8;
                bf[ni][0] = sB[(k0 + tq) * FBP + c0 + gq];
                bf[ni][1] = sB[(k0 + tq + 4) * FBP + c0 + gq];
            }
            #pragma unroll
            for (int mi = 0; mi < 2; mi++)
                #pragma unroll
                for (int ni = 0; ni < 8; ni++)
                    mma8(acc[mi][ni], af[mi], bf[ni]);
        }
        __syncthreads();
    }
    #pragma unroll
    for (int mi = 0; mi < 2; mi++)
        #pragma unroll
        for (int ni = 0; ni < 8; ni++)
            #pragma unroll
            for (int e = 0; e < 4; e++) {
                int gn = bm * 128 + wy * 32 + mi * 16 + gq + (e >> 1) * 8;
                int gc = bn * 128 + wx * 64 + ni * 8 + 2 * tq + (e & 1);
                int dd = gn / M, n = gn % M, mod = n >> 6, ii = n & 63;
                out[(size_t)(dd * L + ii) * 768 + mod * 256 + gc] =
                    fmaxf(acc[mi][ni][e] + bh[gc], 0.f);
            }
}

// ---------------- K7: norms, diag sims, zero LSE accumulators, bf16 convert ----------------
__global__ void k_norm(const float* out) {
    int i = blockIdx.x;
    int tid = threadIdx.x;
    float tv = out[(size_t)i * 768 + tid];
    float av = out[(size_t)i * 768 + 256 + tid];
    float vv = out[(size_t)i * 768 + 512 + tid];
    float q[6] = { tv * tv, av * av, vv * vv, tv * av, tv * vv, av * vv };
    __shared__ float red[6][8];
    __shared__ float sinv[3];
    int lane = tid & 31, w = tid >> 5;
    #pragma unroll
    for (int o = 16; o; o >>= 1)
        #pragma unroll
        for (int k = 0; k < 6; k++) q[k] += __shfl_down_sync(0xffffffffu, q[k], o);
    if (lane == 0)
        #pragma unroll
        for (int k = 0; k < 6; k++) red[k][w] = q[k];
    __syncthreads();
    if (tid == 0) {
        float s[6];
        #pragma unroll
        for (int k = 0; k < 6; k++) {
            s[k] = 0.f;
            #pragma unroll
            for (int w2 = 0; w2 < 8; w2++) s[k] += red[k][w2];
        }
        float it = 1.f / (sqrtf(s[0]) + 1e-8f);
        float ia = 1.f / (sqrtf(s[1]) + 1e-8f);
        float iv = 1.f / (sqrtf(s[2]) + 1e-8f);
        sinv[0] = it * SQTAUI; sinv[1] = ia * SQTAUI; sinv[2] = iv * SQTAUI;
        g_diag[i]             = s[3] * it * ia * TAUINV;
        g_diag[NROWS + i]     = s[4] * it * iv * TAUINV;
        g_diag[2 * NROWS + i] = s[5] * ia * iv * TAUINV;
        g_rowsum[i] = 0.f; g_rowsum[NROWS + i] = 0.f; g_rowsum[2 * NROWS + i] = 0.f;
        g_colsum[i] = 0.f; g_colsum[NROWS + i] = 0.f; g_colsum[2 * NROWS + i] = 0.f;
    }
    __syncthreads();
    g_nb[((size_t)0 * NROWS + i) * G + tid] = __float2bfloat16(tv * sinv[0]);
    g_nb[((size_t)1 * NROWS + i) * G + tid] = __float2bfloat16(av * sinv[1]);
    g_nb[((size_t)2 * NROWS + i) * G + tid] = __float2bfloat16(vv * sinv[2]);
}

// ---------------- K8: bf16 tensor-core sim tiles, cp.async double-buffered ----------------
#define SPITCH 40
__global__ void __launch_bounds__(256) k_sim_mma() {
    int p = blockIdx.z;
    int mx = (p == 2) ? 1 : 0;
    int my = (p == 0) ? 1 : 2;
    int row0 = blockIdx.y * 128, col0 = blockIdx.x * 128;
    __shared__ __nv_bfloat16 sX[2][128 * SPITCH];
    __shared__ __nv_bfloat16 sY[2][128 * SPITCH];
    __shared__ float srow[128], scol[128];
    int tid = threadIdx.x, lane = tid & 31, warp = tid >> 5;
    int wy = warp >> 1, wx = warp & 1;      // warp tile: 32 rows x 64 cols

    const __nv_bfloat16* xg = g_nb + ((size_t)mx * NROWS + row0) * G;
    const __nv_bfloat16* yg = g_nb + ((size_t)my * NROWS + col0) * G;

    int lr = tid >> 2, lc = (tid & 3) * 8;
    int lr2 = lr + 64;

    float acc[2][8][4];
    #pragma unroll
    for (int mi = 0; mi < 2; mi++)
        #pragma unroll
        for (int ni = 0; ni < 8; ni++)
            #pragma unroll
            for (int r = 0; r < 4; r++) acc[mi][ni][r] = 0.f;

    cp16(&sX[0][lr * SPITCH + lc],  xg + (size_t)lr * G + lc);
    cp16(&sX[0][lr2 * SPITCH + lc], xg + (size_t)lr2 * G + lc);
    cp16(&sY[0][lr * SPITCH + lc],  yg + (size_t)lr * G + lc);
    cp16(&sY[0][lr2 * SPITCH + lc], yg + (size_t)lr2 * G + lc);
    cp_commit();

    #pragma unroll
    for (int c = 0; c < 8; c++) {
        int cur = c & 1;
        if (c < 7) {
            int nb = (c + 1) & 1, kc = (c + 1) * 32;
            cp16(&sX[nb][lr * SPITCH + lc],  xg + (size_t)lr * G + kc + lc);
            cp16(&sX[nb][lr2 * SPITCH + lc], xg + (size_t)lr2 * G + kc + lc);
            cp16(&sY[nb][lr * SPITCH + lc],  yg + (size_t)lr * G + kc + lc);
            cp16(&sY[nb][lr2 * SPITCH + lc], yg + (size_t)lr2 * G + kc + lc);
            cp_commit();
            asm volatile("cp.async.wait_group 1;");
        } else {
            asm volatile("cp.async.wait_group 0;");
        }
        __syncthreads();
        #pragma unroll
        for (int ks = 0; ks < 2; ks++) {
            int k0 = ks * 16;
            unsigned A[2][4];
            #pragma unroll
            for (int mi = 0; mi < 2; mi++) {
                int r = wy * 32 + mi * 16 + ((lane >> 3) & 1) * 8 + (lane & 7);
                int cc = k0 + (lane >> 4) * 8;
                unsigned ad = (unsigned)__cvta_generic_to_shared(&sX[cur][r * SPITCH + cc]);
                asm volatile("ldmatrix.sync.aligned.m8n8.x4.shared.b16 {%0,%1,%2,%3},[%4];"
                    : "=r"(A[mi][0]), "=r"(A[mi][1]), "=r"(A[mi][2]), "=r"(A[mi][3])
                    : "r"(ad));
            }
            unsigned B[8][2];
            #pragma unroll
            for (int nb2 = 0; nb2 < 4; nb2++) {
                int r = wx * 64 + nb2 * 16 + (lane >> 4) * 8 + (lane & 7);
                int cc = k0 + ((lane >> 3) & 1) * 8;
                unsigned ad = (unsigned)__cvta_generic_to_shared(&sY[cur][r * SPITCH + cc]);
                asm volatile("ldmatrix.sync.aligned.m8n8.x4.shared.b16 {%0,%1,%2,%3},[%4];"
                    : "=r"(B[2 * nb2][0]), "=r"(B[2 * nb2][1]),
                      "=r"(B[2 * nb2 + 1][0]), "=r"(B[2 * nb2 + 1][1])
                    : "r"(ad));
            }
            #pragma unroll
            for (int mi = 0; mi < 2; mi++)
                #pragma unroll
                for (int ni = 0; ni < 8; ni++)
                    asm volatile(
                        "mma.sync.aligned.m16n8k16.row.col.f32.bf16.bf16.f32 "
                        "{%0,%1,%2,%3},{%4,%5,%6,%7},{%8,%9},{%0,%1,%2,%3};"
                        : "+f"(acc[mi][ni][0]), "+f"(acc[mi][ni][1]),
                          "+f"(acc[mi][ni][2]), "+f"(acc[mi][ni][3])
                        : "r"(A[mi][0]), "r"(A[mi][1]), "r"(A[mi][2]), "r"(A[mi][3]),
                          "r"(B[ni][0]), "r"(B[ni][1]));
        }
        __syncthreads();
    }

    if (tid < 128) { srow[tid] = 0.f; scol[tid] = 0.f; }
    __syncthreads();

    float rowp[2][2] = {{0.f, 0.f}, {0.f, 0.f}};
    float colp[8][2];
    #pragma unroll
    for (int ni = 0; ni < 8; ni++) { colp[ni][0] = 0.f; colp[ni][1] = 0.f; }
    #pragma unroll
    for (int mi = 0; mi < 2; mi++)
        #pragma unroll
        for (int ni = 0; ni < 8; ni++)
            #pragma unroll
            for (int r = 0; r < 4; r++) {
                float e = __expf(acc[mi][ni][r]);
                rowp[mi][r >> 1] += e;
                colp[ni][r & 1] += e;
            }

    #pragma unroll
    for (int mi = 0; mi < 2; mi++)
        #pragma unroll
        for (int h = 0; h < 2; h++) {
            float vv = rowp[mi][h];
            vv += __shfl_xor_sync(0xffffffffu, vv, 1);
            vv += __shfl_xor_sync(0xffffffffu, vv, 2);
            if ((lane & 3) == 0)
                atomicAdd(&srow[wy * 32 + mi * 16 + (lane >> 2) + h * 8], vv);
        }
    #pragma unroll
    for (int ni = 0; ni < 8; ni++)
        #pragma unroll
        for (int s2 = 0; s2 < 2; s2++) {
            float vv = colp[ni][s2];
            vv += __shfl_xor_sync(0xffffffffu, vv, 4);
            vv += __shfl_xor_sync(0xffffffffu, vv, 8);
            vv += __shfl_xor_sync(0xffffffffu, vv, 16);
            if (lane < 4)
                atomicAdd(&scol[wx * 64 + ni * 8 + lane * 2 + s2], vv);
        }
    __syncthreads();
    if (tid < 128) {
        atomicAdd(&g_rowsum[p * NROWS + row0 + tid], srow[tid]);
        atomicAdd(&g_colsum[p * NROWS + col0 + tid], scol[tid]);
    }
}

// ---------------- K9: final loss reduction ----------------
__global__ void k_loss(float* out, int out_size) {
    int tid = threadIdx.x;
    float s = 0.f;
    for (int idx = tid; idx < 3 * NROWS; idx += 256) {
        float dg = g_diag[idx];
        s += 2.f * dg - logf(g_rowsum[idx]) - logf(g_colsum[idx]);
    }
    __shared__ float red[8];
    int lane = tid & 31, w = tid >> 5;
    #pragma unroll
    for (int o = 16; o; o >>= 1) s += __shfl_down_sync(0xffffffffu, s, o);
    if (lane == 0) red[w] = s;
    __syncthreads();
    if (tid == 0) {
        float tot = 0.f;
        #pragma unroll
        for (int w2 = 0; w2 < 8; w2++) tot += red[w2];
        float loss = -tot / (2.f * 3.f * (float)NROWS);
        if (out_size > NROWS * 768) out[NROWS * 768] = loss;
    }
}

// ---------------- launcher ----------------
extern "C" void kernel_launch(void* const* d_in, const int* in_sizes, int n_in,
                              void* d_out, int out_size) {
    const float* t   = (const float*)d_in[0];
    const float* a   = (const float*)d_in[1];
    const float* v   = (const float*)d_in[2];
    const float* Wfc = (const float*)d_in[3];
    const float* bfc = (const float*)d_in[4];
    const float* Wh  = (const float*)d_in[5];
    const float* bh  = (const float*)d_in[6];
    float* out = (float*)d_out;

    k_sq<<<NNODE / 8, 256>>>(t, a, v);
    k_gram_mma<<<dim3(6, 64), 256>>>(t, a, v);
    k_fc_mma<<<dim3(2, 96), 256>>>(t, a, v, Wfc, bfc);
    k_agg_f<<<dim3(8, 64), 256>>>();
    k_out_mma<<<dim3(2, 96), 256>>>(Wh, bh, out);
    k_norm<<<NROWS, 256>>>(out);
    k_sim_mma<<<dim3(32, 32, 3), 256>>>();
    k_loss<<<1, 256>>>(out, out_size);
}

// round 9
// speedup vs baseline: 5.8916x; 1.0867x over previous
#include <cuda_runtime.h>
#include <cuda_bf16.h>
#include <math.h>
#include <float.h>

#define D 64
#define L 64
#define DIMF 512
#define G 256
#define M 192                 // 3*L nodes (= hyperedges) per dialogue
#define KTOP 12
#define NROWS 4096            // D*L
#define NNODE (D*M)           // 12288
#define TAUINV (1.0f/0.07f)
#define SQTAUI 3.7796447300922722f   // sqrt(1/0.07)

// ---- scratch (static device arrays; no allocation allowed) ----
__device__ float    g_sq[NNODE];
__device__ unsigned g_fh[(size_t)NNODE*DIMF];   // tf32 hi of features
__device__ unsigned g_fl[(size_t)NNODE*DIMF];   // tf32 lo of features
__device__ unsigned g_H[NNODE*6];       // 192-bit incidence mask per edge
__device__ float    g_X[NNODE*G];
__device__ float    g_Y[NNODE*G];
__device__ float    g_diag[3*NROWS];
__device__ float    g_rowsum[3*NROWS];
__device__ float    g_colsum[3*NROWS];
__device__ __nv_bfloat16 g_nb[(size_t)3*NROWS*G];   // normalized bf16 features (loss path only)

__device__ __forceinline__ const float* feat_row(int d, int n,
        const float* t, const float* a, const float* v) {
    int mod = n >> 6, i = n & 63;
    const float* base = (mod == 0) ? t : (mod == 1) ? a : v;
    return base + (size_t)(d * L + i) * DIMF;
}

// ---- tf32 helpers ----
__device__ __forceinline__ unsigned f2tf(float x) {
    unsigned u; asm("cvt.rna.tf32.f32 %0, %1;" : "=r"(u) : "f"(x)); return u;
}
__device__ __forceinline__ void hilo(float x, unsigned& h, unsigned& l) {
    h = f2tf(x);
    l = f2tf(x - __uint_as_float(h));
}
__device__ __forceinline__ void mma8(float* c, const unsigned* a, const unsigned* b) {
    asm volatile("mma.sync.aligned.m16n8k8.row.col.f32.tf32.tf32.f32 "
        "{%0,%1,%2,%3},{%4,%5,%6,%7},{%8,%9},{%0,%1,%2,%3};"
        : "+f"(c[0]), "+f"(c[1]), "+f"(c[2]), "+f"(c[3])
        : "r"(a[0]), "r"(a[1]), "r"(a[2]), "r"(a[3]), "r"(b[0]), "r"(b[1]));
}

// ---- cp.async helpers ----
__device__ __forceinline__ void cp16(void* dst_smem, const void* src) {
    unsigned ad = (unsigned)__cvta_generic_to_shared(dst_smem);
    asm volatile("cp.async.cg.shared.global [%0],[%1],16;" :: "r"(ad), "l"(src));
}
__device__ __forceinline__ void cp_commit() {
    asm volatile("cp.async.commit_group;");
}

// ---------------- K1: per-node squared norms + hi/lo precompute ----------------
__global__ void k_sq(const float* t, const float* a, const float* v) {
    int warp = (blockIdx.x * blockDim.x + threadIdx.x) >> 5;
    int lane = threadIdx.x & 31;
    if (warp >= NNODE) return;
    int d = warp / M, n = warp % M;
    const float* r = feat_row(d, n, t, a, v);
    // g_sq: EXACT same summation order as previous rounds (selection stability)
    float s = 0.f;
    #pragma unroll
    for (int c = lane; c < DIMF; c += 32) { float x = r[c]; s += x * x; }
    // hi/lo precompute (L1 hits on the re-read)
    unsigned* fh = g_fh + (size_t)warp * DIMF;
    unsigned* fl = g_fl + (size_t)warp * DIMF;
    #pragma unroll
    for (int c0 = lane * 4; c0 < DIMF; c0 += 128) {
        float4 x = *(const float4*)(r + c0);
        uint4 h, l;
        hilo(x.x, h.x, l.x); hilo(x.y, h.y, l.y);
        hilo(x.z, h.z, l.z); hilo(x.w, h.w, l.w);
        *(uint4*)(fh + c0) = h;
        *(uint4*)(fl + c0) = l;
    }
    #pragma unroll
    for (int o = 16; o; o >>= 1) s += __shfl_down_sync(0xffffffffu, s, o);
    if (lane == 0) g_sq[warp] = s;
}

// ---------------- K2: 3xTF32 gram + d2 + top-12 + incidence masks ----------------
// B tile node-major [n][k] pitch 20, filled by cp.async from precomputed hi/lo.
// A fragments read transposed from the same tile (A rows are a subset of nodes).
#define GBP2 20
__global__ void __launch_bounds__(256) k_gram_mma() {
    __shared__ unsigned Bbuf[2 * 192 * GBP2];        // hi | lo ; reused as d2 [32][192]
    __shared__ float sq[M];
    unsigned* Bhi = Bbuf;
    unsigned* Blo = Bbuf + 192 * GBP2;

    int d = blockIdx.y, i0 = blockIdx.x * 32;
    int tid = threadIdx.x, lane = tid & 31, warp = tid >> 5;
    int gq = lane >> 2, tq = lane & 3;
    if (tid < M) sq[tid] = g_sq[d * M + tid];
    size_t base = (size_t)(d * M) * DIMF;

    float acc[2][3][4];
    #pragma unroll
    for (int mi = 0; mi < 2; mi++)
        #pragma unroll
        for (int ni = 0; ni < 3; ni++)
            #pragma unroll
            for (int e = 0; e < 4; e++) acc[mi][ni][e] = 0.f;

    for (int kc = 0; kc < DIMF; kc += 16) {
        #pragma unroll
        for (int it = 0; it < 3; it++) {
            int idx = tid + it * 256;              // 0..767
            int n = idx >> 2, k4 = (idx & 3) * 4;
            cp16(Bhi + n * GBP2 + k4, g_fh + base + (size_t)n * DIMF + kc + k4);
            cp16(Blo + n * GBP2 + k4, g_fl + base + (size_t)n * DIMF + kc + k4);
        }
        cp_commit();
        asm volatile("cp.async.wait_group 0;");
        __syncthreads();
        #pragma unroll
        for (int k0 = 0; k0 < 16; k0 += 8) {
            unsigned ah[2][4], al[2][4], bh[3][2], bl[3][2];
            #pragma unroll
            for (int mi = 0; mi < 2; mi++) {
                int r0 = (i0 + mi * 16 + gq) * GBP2;
                int r1 = r0 + 8 * GBP2;
                ah[mi][0] = Bhi[r0 + k0 + tq];
                ah[mi][1] = Bhi[r1 + k0 + tq];
                ah[mi][2] = Bhi[r0 + k0 + tq + 4];
                ah[mi][3] = Bhi[r1 + k0 + tq + 4];
                al[mi][0] = Blo[r0 + k0 + tq];
                al[mi][1] = Blo[r1 + k0 + tq];
                al[mi][2] = Blo[r0 + k0 + tq + 4];
                al[mi][3] = Blo[r1 + k0 + tq + 4];
            }
            #pragma unroll
            for (int ni = 0; ni < 3; ni++) {
                int c0 = (warp * 24 + ni * 8 + gq) * GBP2;
                bh[ni][0] = Bhi[c0 + k0 + tq];
                bh[ni][1] = Bhi[c0 + k0 + tq + 4];
                bl[ni][0] = Blo[c0 + k0 + tq];
                bl[ni][1] = Blo[c0 + k0 + tq + 4];
            }
            #pragma unroll
            for (int mi = 0; mi < 2; mi++)
                #pragma unroll
                for (int ni = 0; ni < 3; ni++) {
                    mma8(acc[mi][ni], ah[mi], bh[ni]);
                    mma8(acc[mi][ni], ah[mi], bl[ni]);
                    mma8(acc[mi][ni], al[mi], bh[ni]);
                }
        }
        __syncthreads();
    }

    float* d2s = (float*)Bbuf;
    #pragma unroll
    for (int mi = 0; mi < 2; mi++)
        #pragma unroll
        for (int ni = 0; ni < 3; ni++)
            #pragma unroll
            for (int e = 0; e < 4; e++) {
                int r = mi * 16 + gq + (e >> 1) * 8;
                int c = warp * 24 + ni * 8 + 2 * tq + (e & 1);
                float v2 = sq[i0 + r] + sq[c] - 2.f * acc[mi][ni][e];
                d2s[r * 192 + c] = fmaxf(v2, 0.f);
            }
    __syncthreads();

    int tx = lane;
    for (int q = 0; q < 4; q++) {
        int r = warp * 4 + q;
        float val[6];
        #pragma unroll
        for (int s = 0; s < 6; s++) val[s] = d2s[r * 192 + tx + 32 * s];
        unsigned mask[6] = {0, 0, 0, 0, 0, 0};
        for (int pick = 0; pick < KTOP; pick++) {
            float bv = val[0]; int bi = tx;
            #pragma unroll
            for (int s = 1; s < 6; s++) {
                float vv = val[s];
                if (vv < bv) { bv = vv; bi = tx + 32 * s; }
            }
            #pragma unroll
            for (int o = 16; o; o >>= 1) {
                float ov = __shfl_down_sync(0xffffffffu, bv, o);
                int   oi = __shfl_down_sync(0xffffffffu, bi, o);
                if (ov < bv || (ov == bv && oi < bi)) { bv = ov; bi = oi; }
            }
            bi = __shfl_sync(0xffffffffu, bi, 0);
            if ((bi & 31) == tx) val[bi >> 5] = FLT_MAX;
            mask[bi >> 5] |= 1u << (bi & 31);
        }
        if (tx == 0) {
            int e = i0 + r;
            int u = e / 3;
            mask[u >> 5]           |= 1u << (u & 31);
            mask[(u + 64) >> 5]    |= 1u << ((u + 64) & 31);
            mask[(u + 128) >> 5]   |= 1u << ((u + 128) & 31);
            #pragma unroll
            for (int w = 0; w < 6; w++)
                g_H[(size_t)(d * M + e) * 6 + w] = mask[w];
        }
    }
}

// ---------------- K3: X = feat @ W_fc + b_fc  (tf32 mma, 128x128 tile) ----------------
#define FAP 36
#define FBP 136
__global__ void __launch_bounds__(256) k_fc_mma(const float* Wfc, const float* bfc) {
    __shared__ unsigned sA[128 * FAP];
    __shared__ unsigned sB[32 * FBP];
    int bn = blockIdx.x, bm = blockIdx.y;
    int tid = threadIdx.x, lane = tid & 31, warp = tid >> 5;
    int wy = warp >> 1, wx = warp & 1;
    int gq = lane >> 2, tq = lane & 3;

    float acc[2][8][4];
    #pragma unroll
    for (int mi = 0; mi < 2; mi++)
        #pragma unroll
        for (int ni = 0; ni < 8; ni++)
            #pragma unroll
            for (int e = 0; e < 4; e++) acc[mi][ni][e] = 0.f;

    for (int kc = 0; kc < DIMF; kc += 32) {
        #pragma unroll
        for (int it = 0; it < 4; it++) {
            int idx = tid + it * 256;
            int r = idx >> 3, c = (idx & 7) * 4;
            cp16(sA + r * FAP + c, g_fh + (size_t)(bm * 128 + r) * DIMF + kc + c);
        }
        cp_commit();
        #pragma unroll
        for (int it = 0; it < 4; it++) {
            int idx = tid + it * 256;
            int kr = idx >> 5, n4 = (idx & 31) * 4;
            float4 wv = *(const float4*)(Wfc + (size_t)(kc + kr) * G + bn * 128 + n4);
            sB[kr * FBP + n4]     = f2tf(wv.x);
            sB[kr * FBP + n4 + 1] = f2tf(wv.y);
            sB[kr * FBP + n4 + 2] = f2tf(wv.z);
            sB[kr * FBP + n4 + 3] = f2tf(wv.w);
        }
        asm volatile("cp.async.wait_group 0;");
        __syncthreads();
        #pragma unroll
        for (int k0 = 0; k0 < 32; k0 += 8) {
            unsigned af[2][4], bf[8][2];
            #pragma unroll
            for (int mi = 0; mi < 2; mi++) {
                int row = wy * 32 + mi * 16;
                af[mi][0] = sA[(row + gq) * FAP + k0 + tq];
                af[mi][1] = sA[(row + gq + 8) * FAP + k0 + tq];
                af[mi][2] = sA[(row + gq) * FAP + k0 + tq + 4];
                af[mi][3] = sA[(row + gq + 8) * FAP + k0 + tq + 4];
            }
            #pragma unroll
            for (int ni = 0; ni < 8; ni++) {
                int c0 = wx * 64 + ni * 8;
                bf[ni][0] = sB[(k0 + tq) * FBP + c0 + gq];
                bf[ni][1] = sB[(k0 + tq + 4) * FBP + c0 + gq];
            }
            #pragma unroll
            for (int mi = 0; mi < 2; mi++)
                #pragma unroll
                for (int ni = 0; ni < 8; ni++)
                    mma8(acc[mi][ni], af[mi], bf[ni]);
        }
        __syncthreads();
    }
    #pragma unroll
    for (int mi = 0; mi < 2; mi++)
        #pragma unroll
        for (int ni = 0; ni < 8; ni++)
            #pragma unroll
            for (int e = 0; e < 4; e++) {
                int r  = bm * 128 + wy * 32 + mi * 16 + gq + (e >> 1) * 8;
                int cc = bn * 128 + wx * 64 + ni * 8 + 2 * tq + (e & 1);
                g_X[(size_t)r * G + cc] = acc[mi][ni][e] + bfc[cc];
            }
}

// ---------------- K4: fused hypergraph hops  Y = H^T ((H X)/deg_e) / deg_v ----------------
#define BP3 40     // B pitch (32 + 8)
#define SEP 33     // E tile pitch
#define FONE 0x3F800000u
__global__ void __launch_bounds__(256) k_agg_f() {
    __shared__ unsigned sHw[192 * 6];
    __shared__ float    sdegE[192], sdegV[192];
    __shared__ unsigned sB[2 * 16 * BP3];     // hi | lo
    __shared__ float    sE[192 * SEP];
    int d = blockIdx.y, n0 = blockIdx.x * 32;
    int tid = threadIdx.x, lane = tid & 31, warp = tid >> 5;
    int wy = warp >> 1, wx = warp & 1;        // wy: 48 rows, wx: 16 cols
    int gq = lane >> 2, tq = lane & 3;

    for (int i = tid; i < 192 * 6; i += 256) sHw[i] = g_H[(size_t)(d * M) * 6 + i];
    __syncthreads();
    if (tid < 192) {
        int dege = 0;
        #pragma unroll
        for (int w = 0; w < 6; w++) dege += __popc(sHw[tid * 6 + w]);
        sdegE[tid] = 1.f / (float)dege;
        int wsel = tid >> 5, bsel = tid & 31;
        int degv = 0;
        for (int e = 0; e < 192; e++) degv += (sHw[e * 6 + wsel] >> bsel) & 1u;
        sdegV[tid] = 1.f / (float)degv;
    }

    float acc[3][2][4];
    #pragma unroll
    for (int mi = 0; mi < 3; mi++)
        #pragma unroll
        for (int ni = 0; ni < 2; ni++)
            #pragma unroll
            for (int e = 0; e < 4; e++) acc[mi][ni][e] = 0.f;

    int kr = tid >> 4, c2 = (tid & 15) * 2;   // 16 rows x 32 cols, float2/thread
    float2 nxt = *(const float2*)(g_X + (size_t)(d * M + kr) * G + n0 + c2);

    // ---- hop 0: E = (H @ X) / deg_e ----
    for (int kc = 0; kc < 192; kc += 16) {
        hilo(nxt.x, sB[kr * BP3 + c2],     sB[16 * BP3 + kr * BP3 + c2]);
        hilo(nxt.y, sB[kr * BP3 + c2 + 1], sB[16 * BP3 + kr * BP3 + c2 + 1]);
        __syncthreads();
        if (kc + 16 < 192)
            nxt = *(const float2*)(g_X + (size_t)(d * M + kc + 16 + kr) * G + n0 + c2);
        #pragma unroll
        for (int k0 = 0; k0 < 16; k0 += 8) {
            unsigned af[3][4], bh[2][2], bl[2][2];
            int kk = kc + k0 + tq;
            int kw = kk >> 5, kb = kk & 31;        // kk and kk+4 share a word
            #pragma unroll
            for (int mi = 0; mi < 3; mi++) {
                int e0 = wy * 48 + mi * 16 + gq;
                unsigned w0 = sHw[e0 * 6 + kw];
                unsigned w1 = sHw[(e0 + 8) * 6 + kw];
                af[mi][0] = ((w0 >> kb) & 1u)       ? FONE : 0u;
                af[mi][1] = ((w1 >> kb) & 1u)       ? FONE : 0u;
                af[mi][2] = ((w0 >> (kb + 4)) & 1u) ? FONE : 0u;
                af[mi][3] = ((w1 >> (kb + 4)) & 1u) ? FONE : 0u;
            }
            #pragma unroll
            for (int ni = 0; ni < 2; ni++) {
                int c0 = wx * 16 + ni * 8;
                bh[ni][0] = sB[(k0 + tq) * BP3 + c0 + gq];
                bh[ni][1] = sB[(k0 + tq + 4) * BP3 + c0 + gq];
                bl[ni][0] = sB[16 * BP3 + (k0 + tq) * BP3 + c0 + gq];
                bl[ni][1] = sB[16 * BP3 + (k0 + tq + 4) * BP3 + c0 + gq];
            }
            #pragma unroll
            for (int mi = 0; mi < 3; mi++)
                #pragma unroll
                for (int ni = 0; ni < 2; ni++) {
                    mma8(acc[mi][ni], af[mi], bh[ni]);
                    mma8(acc[mi][ni], af[mi], bl[ni]);
                }
        }
        __syncthreads();
    }
    #pragma unroll
    for (int mi = 0; mi < 3; mi++)
        #pragma unroll
        for (int ni = 0; ni < 2; ni++)
            #pragma unroll
            for (int e = 0; e < 4; e++) {
                int r = wy * 48 + mi * 16 + gq + (e >> 1) * 8;
                int c = wx * 16 + ni * 8 + 2 * tq + (e & 1);
                sE[r * SEP + c] = acc[mi][ni][e] * sdegE[r];
            }
    #pragma unroll
    for (int mi = 0; mi < 3; mi++)
        #pragma unroll
        for (int ni = 0; ni < 2; ni++)
            #pragma unroll
            for (int e = 0; e < 4; e++) acc[mi][ni][e] = 0.f;
    __syncthreads();

    // ---- hop 1: Y = (H^T @ E) / deg_v ----
    for (int kc = 0; kc < 192; kc += 16) {
        float e0v = sE[(kc + kr) * SEP + c2];
        float e1v = sE[(kc + kr) * SEP + c2 + 1];
        hilo(e0v, sB[kr * BP3 + c2],     sB[16 * BP3 + kr * BP3 + c2]);
        hilo(e1v, sB[kr * BP3 + c2 + 1], sB[16 * BP3 + kr * BP3 + c2 + 1]);
        __syncthreads();
        #pragma unroll
        for (int k0 = 0; k0 < 16; k0 += 8) {
            unsigned af[3][4], bh[2][2], bl[2][2];
            int kk  = kc + k0 + tq;       // edge index
            int kk2 = kk + 4;
            #pragma unroll
            for (int mi = 0; mi < 3; mi++) {
                int nrow = wy * 48 + mi * 16 + gq;    // node index
                int nw = nrow >> 5, nb = nrow & 31;   // nrow and nrow+8 share a word
                unsigned w0 = sHw[kk * 6 + nw];
                unsigned w1 = sHw[kk2 * 6 + nw];
                af[mi][0] = ((w0 >> nb) & 1u)       ? FONE : 0u;
                af[mi][1] = ((w0 >> (nb + 8)) & 1u) ? FONE : 0u;
                af[mi][2] = ((w1 >> nb) & 1u)       ? FONE : 0u;
                af[mi][3] = ((w1 >> (nb + 8)) & 1u) ? FONE : 0u;
            }
            #pragma unroll
            for (int ni = 0; ni < 2; ni++) {
                int c0 = wx * 16 + ni * 8;
                bh[ni][0] = sB[(k0 + tq) * BP3 + c0 + gq];
                bh[ni][1] = sB[(k0 + tq + 4) * BP3 + c0 + gq];
                bl[ni][0] = sB[16 * BP3 + (k0 + tq) * BP3 + c0 + gq];
                bl[ni][1] = sB[16 * BP3 + (k0 + tq + 4) * BP3 + c0 + gq];
            }
            #pragma unroll
            for (int mi = 0; mi < 3; mi++)
                #pragma unroll
                for (int ni = 0; ni < 2; ni++) {
                    mma8(acc[mi][ni], af[mi], bh[ni]);
                    mma8(acc[mi][ni], af[mi], bl[ni]);
                }
        }
        __syncthreads();
    }
    #pragma unroll
    for (int mi = 0; mi < 3; mi++)
        #pragma unroll
        for (int ni = 0; ni < 2; ni++)
            #pragma unroll
            for (int e = 0; e < 4; e++) {
                int r = wy * 48 + mi * 16 + gq + (e >> 1) * 8;
                int c = n0 + wx * 16 + ni * 8 + 2 * tq + (e & 1);
                g_Y[(size_t)(d * M + r) * G + c] = acc[mi][ni][e] * sdegV[r];
            }
}

// ---------------- K6: out = relu(Y @ W_h + b_h) (tf32 mma), regrouped ----------------
__global__ void __launch_bounds__(256) k_out_mma(const float* Wh, const float* bh,
                                                 float* out) {
    __shared__ unsigned sA[128 * FAP];
    __shared__ unsigned sB[32 * FBP];
    int bn = blockIdx.x, bm = blockIdx.y;
    int tid = threadIdx.x, lane = tid & 31, warp = tid >> 5;
    int wy = warp >> 1, wx = warp & 1;
    int gq = lane >> 2, tq = lane & 3;

    float acc[2][8][4];
    #pragma unroll
    for (int mi = 0; mi < 2; mi++)
        #pragma unroll
        for (int ni = 0; ni < 8; ni++)
            #pragma unroll
            for (int e = 0; e < 4; e++) acc[mi][ni][e] = 0.f;

    for (int kc = 0; kc < G; kc += 32) {
        #pragma unroll
        for (int it = 0; it < 4; it++) {
            int idx = tid + it * 256;
            int r = idx >> 3, c = (idx & 7) * 4;
            float4 xv = *(const float4*)(g_Y + (size_t)(bm * 128 + r) * G + kc + c);
            sA[r * FAP + c]     = f2tf(xv.x);
            sA[r * FAP + c + 1] = f2tf(xv.y);
            sA[r * FAP + c + 2] = f2tf(xv.z);
            sA[r * FAP + c + 3] = f2tf(xv.w);
        }
        #pragma unroll
        for (int it = 0; it < 4; it++) {
            int idx = tid + it * 256;
            int kr = idx >> 5, n4 = (idx & 31) * 4;
            float4 wv = *(const float4*)(Wh + (size_t)(kc + kr) * G + bn * 128 + n4);
            sB[kr * FBP + n4]     = f2tf(wv.x);
            sB[kr * FBP + n4 + 1] = f2tf(wv.y);
            sB[kr * FBP + n4 + 2] = f2tf(wv.z);
            sB[kr * FBP + n4 + 3] = f2tf(wv.w);
        }
        __syncthreads();
        #pragma unroll
        for (int k0 = 0; k0 < 32; k0 += 8) {
            unsigned af[2][4], bf[8][2];
            #pragma unroll
            for (int mi = 0; mi < 2; mi++) {
                int row = wy * 32 + mi * 16;
                af[mi][0] = sA[(row + gq) * FAP + k0 + tq];
                af[mi][1] = sA[(row + gq + 8) * FAP + k0 + tq];
                af[mi][2] = sA[(row + gq) * FAP + k0 + tq + 4];
                af[mi][3] = sA[(row + gq + 8) * FAP + k0 + tq + 4];
            }
            #pragma unroll
            for (int ni = 0; ni < 8; ni++) {
                int c0 = wx * 64 + ni * 8;
                bf[ni][0] = sB[(k0 + tq) * FBP + c0 + gq];
                bf[ni][1] = sB[(k0 + tq + 4) * FBP + c0 + gq];
            }
            #pragma unroll
            for (int mi = 0; mi < 2; mi++)
                #pragma unroll
                for (int ni = 0; ni < 8; ni++)
                    mma8(acc[mi][ni], af[mi], bf[ni]);
        }
        __syncthreads();
    }
    #pragma unroll
    for (int mi = 0; mi < 2; mi++)
        #pragma unroll
        for (int ni = 0; ni < 8; ni++)
            #pragma unroll
            for (int e = 0; e < 4; e++) {
                int gn = bm * 128 + wy * 32 + mi * 16 + gq + (e >> 1) * 8;
                int gc = bn * 128 + wx * 64 + ni * 8 + 2 * tq + (e & 1);
                int dd = gn / M, n = gn % M, mod = n >> 6, ii = n & 63;
                out[(size_t)(dd * L + ii) * 768 + mod * 256 + gc] =
                    fmaxf(acc[mi][ni][e] + bh[gc], 0.f);
            }
}

// ---------------- K7: norms, diag sims, zero LSE accumulators, bf16 convert ----------------
__global__ void k_norm(const float* out) {
    int i = blockIdx.x;
    int tid = threadIdx.x;
    float tv = out[(size_t)i * 768 + tid];
    float av = out[(size_t)i * 768 + 256 + tid];
    float vv = out[(size_t)i * 768 + 512 + tid];
    float q[6] = { tv * tv, av * av, vv * vv, tv * av, tv * vv, av * vv };
    __shared__ float red[6][8];
    __shared__ float sinv[3];
    int lane = tid & 31, w = tid >> 5;
    #pragma unroll
    for (int o = 16; o; o >>= 1)
        #pragma unroll
        for (int k = 0; k < 6; k++) q[k] += __shfl_down_sync(0xffffffffu, q[k], o);
    if (lane == 0)
        #pragma unroll
        for (int k = 0; k < 6; k++) red[k][w] = q[k];
    __syncthreads();
    if (tid == 0) {
        float s[6];
        #pragma unroll
        for (int k = 0; k < 6; k++) {
            s[k] = 0.f;
            #pragma unroll
            for (int w2 = 0; w2 < 8; w2++) s[k] += red[k][w2];
        }
        float it = 1.f / (sqrtf(s[0]) + 1e-8f);
        float ia = 1.f / (sqrtf(s[1]) + 1e-8f);
        float iv = 1.f / (sqrtf(s[2]) + 1e-8f);
        sinv[0] = it * SQTAUI; sinv[1] = ia * SQTAUI; sinv[2] = iv * SQTAUI;
        g_diag[i]             = s[3] * it * ia * TAUINV;
        g_diag[NROWS + i]     = s[4] * it * iv * TAUINV;
        g_diag[2 * NROWS + i] = s[5] * ia * iv * TAUINV;
        g_rowsum[i] = 0.f; g_rowsum[NROWS + i] = 0.f; g_rowsum[2 * NROWS + i] = 0.f;
        g_colsum[i] = 0.f; g_colsum[NROWS + i] = 0.f; g_colsum[2 * NROWS + i] = 0.f;
    }
    __syncthreads();
    g_nb[((size_t)0 * NROWS + i) * G + tid] = __float2bfloat16(tv * sinv[0]);
    g_nb[((size_t)1 * NROWS + i) * G + tid] = __float2bfloat16(av * sinv[1]);
    g_nb[((size_t)2 * NROWS + i) * G + tid] = __float2bfloat16(vv * sinv[2]);
}

// ---------------- K8: bf16 tensor-core sim tiles, cp.async double-buffered ----------------
#define SPITCH 40
__global__ void __launch_bounds__(256) k_sim_mma() {
    int p = blockIdx.z;
    int mx = (p == 2) ? 1 : 0;
    int my = (p == 0) ? 1 : 2;
    int row0 = blockIdx.y * 128, col0 = blockIdx.x * 128;
    __shared__ __nv_bfloat16 sX[2][128 * SPITCH];
    __shared__ __nv_bfloat16 sY[2][128 * SPITCH];
    __shared__ float srow[128], scol[128];
    int tid = threadIdx.x, lane = tid & 31, warp = tid >> 5;
    int wy = warp >> 1, wx = warp & 1;      // warp tile: 32 rows x 64 cols

    const __nv_bfloat16* xg = g_nb + ((size_t)mx * NROWS + row0) * G;
    const __nv_bfloat16* yg = g_nb + ((size_t)my * NROWS + col0) * G;

    int lr = tid >> 2, lc = (tid & 3) * 8;
    int lr2 = lr + 64;

    float acc[2][8][4];
    #pragma unroll
    for (int mi = 0; mi < 2; mi++)
        #pragma unroll
        for (int ni = 0; ni < 8; ni++)
            #pragma unroll
            for (int r = 0; r < 4; r++) acc[mi][ni][r] = 0.f;

    cp16(&sX[0][lr * SPITCH + lc],  xg + (size_t)lr * G + lc);
    cp16(&sX[0][lr2 * SPITCH + lc], xg + (size_t)lr2 * G + lc);
    cp16(&sY[0][lr * SPITCH + lc],  yg + (size_t)lr * G + lc);
    cp16(&sY[0][lr2 * SPITCH + lc], yg + (size_t)lr2 * G + lc);
    cp_commit();

    #pragma unroll
    for (int c = 0; c < 8; c++) {
        int cur = c & 1;
        if (c < 7) {
            int nb = (c + 1) & 1, kc = (c + 1) * 32;
            cp16(&sX[nb][lr * SPITCH + lc],  xg + (size_t)lr * G + kc + lc);
            cp16(&sX[nb][lr2 * SPITCH + lc], xg + (size_t)lr2 * G + kc + lc);
            cp16(&sY[nb][lr * SPITCH + lc],  yg + (size_t)lr * G + kc + lc);
            cp16(&sY[nb][lr2 * SPITCH + lc], yg + (size_t)lr2 * G + kc + lc);
            cp_commit();
            asm volatile("cp.async.wait_group 1;");
        } else {
            asm volatile("cp.async.wait_group 0;");
        }
        __syncthreads();
        #pragma unroll
        for (int ks = 0; ks < 2; ks++) {
            int k0 = ks * 16;
            unsigned A[2][4];
            #pragma unroll
            for (int mi = 0; mi < 2; mi++) {
                int r = wy * 32 + mi * 16 + ((lane >> 3) & 1) * 8 + (lane & 7);
                int cc = k0 + (lane >> 4) * 8;
                unsigned ad = (unsigned)__cvta_generic_to_shared(&sX[cur][r * SPITCH + cc]);
                asm volatile("ldmatrix.sync.aligned.m8n8.x4.shared.b16 {%0,%1,%2,%3},[%4];"
                    : "=r"(A[mi][0]), "=r"(A[mi][1]), "=r"(A[mi][2]), "=r"(A[mi][3])
                    : "r"(ad));
            }
            unsigned B[8][2];
            #pragma unroll
            for (int nb2 = 0; nb2 < 4; nb2++) {
                int r = wx * 64 + nb2 * 16 + (lane >> 4) * 8 + (lane & 7);
                int cc = k0 + ((lane >> 3) & 1) * 8;
                unsigned ad = (unsigned)__cvta_generic_to_shared(&sY[cur][r * SPITCH + cc]);
                asm volatile("ldmatrix.sync.aligned.m8n8.x4.shared.b16 {%0,%1,%2,%3},[%4];"
                    : "=r"(B[2 * nb2][0]), "=r"(B[2 * nb2][1]),
                      "=r"(B[2 * nb2 + 1][0]), "=r"(B[2 * nb2 + 1][1])
                    : "r"(ad));
            }
            #pragma unroll
            for (int mi = 0; mi < 2; mi++)
                #pragma unroll
                for (int ni = 0; ni < 8; ni++)
                    asm volatile(
                        "mma.sync.aligned.m16n8k16.row.col.f32.bf16.bf16.f32 "
                        "{%0,%1,%2,%3},{%4,%5,%6,%7},{%8,%9},{%0,%1,%2,%3};"
                        : "+f"(acc[mi][ni][0]), "+f"(acc[mi][ni][1]),
                          "+f"(acc[mi][ni][2]), "+f"(acc[mi][ni][3])
                        : "r"(A[mi][0]), "r"(A[mi][1]), "r"(A[mi][2]), "r"(A[mi][3]),
                          "r"(B[ni][0]), "r"(B[ni][1]));
        }
        __syncthreads();
    }

    if (tid < 128) { srow[tid] = 0.f; scol[tid] = 0.f; }
    __syncthreads();

    float rowp[2][2] = {{0.f, 0.f}, {0.f, 0.f}};
    float colp[8][2];
    #pragma unroll
    for (int ni = 0; ni < 8; ni++) { colp[ni][0] = 0.f; colp[ni][1] = 0.f; }
    #pragma unroll
    for (int mi = 0; mi < 2; mi++)
        #pragma unroll
        for (int ni = 0; ni < 8; ni++)
            #pragma unroll
            for (int r = 0; r < 4; r++) {
                float e = __expf(acc[mi][ni][r]);
                rowp[mi][r >> 1] += e;
                colp[ni][r & 1] += e;
            }

    #pragma unroll
    for (int mi = 0; mi < 2; mi++)
        #pragma unroll
        for (int h = 0; h < 2; h++) {
            float vv = rowp[mi][h];
            vv += __shfl_xor_sync(0xffffffffu, vv, 1);
            vv += __shfl_xor_sync(0xffffffffu, vv, 2);
            if ((lane & 3) == 0)
                atomicAdd(&srow[wy * 32 + mi * 16 + (lane >> 2) + h * 8], vv);
        }
    #pragma unroll
    for (int ni = 0; ni < 8; ni++)
        #pragma unroll
        for (int s2 = 0; s2 < 2; s2++) {
            float vv = colp[ni][s2];
            vv += __shfl_xor_sync(0xffffffffu, vv, 4);
            vv += __shfl_xor_sync(0xffffffffu, vv, 8);
            vv += __shfl_xor_sync(0xffffffffu, vv, 16);
            if (lane < 4)
                atomicAdd(&scol[wx * 64 + ni * 8 + lane * 2 + s2], vv);
        }
    __syncthreads();
    if (tid < 128) {
        atomicAdd(&g_rowsum[p * NROWS + row0 + tid], srow[tid]);
        atomicAdd(&g_colsum[p * NROWS + col0 + tid], scol[tid]);
    }
}

// ---------------- K9: final loss reduction ----------------
__global__ void k_loss(float* out, int out_size) {
    int tid = threadIdx.x;
    float s = 0.f;
    for (int idx = tid; idx < 3 * NROWS; idx += 256) {
        float dg = g_diag[idx];
        s += 2.f * dg - logf(g_rowsum[idx]) - logf(g_colsum[idx]);
    }
    __shared__ float red[8];
    int lane = tid & 31, w = tid >> 5;
    #pragma unroll
    for (int o = 16; o; o >>= 1) s += __shfl_down_sync(0xffffffffu, s, o);
    if (lane == 0) red[w] = s;
    __syncthreads();
    if (tid == 0) {
        float tot = 0.f;
        #pragma unroll
        for (int w2 = 0; w2 < 8; w2++) tot += red[w2];
        float loss = -tot / (2.f * 3.f * (float)NROWS);
        if (out_size > NROWS * 768) out[NROWS * 768] = loss;
    }
}

// ---------------- launcher ----------------
extern "C" void kernel_launch(void* const* d_in, const int* in_sizes, int n_in,
                              void* d_out, int out_size) {
    const float* t   = (const float*)d_in[0];
    const float* a   = (const float*)d_in[1];
    const float* v   = (const float*)d_in[2];
    const float* Wfc = (const float*)d_in[3];
    const float* bfc = (const float*)d_in[4];
    const float* Wh  = (const float*)d_in[5];
    const float* bh  = (const float*)d_in[6];
    float* out = (float*)d_out;

    k_sq<<<NNODE / 8, 256>>>(t, a, v);
    k_gram_mma<<<dim3(6, 64), 256>>>();
    k_fc_mma<<<dim3(2, 96), 256>>>(Wfc, bfc);
    k_agg_f<<<dim3(8, 64), 256>>>();
    k_out_mma<<<dim3(2, 96), 256>>>(Wh, bh, out);
    k_norm<<<NROWS, 256>>>(out);
    k_sim_mma<<<dim3(32, 32, 3), 256>>>();
    k_loss<<<1, 256>>>(out, out_size);
}

// round 10
// speedup vs baseline: 5.9155x; 1.0040x over previous
#include <cuda_runtime.h>
#include <cuda_bf16.h>
#include <math.h>
#include <float.h>

#define D 64
#define L 64
#define DIMF 512
#define G 256
#define M 192                 // 3*L nodes (= hyperedges) per dialogue
#define KTOP 12
#define NROWS 4096            // D*L
#define NNODE (D*M)           // 12288
#define TAUINV (1.0f/0.07f)
#define SQTAUI 3.7796447300922722f   // sqrt(1/0.07)

// ---- scratch (static device arrays; no allocation allowed) ----
__device__ float    g_sq[NNODE];
__device__ unsigned g_fh[(size_t)NNODE*DIMF];   // tf32 hi of features
__device__ unsigned g_fl[(size_t)NNODE*DIMF];   // tf32 lo of features
__device__ unsigned g_H[NNODE*6];       // 192-bit incidence mask per edge
__device__ float    g_X[NNODE*G];
__device__ float    g_Y[NNODE*G];
__device__ float    g_diag[3*NROWS];
__device__ float    g_rowsum[3*NROWS];
__device__ float    g_colsum[3*NROWS];
__device__ __nv_bfloat16 g_nb[(size_t)3*NROWS*G];   // normalized bf16 features (loss path only)

__device__ __forceinline__ const float* feat_row(int d, int n,
        const float* t, const float* a, const float* v) {
    int mod = n >> 6, i = n & 63;
    const float* base = (mod == 0) ? t : (mod == 1) ? a : v;
    return base + (size_t)(d * L + i) * DIMF;
}

// ---- tf32 helpers ----
__device__ __forceinline__ unsigned f2tf(float x) {
    unsigned u; asm("cvt.rna.tf32.f32 %0, %1;" : "=r"(u) : "f"(x)); return u;
}
__device__ __forceinline__ void hilo(float x, unsigned& h, unsigned& l) {
    h = f2tf(x);
    l = f2tf(x - __uint_as_float(h));
}
__device__ __forceinline__ void mma8(float* c, const unsigned* a, const unsigned* b) {
    asm volatile("mma.sync.aligned.m16n8k8.row.col.f32.tf32.tf32.f32 "
        "{%0,%1,%2,%3},{%4,%5,%6,%7},{%8,%9},{%0,%1,%2,%3};"
        : "+f"(c[0]), "+f"(c[1]), "+f"(c[2]), "+f"(c[3])
        : "r"(a[0]), "r"(a[1]), "r"(a[2]), "r"(a[3]), "r"(b[0]), "r"(b[1]));
}

// ---- cp.async helpers ----
__device__ __forceinline__ void cp16(void* dst_smem, const void* src) {
    unsigned ad = (unsigned)__cvta_generic_to_shared(dst_smem);
    asm volatile("cp.async.cg.shared.global [%0],[%1],16;" :: "r"(ad), "l"(src));
}
__device__ __forceinline__ void cp_commit() {
    asm volatile("cp.async.commit_group;");
}

// ---------------- K1: per-node squared norms + hi/lo precompute ----------------
__global__ void k_sq(const float* t, const float* a, const float* v) {
    int warp = (blockIdx.x * blockDim.x + threadIdx.x) >> 5;
    int lane = threadIdx.x & 31;
    if (warp >= NNODE) return;
    int d = warp / M, n = warp % M;
    const float* r = feat_row(d, n, t, a, v);
    float s = 0.f;
    #pragma unroll
    for (int c = lane; c < DIMF; c += 32) { float x = r[c]; s += x * x; }
    unsigned* fh = g_fh + (size_t)warp * DIMF;
    unsigned* fl = g_fl + (size_t)warp * DIMF;
    #pragma unroll
    for (int c0 = lane * 4; c0 < DIMF; c0 += 128) {
        float4 x = *(const float4*)(r + c0);
        uint4 h, l;
        hilo(x.x, h.x, l.x); hilo(x.y, h.y, l.y);
        hilo(x.z, h.z, l.z); hilo(x.w, h.w, l.w);
        *(uint4*)(fh + c0) = h;
        *(uint4*)(fl + c0) = l;
    }
    #pragma unroll
    for (int o = 16; o; o >>= 1) s += __shfl_down_sync(0xffffffffu, s, o);
    if (lane == 0) g_sq[warp] = s;
}

// ---------------- K2: 3xTF32 gram + d2 + top-12 + incidence masks ----------------
#define GBP2 20
__global__ void __launch_bounds__(256) k_gram_mma() {
    __shared__ unsigned Bbuf[2 * 192 * GBP2];        // hi | lo ; reused as d2 [32][192]
    __shared__ float sq[M];
    unsigned* Bhi = Bbuf;
    unsigned* Blo = Bbuf + 192 * GBP2;

    int d = blockIdx.y, i0 = blockIdx.x * 32;
    int tid = threadIdx.x, lane = tid & 31, warp = tid >> 5;
    int gq = lane >> 2, tq = lane & 3;
    if (tid < M) sq[tid] = g_sq[d * M + tid];
    size_t base = (size_t)(d * M) * DIMF;

    float acc[2][3][4];
    #pragma unroll
    for (int mi = 0; mi < 2; mi++)
        #pragma unroll
        for (int ni = 0; ni < 3; ni++)
            #pragma unroll
            for (int e = 0; e < 4; e++) acc[mi][ni][e] = 0.f;

    for (int kc = 0; kc < DIMF; kc += 16) {
        #pragma unroll
        for (int it = 0; it < 3; it++) {
            int idx = tid + it * 256;              // 0..767
            int n = idx >> 2, k4 = (idx & 3) * 4;
            cp16(Bhi + n * GBP2 + k4, g_fh + base + (size_t)n * DIMF + kc + k4);
            cp16(Blo + n * GBP2 + k4, g_fl + base + (size_t)n * DIMF + kc + k4);
        }
        cp_commit();
        asm volatile("cp.async.wait_group 0;");
        __syncthreads();
        #pragma unroll
        for (int k0 = 0; k0 < 16; k0 += 8) {
            unsigned ah[2][4], al[2][4], bh[3][2], bl[3][2];
            #pragma unroll
            for (int mi = 0; mi < 2; mi++) {
                int r0 = (i0 + mi * 16 + gq) * GBP2;
                int r1 = r0 + 8 * GBP2;
                ah[mi][0] = Bhi[r0 + k0 + tq];
                ah[mi][1] = Bhi[r1 + k0 + tq];
                ah[mi][2] = Bhi[r0 + k0 + tq + 4];
                ah[mi][3] = Bhi[r1 + k0 + tq + 4];
                al[mi][0] = Blo[r0 + k0 + tq];
                al[mi][1] = Blo[r1 + k0 + tq];
                al[mi][2] = Blo[r0 + k0 + tq + 4];
                al[mi][3] = Blo[r1 + k0 + tq + 4];
            }
            #pragma unroll
            for (int ni = 0; ni < 3; ni++) {
                int c0 = (warp * 24 + ni * 8 + gq) * GBP2;
                bh[ni][0] = Bhi[c0 + k0 + tq];
                bh[ni][1] = Bhi[c0 + k0 + tq + 4];
                bl[ni][0] = Blo[c0 + k0 + tq];
                bl[ni][1] = Blo[c0 + k0 + tq + 4];
            }
            #pragma unroll
            for (int mi = 0; mi < 2; mi++)
                #pragma unroll
                for (int ni = 0; ni < 3; ni++) {
                    mma8(acc[mi][ni], ah[mi], bh[ni]);
                    mma8(acc[mi][ni], ah[mi], bl[ni]);
                    mma8(acc[mi][ni], al[mi], bh[ni]);
                }
        }
        __syncthreads();
    }

    float* d2s = (float*)Bbuf;
    #pragma unroll
    for (int mi = 0; mi < 2; mi++)
        #pragma unroll
        for (int ni = 0; ni < 3; ni++)
            #pragma unroll
            for (int e = 0; e < 4; e++) {
                int r = mi * 16 + gq + (e >> 1) * 8;
                int c = warp * 24 + ni * 8 + 2 * tq + (e & 1);
                float v2 = sq[i0 + r] + sq[c] - 2.f * acc[mi][ni][e];
                d2s[r * 192 + c] = fmaxf(v2, 0.f);
            }
    __syncthreads();

    int tx = lane;
    for (int q = 0; q < 4; q++) {
        int r = warp * 4 + q;
        float val[6];
        #pragma unroll
        for (int s = 0; s < 6; s++) val[s] = d2s[r * 192 + tx + 32 * s];
        unsigned mask[6] = {0, 0, 0, 0, 0, 0};
        for (int pick = 0; pick < KTOP; pick++) {
            float bv = val[0]; int bi = tx;
            #pragma unroll
            for (int s = 1; s < 6; s++) {
                float vv = val[s];
                if (vv < bv) { bv = vv; bi = tx + 32 * s; }
            }
            #pragma unroll
            for (int o = 16; o; o >>= 1) {
                float ov = __shfl_down_sync(0xffffffffu, bv, o);
                int   oi = __shfl_down_sync(0xffffffffu, bi, o);
                if (ov < bv || (ov == bv && oi < bi)) { bv = ov; bi = oi; }
            }
            bi = __shfl_sync(0xffffffffu, bi, 0);
            if ((bi & 31) == tx) val[bi >> 5] = FLT_MAX;
            mask[bi >> 5] |= 1u << (bi & 31);
        }
        if (tx == 0) {
            int e = i0 + r;
            int u = e / 3;
            mask[u >> 5]           |= 1u << (u & 31);
            mask[(u + 64) >> 5]    |= 1u << ((u + 64) & 31);
            mask[(u + 128) >> 5]   |= 1u << ((u + 128) & 31);
            #pragma unroll
            for (int w = 0; w < 6; w++)
                g_H[(size_t)(d * M + e) * 6 + w] = mask[w];
        }
    }
}

// ---------------- K3: X = feat @ W_fc + b_fc  (tf32 mma, 128x128 tile) ----------------
#define FAP 36
#define FBP 136
__global__ void __launch_bounds__(256) k_fc_mma(const float* Wfc, const float* bfc) {
    __shared__ unsigned sA[128 * FAP];
    __shared__ unsigned sB[32 * FBP];
    int bn = blockIdx.x, bm = blockIdx.y;
    int tid = threadIdx.x, lane = tid & 31, warp = tid >> 5;
    int wy = warp >> 1, wx = warp & 1;
    int gq = lane >> 2, tq = lane & 3;

    float acc[2][8][4];
    #pragma unroll
    for (int mi = 0; mi < 2; mi++)
        #pragma unroll
        for (int ni = 0; ni < 8; ni++)
            #pragma unroll
            for (int e = 0; e < 4; e++) acc[mi][ni][e] = 0.f;

    for (int kc = 0; kc < DIMF; kc += 32) {
        #pragma unroll
        for (int it = 0; it < 4; it++) {
            int idx = tid + it * 256;
            int r = idx >> 3, c = (idx & 7) * 4;
            cp16(sA + r * FAP + c, g_fh + (size_t)(bm * 128 + r) * DIMF + kc + c);
        }
        cp_commit();
        #pragma unroll
        for (int it = 0; it < 4; it++) {
            int idx = tid + it * 256;
            int kr = idx >> 5, n4 = (idx & 31) * 4;
            float4 wv = *(const float4*)(Wfc + (size_t)(kc + kr) * G + bn * 128 + n4);
            sB[kr * FBP + n4]     = f2tf(wv.x);
            sB[kr * FBP + n4 + 1] = f2tf(wv.y);
            sB[kr * FBP + n4 + 2] = f2tf(wv.z);
            sB[kr * FBP + n4 + 3] = f2tf(wv.w);
        }
        asm volatile("cp.async.wait_group 0;");
        __syncthreads();
        #pragma unroll
        for (int k0 = 0; k0 < 32; k0 += 8) {
            unsigned af[2][4], bf[8][2];
            #pragma unroll
            for (int mi = 0; mi < 2; mi++) {
                int row = wy * 32 + mi * 16;
                af[mi][0] = sA[(row + gq) * FAP + k0 + tq];
                af[mi][1] = sA[(row + gq + 8) * FAP + k0 + tq];
                af[mi][2] = sA[(row + gq) * FAP + k0 + tq + 4];
                af[mi][3] = sA[(row + gq + 8) * FAP + k0 + tq + 4];
            }
            #pragma unroll
            for (int ni = 0; ni < 8; ni++) {
                int c0 = wx * 64 + ni * 8;
                bf[ni][0] = sB[(k0 + tq) * FBP + c0 + gq];
                bf[ni][1] = sB[(k0 + tq + 4) * FBP + c0 + gq];
            }
            #pragma unroll
            for (int mi = 0; mi < 2; mi++)
                #pragma unroll
                for (int ni = 0; ni < 8; ni++)
                    mma8(acc[mi][ni], af[mi], bf[ni]);
        }
        __syncthreads();
    }
    #pragma unroll
    for (int mi = 0; mi < 2; mi++)
        #pragma unroll
        for (int ni = 0; ni < 8; ni++)
            #pragma unroll
            for (int e = 0; e < 4; e++) {
                int r  = bm * 128 + wy * 32 + mi * 16 + gq + (e >> 1) * 8;
                int cc = bn * 128 + wx * 64 + ni * 8 + 2 * tq + (e & 1);
                g_X[(size_t)r * G + cc] = acc[mi][ni][e] + bfc[cc];
            }
}

// ---------------- K4: fused hypergraph hops  Y = H^T ((H X)/deg_e) / deg_v ----------------
// sHT = bit-transposed incidence (node-major), built via warp 32x32 bit transpose.
#define BP3 40     // B pitch (32 + 8)
#define SEP 33     // E tile pitch
#define FONE 0x3F800000u
__global__ void __launch_bounds__(256) k_agg_f() {
    __shared__ unsigned sHw[192 * 6];   // [edge][node-word]
    __shared__ unsigned sHT[192 * 6];   // [node][edge-word]
    __shared__ float    sdegE[192], sdegV[192];
    __shared__ unsigned sB[2 * 16 * BP3];     // hi | lo
    __shared__ float    sE[192 * SEP];
    int d = blockIdx.y, n0 = blockIdx.x * 32;
    int tid = threadIdx.x, lane = tid & 31, warp = tid >> 5;
    int wy = warp >> 1, wx = warp & 1;        // wy: 48 rows, wx: 16 cols
    int gq = lane >> 2, tq = lane & 3;

    for (int i = tid; i < 192 * 6; i += 256) sHw[i] = g_H[(size_t)(d * M) * 6 + i];
    __syncthreads();

    // 32x32 bit-transpose blocks: 6x6 blocks over 8 warps
    for (int blk = warp; blk < 36; blk += 8) {
        int eb = blk / 6, nb = blk % 6;
        unsigned x = sHw[(eb * 32 + lane) * 6 + nb];
        #pragma unroll
        for (int i = 16; i >= 1; i >>= 1) {
            unsigned m = 0xFFFFFFFFu / ((1u << i) + 1u);
            unsigned y = __shfl_xor_sync(0xffffffffu, x, i);
            x = (lane & i) ? (((y >> i) & m) | (x & ~m))
                           : ((x & m) | ((y & m) << i));
        }
        sHT[(nb * 32 + lane) * 6 + eb] = x;
    }
    __syncthreads();

    if (tid < 192) {
        int dege = 0, degv = 0;
        #pragma unroll
        for (int w = 0; w < 6; w++) {
            dege += __popc(sHw[tid * 6 + w]);
            degv += __popc(sHT[tid * 6 + w]);
        }
        sdegE[tid] = 1.f / (float)dege;
        sdegV[tid] = 1.f / (float)degv;
    }

    float acc[3][2][4];
    #pragma unroll
    for (int mi = 0; mi < 3; mi++)
        #pragma unroll
        for (int ni = 0; ni < 2; ni++)
            #pragma unroll
            for (int e = 0; e < 4; e++) acc[mi][ni][e] = 0.f;

    int kr = tid >> 4, c2 = (tid & 15) * 2;   // 16 rows x 32 cols, float2/thread
    float2 nxt = *(const float2*)(g_X + (size_t)(d * M + kr) * G + n0 + c2);

    // ---- hop 0: E = (H @ X) / deg_e ----
    for (int kc = 0; kc < 192; kc += 16) {
        hilo(nxt.x, sB[kr * BP3 + c2],     sB[16 * BP3 + kr * BP3 + c2]);
        hilo(nxt.y, sB[kr * BP3 + c2 + 1], sB[16 * BP3 + kr * BP3 + c2 + 1]);
        __syncthreads();
        if (kc + 16 < 192)
            nxt = *(const float2*)(g_X + (size_t)(d * M + kc + 16 + kr) * G + n0 + c2);
        int kw = kc >> 5, sh = kc & 31;
        unsigned hw0[3], hw1[3];
        #pragma unroll
        for (int mi = 0; mi < 3; mi++) {
            int e0 = wy * 48 + mi * 16 + gq;
            hw0[mi] = sHw[e0 * 6 + kw];
            hw1[mi] = sHw[(e0 + 8) * 6 + kw];
        }
        #pragma unroll
        for (int k0 = 0; k0 < 16; k0 += 8) {
            unsigned af[3][4], bh[2][2], bl[2][2];
            int b0 = sh + k0 + tq;
            #pragma unroll
            for (int mi = 0; mi < 3; mi++) {
                af[mi][0] = ((hw0[mi] >> b0) & 1u)       ? FONE : 0u;
                af[mi][1] = ((hw1[mi] >> b0) & 1u)       ? FONE : 0u;
                af[mi][2] = ((hw0[mi] >> (b0 + 4)) & 1u) ? FONE : 0u;
                af[mi][3] = ((hw1[mi] >> (b0 + 4)) & 1u) ? FONE : 0u;
            }
            #pragma unroll
            for (int ni = 0; ni < 2; ni++) {
                int c0 = wx * 16 + ni * 8;
                bh[ni][0] = sB[(k0 + tq) * BP3 + c0 + gq];
                bh[ni][1] = sB[(k0 + tq + 4) * BP3 + c0 + gq];
                bl[ni][0] = sB[16 * BP3 + (k0 + tq) * BP3 + c0 + gq];
                bl[ni][1] = sB[16 * BP3 + (k0 + tq + 4) * BP3 + c0 + gq];
            }
            #pragma unroll
            for (int mi = 0; mi < 3; mi++)
                #pragma unroll
                for (int ni = 0; ni < 2; ni++) {
                    mma8(acc[mi][ni], af[mi], bh[ni]);
                    mma8(acc[mi][ni], af[mi], bl[ni]);
                }
        }
        __syncthreads();
    }
    #pragma unroll
    for (int mi = 0; mi < 3; mi++)
        #pragma unroll
        for (int ni = 0; ni < 2; ni++)
            #pragma unroll
            for (int e = 0; e < 4; e++) {
                int r = wy * 48 + mi * 16 + gq + (e >> 1) * 8;
                int c = wx * 16 + ni * 8 + 2 * tq + (e & 1);
                sE[r * SEP + c] = acc[mi][ni][e] * sdegE[r];
            }
    #pragma unroll
    for (int mi = 0; mi < 3; mi++)
        #pragma unroll
        for (int ni = 0; ni < 2; ni++)
            #pragma unroll
            for (int e = 0; e < 4; e++) acc[mi][ni][e] = 0.f;
    __syncthreads();

    // ---- hop 1: Y = (H^T @ E) / deg_v  (A bits from node-major sHT) ----
    for (int kc = 0; kc < 192; kc += 16) {
        float e0v = sE[(kc + kr) * SEP + c2];
        float e1v = sE[(kc + kr) * SEP + c2 + 1];
        hilo(e0v, sB[kr * BP3 + c2],     sB[16 * BP3 + kr * BP3 + c2]);
        hilo(e1v, sB[kr * BP3 + c2 + 1], sB[16 * BP3 + kr * BP3 + c2 + 1]);
        __syncthreads();
        int kw = kc >> 5, sh = kc & 31;
        unsigned ht0[3], ht1[3];
        #pragma unroll
        for (int mi = 0; mi < 3; mi++) {
            int nrow = wy * 48 + mi * 16 + gq;
            ht0[mi] = sHT[nrow * 6 + kw];
            ht1[mi] = sHT[(nrow + 8) * 6 + kw];
        }
        #pragma unroll
        for (int k0 = 0; k0 < 16; k0 += 8) {
            unsigned af[3][4], bh[2][2], bl[2][2];
            int b0 = sh + k0 + tq;
            #pragma unroll
            for (int mi = 0; mi < 3; mi++) {
                af[mi][0] = ((ht0[mi] >> b0) & 1u)       ? FONE : 0u;
                af[mi][1] = ((ht1[mi] >> b0) & 1u)       ? FONE : 0u;
                af[mi][2] = ((ht0[mi] >> (b0 + 4)) & 1u) ? FONE : 0u;
                af[mi][3] = ((ht1[mi] >> (b0 + 4)) & 1u) ? FONE : 0u;
            }
            #pragma unroll
            for (int ni = 0; ni < 2; ni++) {
                int c0 = wx * 16 + ni * 8;
                bh[ni][0] = sB[(k0 + tq) * BP3 + c0 + gq];
                bh[ni][1] = sB[(k0 + tq + 4) * BP3 + c0 + gq];
                bl[ni][0] = sB[16 * BP3 + (k0 + tq) * BP3 + c0 + gq];
                bl[ni][1] = sB[16 * BP3 + (k0 + tq + 4) * BP3 + c0 + gq];
            }
            #pragma unroll
            for (int mi = 0; mi < 3; mi++)
                #pragma unroll
                for (int ni = 0; ni < 2; ni++) {
                    mma8(acc[mi][ni], af[mi], bh[ni]);
                    mma8(acc[mi][ni], af[mi], bl[ni]);
                }
        }
        __syncthreads();
    }
    #pragma unroll
    for (int mi = 0; mi < 3; mi++)
        #pragma unroll
        for (int ni = 0; ni < 2; ni++)
            #pragma unroll
            for (int e = 0; e < 4; e++) {
                int r = wy * 48 + mi * 16 + gq + (e >> 1) * 8;
                int c = n0 + wx * 16 + ni * 8 + 2 * tq + (e & 1);
                g_Y[(size_t)(d * M + r) * G + c] = acc[mi][ni][e] * sdegV[r];
            }
}

// ---------------- K6: out = relu(Y @ W_h + b_h) (tf32 mma), regrouped ----------------
__global__ void __launch_bounds__(256) k_out_mma(const float* Wh, const float* bh,
                                                 float* out) {
    __shared__ unsigned sA[128 * FAP];
    __shared__ unsigned sB[32 * FBP];
    int bn = blockIdx.x, bm = blockIdx.y;
    int tid = threadIdx.x, lane = tid & 31, warp = tid >> 5;
    int wy = warp >> 1, wx = warp & 1;
    int gq = lane >> 2, tq = lane & 3;

    float acc[2][8][4];
    #pragma unroll
    for (int mi = 0; mi < 2; mi++)
        #pragma unroll
        for (int ni = 0; ni < 8; ni++)
            #pragma unroll
            for (int e = 0; e < 4; e++) acc[mi][ni][e] = 0.f;

    for (int kc = 0; kc < G; kc += 32) {
        #pragma unroll
        for (int it = 0; it < 4; it++) {
            int idx = tid + it * 256;
            int r = idx >> 3, c = (idx & 7) * 4;
            float4 xv = *(const float4*)(g_Y + (size_t)(bm * 128 + r) * G + kc + c);
            sA[r * FAP + c]     = f2tf(xv.x);
            sA[r * FAP + c + 1] = f2tf(xv.y);
            sA[r * FAP + c + 2] = f2tf(xv.z);
            sA[r * FAP + c + 3] = f2tf(xv.w);
        }
        #pragma unroll
        for (int it = 0; it < 4; it++) {
            int idx = tid + it * 256;
            int kr = idx >> 5, n4 = (idx & 31) * 4;
            float4 wv = *(const float4*)(Wh + (size_t)(kc + kr) * G + bn * 128 + n4);
            sB[kr * FBP + n4]     = f2tf(wv.x);
            sB[kr * FBP + n4 + 1] = f2tf(wv.y);
            sB[kr * FBP + n4 + 2] = f2tf(wv.z);
            sB[kr * FBP + n4 + 3] = f2tf(wv.w);
        }
        __syncthreads();
        #pragma unroll
        for (int k0 = 0; k0 < 32; k0 += 8) {
            unsigned af[2][4], bf[8][2];
            #pragma unroll
            for (int mi = 0; mi < 2; mi++) {
                int row = wy * 32 + mi * 16;
                af[mi][0] = sA[(row + gq) * FAP + k0 + tq];
                af[mi][1] = sA[(row + gq + 8) * FAP + k0 + tq];
                af[mi][2] = sA[(row + gq) * FAP + k0 + tq + 4];
                af[mi][3] = sA[(row + gq + 8) * FAP + k0 + tq + 4];
            }
            #pragma unroll
            for (int ni = 0; ni < 8; ni++) {
                int c0 = wx * 64 + ni * 8;
                bf[ni][0] = sB[(k0 + tq) * FBP + c0 + gq];
                bf[ni][1] = sB[(k0 + tq + 4) * FBP + c0 + gq];
            }
            #pragma unroll
            for (int mi = 0; mi < 2; mi++)
                #pragma unroll
                for (int ni = 0; ni < 8; ni++)
                    mma8(acc[mi][ni], af[mi], bf[ni]);
        }
        __syncthreads();
    }
    #pragma unroll
    for (int mi = 0; mi < 2; mi++)
        #pragma unroll
        for (int ni = 0; ni < 8; ni++)
            #pragma unroll
            for (int e = 0; e < 4; e++) {
                int gn = bm * 128 + wy * 32 + mi * 16 + gq + (e >> 1) * 8;
                int gc = bn * 128 + wx * 64 + ni * 8 + 2 * tq + (e & 1);
                int dd = gn / M, n = gn % M, mod = n >> 6, ii = n & 63;
                out[(size_t)(dd * L + ii) * 768 + mod * 256 + gc] =
                    fmaxf(acc[mi][ni][e] + bh[gc], 0.f);
            }
}

// ---------------- K7: norms, diag sims, zero LSE accumulators, bf16 convert ----------------
__global__ void k_norm(const float* out) {
    int i = blockIdx.x;
    int tid = threadIdx.x;
    float tv = out[(size_t)i * 768 + tid];
    float av = out[(size_t)i * 768 + 256 + tid];
    float vv = out[(size_t)i * 768 + 512 + tid];
    float q[6] = { tv * tv, av * av, vv * vv, tv * av, tv * vv, av * vv };
    __shared__ float red[6][8];
    __shared__ float sinv[3];
    int lane = tid & 31, w = tid >> 5;
    #pragma unroll
    for (int o = 16; o; o >>= 1)
        #pragma unroll
        for (int k = 0; k < 6; k++) q[k] += __shfl_down_sync(0xffffffffu, q[k], o);
    if (lane == 0)
        #pragma unroll
        for (int k = 0; k < 6; k++) red[k][w] = q[k];
    __syncthreads();
    if (tid == 0) {
        float s[6];
        #pragma unroll
        for (int k = 0; k < 6; k++) {
            s[k] = 0.f;
            #pragma unroll
            for (int w2 = 0; w2 < 8; w2++) s[k] += red[k][w2];
        }
        float it = 1.f / (sqrtf(s[0]) + 1e-8f);
        float ia = 1.f / (sqrtf(s[1]) + 1e-8f);
        float iv = 1.f / (sqrtf(s[2]) + 1e-8f);
        sinv[0] = it * SQTAUI; sinv[1] = ia * SQTAUI; sinv[2] = iv * SQTAUI;
        g_diag[i]             = s[3] * it * ia * TAUINV;
        g_diag[NROWS + i]     = s[4] * it * iv * TAUINV;
        g_diag[2 * NROWS + i] = s[5] * ia * iv * TAUINV;
        g_rowsum[i] = 0.f; g_rowsum[NROWS + i] = 0.f; g_rowsum[2 * NROWS + i] = 0.f;
        g_colsum[i] = 0.f; g_colsum[NROWS + i] = 0.f; g_colsum[2 * NROWS + i] = 0.f;
    }
    __syncthreads();
    g_nb[((size_t)0 * NROWS + i) * G + tid] = __float2bfloat16(tv * sinv[0]);
    g_nb[((size_t)1 * NROWS + i) * G + tid] = __float2bfloat16(av * sinv[1]);
    g_nb[((size_t)2 * NROWS + i) * G + tid] = __float2bfloat16(vv * sinv[2]);
}

// ---------------- K8: bf16 sim tiles; X panel resident, 4 col tiles per block ----------------
#define SPITCH 40
#define XPITCH 264
#define SIM_SMEM (128*XPITCH*2 + 2*128*SPITCH*2 + 256*4)
__global__ void __launch_bounds__(256) k_sim_mma() {
    extern __shared__ __align__(16) char dsm[];
    __nv_bfloat16* sXp = (__nv_bfloat16*)dsm;                       // 128 x 256 panel
    __nv_bfloat16* sY  = sXp + 128 * XPITCH;                         // 2 x 128 x SPITCH
    float* srow = (float*)(sY + 2 * 128 * SPITCH);
    float* scol = srow + 128;

    int p = blockIdx.z;
    int mx = (p == 2) ? 1 : 0;
    int my = (p == 0) ? 1 : 2;
    int row0 = blockIdx.y * 128;
    int tid = threadIdx.x, lane = tid & 31, warp = tid >> 5;
    int wy = warp >> 1, wx = warp & 1;      // warp tile: 32 rows x 64 cols

    const __nv_bfloat16* xg = g_nb + ((size_t)mx * NROWS + row0) * G;

    // load full X panel once
    #pragma unroll
    for (int it = 0; it < 16; it++) {
        int idx = tid + it * 256;
        int r = idx >> 5, c = (idx & 31) * 8;
        cp16(sXp + r * XPITCH + c, xg + (size_t)r * G + c);
    }
    cp_commit();
    asm volatile("cp.async.wait_group 0;");
    __syncthreads();

    int lr = tid >> 2, lc = (tid & 3) * 8;
    int lr2 = lr + 64;

    for (int j = 0; j < 4; j++) {
        int col0 = (blockIdx.x * 4 + j) * 128;
        const __nv_bfloat16* yg = g_nb + ((size_t)my * NROWS + col0) * G;

        float acc[2][8][4];
        #pragma unroll
        for (int mi = 0; mi < 2; mi++)
            #pragma unroll
            for (int ni = 0; ni < 8; ni++)
                #pragma unroll
                for (int r = 0; r < 4; r++) acc[mi][ni][r] = 0.f;

        // prologue: chunk 0 into buffer 0
        cp16(sY + lr * SPITCH + lc,                 yg + (size_t)lr * G + lc);
        cp16(sY + lr2 * SPITCH + lc,                yg + (size_t)lr2 * G + lc);
        cp_commit();

        #pragma unroll
        for (int c = 0; c < 8; c++) {
            int cur = c & 1;
            if (c < 7) {
                int nb = (c + 1) & 1, kc2 = (c + 1) * 32;
                cp16(sY + nb * 128 * SPITCH + lr * SPITCH + lc,
                     yg + (size_t)lr * G + kc2 + lc);
                cp16(sY + nb * 128 * SPITCH + lr2 * SPITCH + lc,
                     yg + (size_t)lr2 * G + kc2 + lc);
                cp_commit();
                asm volatile("cp.async.wait_group 1;");
            } else {
                asm volatile("cp.async.wait_group 0;");
            }
            __syncthreads();
            int kc = c * 32;
            #pragma unroll
            for (int ks = 0; ks < 2; ks++) {
                int k0 = ks * 16;
                unsigned A[2][4];
                #pragma unroll
                for (int mi = 0; mi < 2; mi++) {
                    int r = wy * 32 + mi * 16 + ((lane >> 3) & 1) * 8 + (lane & 7);
                    int cc = kc + k0 + (lane >> 4) * 8;
                    unsigned ad = (unsigned)__cvta_generic_to_shared(sXp + r * XPITCH + cc);
                    asm volatile("ldmatrix.sync.aligned.m8n8.x4.shared.b16 {%0,%1,%2,%3},[%4];"
                        : "=r"(A[mi][0]), "=r"(A[mi][1]), "=r"(A[mi][2]), "=r"(A[mi][3])
                        : "r"(ad));
                }
                unsigned B[8][2];
                #pragma unroll
                for (int nb2 = 0; nb2 < 4; nb2++) {
                    int r = wx * 64 + nb2 * 16 + (lane >> 4) * 8 + (lane & 7);
                    int cc = k0 + ((lane >> 3) & 1) * 8;
                    unsigned ad = (unsigned)__cvta_generic_to_shared(
                        sY + cur * 128 * SPITCH + r * SPITCH + cc);
                    asm volatile("ldmatrix.sync.aligned.m8n8.x4.shared.b16 {%0,%1,%2,%3},[%4];"
                        : "=r"(B[2 * nb2][0]), "=r"(B[2 * nb2][1]),
                          "=r"(B[2 * nb2 + 1][0]), "=r"(B[2 * nb2 + 1][1])
                        : "r"(ad));
                }
                #pragma unroll
                for (int mi = 0; mi < 2; mi++)
                    #pragma unroll
                    for (int ni = 0; ni < 8; ni++)
                        asm volatile(
                            "mma.sync.aligned.m16n8k16.row.col.f32.bf16.bf16.f32 "
                            "{%0,%1,%2,%3},{%4,%5,%6,%7},{%8,%9},{%0,%1,%2,%3};"
                            : "+f"(acc[mi][ni][0]), "+f"(acc[mi][ni][1]),
                              "+f"(acc[mi][ni][2]), "+f"(acc[mi][ni][3])
                            : "r"(A[mi][0]), "r"(A[mi][1]), "r"(A[mi][2]), "r"(A[mi][3]),
                              "r"(B[ni][0]), "r"(B[ni][1]));
            }
            __syncthreads();
        }

        // epilogue for tile j
        if (tid < 128) { srow[tid] = 0.f; scol[tid] = 0.f; }
        __syncthreads();

        float rowp[2][2] = {{0.f, 0.f}, {0.f, 0.f}};
        float colp[8][2];
        #pragma unroll
        for (int ni = 0; ni < 8; ni++) { colp[ni][0] = 0.f; colp[ni][1] = 0.f; }
        #pragma unroll
        for (int mi = 0; mi < 2; mi++)
            #pragma unroll
            for (int ni = 0; ni < 8; ni++)
                #pragma unroll
                for (int r = 0; r < 4; r++) {
                    float e = __expf(acc[mi][ni][r]);
                    rowp[mi][r >> 1] += e;
                    colp[ni][r & 1] += e;
                }

        #pragma unroll
        for (int mi = 0; mi < 2; mi++)
            #pragma unroll
            for (int h = 0; h < 2; h++) {
                float vv = rowp[mi][h];
                vv += __shfl_xor_sync(0xffffffffu, vv, 1);
                vv += __shfl_xor_sync(0xffffffffu, vv, 2);
                if ((lane & 3) == 0)
                    atomicAdd(&srow[wy * 32 + mi * 16 + (lane >> 2) + h * 8], vv);
            }
        #pragma unroll
        for (int ni = 0; ni < 8; ni++)
            #pragma unroll
            for (int s2 = 0; s2 < 2; s2++) {
                float vv = colp[ni][s2];
                vv += __shfl_xor_sync(0xffffffffu, vv, 4);
                vv += __shfl_xor_sync(0xffffffffu, vv, 8);
                vv += __shfl_xor_sync(0xffffffffu, vv, 16);
                if (lane < 4)
                    atomicAdd(&scol[wx * 64 + ni * 8 + lane * 2 + s2], vv);
            }
        __syncthreads();
        if (tid < 128) {
            atomicAdd(&g_rowsum[p * NROWS + row0 + tid], srow[tid]);
            atomicAdd(&g_colsum[p * NROWS + col0 + tid], scol[tid]);
        }
        __syncthreads();
    }
}

// ---------------- K9: final loss reduction ----------------
__global__ void k_loss(float* out, int out_size) {
    int tid = threadIdx.x;
    float s = 0.f;
    for (int idx = tid; idx < 3 * NROWS; idx += 256) {
        float dg = g_diag[idx];
        s += 2.f * dg - logf(g_rowsum[idx]) - logf(g_colsum[idx]);
    }
    __shared__ float red[8];
    int lane = tid & 31, w = tid >> 5;
    #pragma unroll
    for (int o = 16; o; o >>= 1) s += __shfl_down_sync(0xffffffffu, s, o);
    if (lane == 0) red[w] = s;
    __syncthreads();
    if (tid == 0) {
        float tot = 0.f;
        #pragma unroll
        for (int w2 = 0; w2 < 8; w2++) tot += red[w2];
        float loss = -tot / (2.f * 3.f * (float)NROWS);
        if (out_size > NROWS * 768) out[NROWS * 768] = loss;
    }
}

// ---------------- launcher ----------------
extern "C" void kernel_launch(void* const* d_in, const int* in_sizes, int n_in,
                              void* d_out, int out_size) {
    const float* t   = (const float*)d_in[0];
    const float* a   = (const float*)d_in[1];
    const float* v   = (const float*)d_in[2];
    const float* Wfc = (const float*)d_in[3];
    const float* bfc = (const float*)d_in[4];
    const float* Wh  = (const float*)d_in[5];
    const float* bh  = (const float*)d_in[6];
    float* out = (float*)d_out;

    cudaFuncSetAttribute(k_sim_mma,
        cudaFuncAttributeMaxDynamicSharedMemorySize, SIM_SMEM);

    k_sq<<<NNODE / 8, 256>>>(t, a, v);
    k_gram_mma<<<dim3(6, 64), 256>>>();
    k_fc_mma<<<dim3(2, 96), 256>>>(Wfc, bfc);
    k_agg_f<<<dim3(8, 64), 256>>>();
    k_out_mma<<<dim3(2, 96), 256>>>(Wh, bh, out);
    k_norm<<<NROWS, 256>>>(out);
    k_sim_mma<<<dim3(8, 32, 3), 256, SIM_SMEM>>>();
    k_loss<<<1, 256>>>(out, out_size);
}